// round 1
// baseline (speedup 1.0000x reference)
#include <cuda_runtime.h>
#include <math.h>

#define BB 4
#define CC 128
#define NPIX 4096
#define NH 4
#define DH 32
#define EPSF 1e-6f

// Scratch (device globals; no allocation in kernel_launch)
__device__ float g_h[BB * CC * NPIX];        // normalized input  [b, c, n]
__device__ float g_qkv[BB * 3 * CC * NPIX];  // qkv               [b, o, n], o in [0,384)
__device__ float g_att[BB * CC * NPIX];      // attention output  [b, c, n]

// ---------------------------------------------------------------------------
// K1: per-pixel channel LayerNorm: mean/var over C for each (b, n)
// ---------------------------------------------------------------------------
__global__ void norm_kernel(const float* __restrict__ x,
                            const float* __restrict__ w,
                            const float* __restrict__ bias) {
    int pix = blockIdx.x * blockDim.x + threadIdx.x;  // 0..16383
    int b = pix >> 12;
    int n = pix & (NPIX - 1);
    const float* xp = x + (size_t)b * CC * NPIX + n;
    float s = 0.f, s2 = 0.f;
#pragma unroll 8
    for (int c = 0; c < CC; c++) {
        float v = xp[(size_t)c * NPIX];
        s += v;
        s2 += v * v;
    }
    float mean = s * (1.0f / CC);
    float var  = s2 * (1.0f / CC) - mean * mean;
    float inv  = rsqrtf(var + EPSF);
    float* hp = g_h + (size_t)b * CC * NPIX + n;
#pragma unroll 8
    for (int c = 0; c < CC; c++) {
        float v = xp[(size_t)c * NPIX];
        hp[(size_t)c * NPIX] = (v - mean) * inv * w[c] + bias[c];
    }
}

// ---------------------------------------------------------------------------
// K2/K4: GEMM  Out[b, o0+o, n0+n] = sum_c W[o, c] * In[b, c, n] + bias[o] (+resid)
// block tile: 64 (o) x 128 (n), K = 128, blockDim = 256
// ---------------------------------------------------------------------------
__global__ void gemm_kernel(const float* __restrict__ W,
                            const float* __restrict__ bias,
                            const float* __restrict__ In,
                            float* __restrict__ Out,
                            const float* __restrict__ resid,
                            int OCtot) {
    __shared__ float Ws[64][33];    // [o][k] (padded)
    __shared__ float Hs[32][128];   // [k][n]

    const int b  = blockIdx.z;
    const int o0 = blockIdx.y * 64;
    const int n0 = blockIdx.x * 128;
    const int tid = threadIdx.x;
    const int to = tid >> 4;   // 0..15 -> 4 o rows
    const int tn = tid & 15;   // 0..15 -> 4+4 n cols

    float acc[4][8];
#pragma unroll
    for (int i = 0; i < 4; i++)
#pragma unroll
        for (int j = 0; j < 8; j++) acc[i][j] = 0.f;

    for (int kk = 0; kk < CC; kk += 32) {
        __syncthreads();
        // load W tile [64 o][32 k], global reads coalesced along k
        for (int idx = tid; idx < 64 * 32; idx += 256) {
            int o = idx >> 5, k = idx & 31;
            Ws[o][k] = W[(size_t)(o0 + o) * CC + kk + k];
        }
        // load In tile [32 k][128 n], coalesced along n
        for (int idx = tid; idx < 32 * 128; idx += 256) {
            int k = idx >> 7, n = idx & 127;
            Hs[k][n] = In[((size_t)b * CC + kk + k) * NPIX + n0 + n];
        }
        __syncthreads();
#pragma unroll
        for (int k = 0; k < 32; k++) {
            float wv[4];
#pragma unroll
            for (int i = 0; i < 4; i++) wv[i] = Ws[to * 4 + i][k];
            float4 h0 = *(const float4*)&Hs[k][tn * 4];
            float4 h1 = *(const float4*)&Hs[k][64 + tn * 4];
            float hv[8] = {h0.x, h0.y, h0.z, h0.w, h1.x, h1.y, h1.z, h1.w};
#pragma unroll
            for (int i = 0; i < 4; i++)
#pragma unroll
                for (int j = 0; j < 8; j++) acc[i][j] = fmaf(wv[i], hv[j], acc[i][j]);
        }
    }

#pragma unroll
    for (int i = 0; i < 4; i++) {
        int o = o0 + to * 4 + i;
        float bb = bias[o];
#pragma unroll
        for (int j = 0; j < 8; j++) {
            int n = n0 + ((j < 4) ? (tn * 4 + j) : (64 + tn * 4 + (j - 4)));
            size_t oidx = ((size_t)b * OCtot + o) * NPIX + n;
            float v = acc[i][j] + bb;
            if (resid) v += resid[((size_t)b * CC + o) * NPIX + n];
            Out[oidx] = v;
        }
    }
}

// ---------------------------------------------------------------------------
// K3: flash attention, fp32. One CTA = (b, head, 64-query tile). blockDim 256.
// S tile = 64q x 64m, online softmax, O accum [32c x 64q] in registers.
// ---------------------------------------------------------------------------
__global__ void attn_kernel() {
    __shared__ float Qs[DH][64];
    __shared__ float Ks[DH][64];
    __shared__ float Vs[DH][64];
    __shared__ float Ss[64][65];
    __shared__ float rowM[64], rowL[64], corr[64];
    __shared__ float pm[64][4], ps[64][4];

    const int b  = blockIdx.z;
    const int h  = blockIdx.y;
    const int q0 = blockIdx.x * 64;
    const int tid = threadIdx.x;
    const float scale = 0.17677669529663687f;  // 1/sqrt(32)

    const float* qb = g_qkv + ((size_t)b * 3 * CC + h * DH) * NPIX;
    const float* kb = g_qkv + ((size_t)b * 3 * CC + CC + h * DH) * NPIX;
    const float* vb = g_qkv + ((size_t)b * 3 * CC + 2 * CC + h * DH) * NPIX;

    // load Q tile [c][q]
    for (int idx = tid; idx < DH * 64; idx += 256) {
        int c = idx >> 6, n = idx & 63;
        Qs[c][n] = qb[(size_t)c * NPIX + q0 + n];
    }
    if (tid < 64) { rowM[tid] = -3.0e38f; rowL[tid] = 0.f; }

    const int tq  = tid >> 4;  // 0..15 (4 q rows each) for S phase
    const int tm  = tid & 15;  // 0..15 (4 m cols each)
    const int tc  = tid >> 5;  // 0..7  (4 c rows each) for O phase
    const int tqo = tid & 31;  // 0..31 (2 q cols each)
    const int srow = tid >> 2; // softmax row
    const int spart = tid & 3; // softmax partition

    float oacc[4][2];
#pragma unroll
    for (int i = 0; i < 4; i++) { oacc[i][0] = 0.f; oacc[i][1] = 0.f; }

    for (int m0 = 0; m0 < NPIX; m0 += 64) {
        __syncthreads();  // prev O-phase done with Ks/Vs/Ss
        for (int idx = tid; idx < DH * 64; idx += 256) {
            int c = idx >> 6, n = idx & 63;
            Ks[c][n] = kb[(size_t)c * NPIX + m0 + n];
            Vs[c][n] = vb[(size_t)c * NPIX + m0 + n];
        }
        __syncthreads();

        // ---- S = Q^T K (64x64), 4x4 microtile / thread ----
        float acc[4][4];
#pragma unroll
        for (int i = 0; i < 4; i++)
#pragma unroll
            for (int j = 0; j < 4; j++) acc[i][j] = 0.f;
#pragma unroll
        for (int c = 0; c < DH; c++) {
            float4 a = *(const float4*)&Qs[c][tq * 4];
            float4 kv = *(const float4*)&Ks[c][tm * 4];
            float av[4] = {a.x, a.y, a.z, a.w};
            float kvv[4] = {kv.x, kv.y, kv.z, kv.w};
#pragma unroll
            for (int i = 0; i < 4; i++)
#pragma unroll
                for (int j = 0; j < 4; j++) acc[i][j] = fmaf(av[i], kvv[j], acc[i][j]);
        }
#pragma unroll
        for (int i = 0; i < 4; i++)
#pragma unroll
            for (int j = 0; j < 4; j++) Ss[tq * 4 + i][tm * 4 + j] = acc[i][j] * scale;
        __syncthreads();

        // ---- online softmax (parallel: 4 threads/row) ----
        {
            float lm = -3.0e38f;
#pragma unroll
            for (int j = 0; j < 16; j++) lm = fmaxf(lm, Ss[srow][spart * 16 + j]);
            pm[srow][spart] = lm;
        }
        __syncthreads();
        if (tid < 64) {
            float mOld = rowM[tid];
            float mNew = fmaxf(fmaxf(pm[tid][0], pm[tid][1]), fmaxf(pm[tid][2], pm[tid][3]));
            mNew = fmaxf(mOld, mNew);
            rowM[tid] = mNew;
            corr[tid] = __expf(mOld - mNew);
        }
        __syncthreads();
        {
            float mN = rowM[srow];
            float lsum = 0.f;
#pragma unroll
            for (int j = 0; j < 16; j++) {
                float p = __expf(Ss[srow][spart * 16 + j] - mN);
                Ss[srow][spart * 16 + j] = p;
                lsum += p;
            }
            ps[srow][spart] = lsum;
        }
        __syncthreads();
        if (tid < 64) {
            rowL[tid] = rowL[tid] * corr[tid] +
                        (ps[tid][0] + ps[tid][1] + ps[tid][2] + ps[tid][3]);
        }
        __syncthreads();

        // ---- O += V P^T (32c x 64q), with running-max correction ----
        float c0 = corr[2 * tqo], c1 = corr[2 * tqo + 1];
#pragma unroll
        for (int i = 0; i < 4; i++) { oacc[i][0] *= c0; oacc[i][1] *= c1; }
#pragma unroll 4
        for (int m = 0; m < 64; m++) {
            float p0 = Ss[2 * tqo][m];
            float p1 = Ss[2 * tqo + 1][m];
#pragma unroll
            for (int i = 0; i < 4; i++) {
                float v = Vs[tc * 4 + i][m];
                oacc[i][0] = fmaf(v, p0, oacc[i][0]);
                oacc[i][1] = fmaf(v, p1, oacc[i][1]);
            }
        }
    }

    // final normalize + store
    float l0 = 1.0f / rowL[2 * tqo];
    float l1 = 1.0f / rowL[2 * tqo + 1];
    float* ob = g_att + ((size_t)b * CC + h * DH) * NPIX + q0;
#pragma unroll
    for (int i = 0; i < 4; i++) {
        ob[(size_t)(tc * 4 + i) * NPIX + 2 * tqo]     = oacc[i][0] * l0;
        ob[(size_t)(tc * 4 + i) * NPIX + 2 * tqo + 1] = oacc[i][1] * l1;
    }
}

// ---------------------------------------------------------------------------
extern "C" void kernel_launch(void* const* d_in, const int* in_sizes, int n_in,
                              void* d_out, int out_size) {
    const float* x      = (const float*)d_in[0];
    const float* norm_w = (const float*)d_in[1];
    const float* norm_b = (const float*)d_in[2];
    const float* qkv_w  = (const float*)d_in[3];
    const float* qkv_b  = (const float*)d_in[4];
    const float* proj_w = (const float*)d_in[5];
    const float* proj_b = (const float*)d_in[6];
    float* out = (float*)d_out;

    float *g_h_p, *g_qkv_p, *g_att_p;
    cudaGetSymbolAddress((void**)&g_h_p, g_h);
    cudaGetSymbolAddress((void**)&g_qkv_p, g_qkv);
    cudaGetSymbolAddress((void**)&g_att_p, g_att);

    // K1: norm
    norm_kernel<<<(BB * NPIX) / 256, 256>>>(x, norm_w, norm_b);

    // K2: qkv = qkv_w @ h  -> [b, 384, n]
    gemm_kernel<<<dim3(NPIX / 128, 384 / 64, BB), 256>>>(
        qkv_w, qkv_b, g_h_p, g_qkv_p, nullptr, 3 * CC);

    // K3: attention -> g_att [b, 128, n]
    attn_kernel<<<dim3(NPIX / 64, NH, BB), 256>>>();

    // K4: proj + bias + residual -> d_out
    gemm_kernel<<<dim3(NPIX / 128, CC / 64, BB), 256>>>(
        proj_w, proj_b, g_att_p, out, x, CC);
}

// round 4
// speedup vs baseline: 2.7519x; 2.7519x over previous
#include <cuda_runtime.h>
#include <cuda_bf16.h>
#include <math.h>
#include <stdint.h>

#define BB 4
#define CC 128
#define NPIX 4096
#define NH 4
#define DH 32
#define EPSF 1e-6f

// Scratch (device globals; no allocation in kernel_launch)
__device__ float g_h[BB * CC * NPIX];        // normalized input  [b, c, n]
__device__ float g_qkv[BB * 3 * CC * NPIX];  // qkv               [b, o, n]
__device__ float g_att[BB * CC * NPIX];      // attention output  [b, c, n]

// ---------------------------------------------------------------------------
// K1: per-pixel channel LayerNorm
// ---------------------------------------------------------------------------
__global__ void norm_kernel(const float* __restrict__ x,
                            const float* __restrict__ w,
                            const float* __restrict__ bias) {
    int pix = blockIdx.x * blockDim.x + threadIdx.x;
    int b = pix >> 12;
    int n = pix & (NPIX - 1);
    const float* xp = x + (size_t)b * CC * NPIX + n;
    float s = 0.f, s2 = 0.f;
#pragma unroll 8
    for (int c = 0; c < CC; c++) {
        float v = xp[(size_t)c * NPIX];
        s += v;
        s2 += v * v;
    }
    float mean = s * (1.0f / CC);
    float var  = s2 * (1.0f / CC) - mean * mean;
    float inv  = rsqrtf(var + EPSF);
    float* hp = g_h + (size_t)b * CC * NPIX + n;
#pragma unroll 8
    for (int c = 0; c < CC; c++) {
        float v = xp[(size_t)c * NPIX];
        hp[(size_t)c * NPIX] = (v - mean) * inv * w[c] + bias[c];
    }
}

// ---------------------------------------------------------------------------
// K2/K4: SIMT GEMM (unchanged from passing round 1)
// ---------------------------------------------------------------------------
__global__ void gemm_kernel(const float* __restrict__ W,
                            const float* __restrict__ bias,
                            const float* __restrict__ In,
                            float* __restrict__ Out,
                            const float* __restrict__ resid,
                            int OCtot) {
    __shared__ float Ws[64][33];
    __shared__ float Hs[32][128];

    const int b  = blockIdx.z;
    const int o0 = blockIdx.y * 64;
    const int n0 = blockIdx.x * 128;
    const int tid = threadIdx.x;
    const int to = tid >> 4;
    const int tn = tid & 15;

    float acc[4][8];
#pragma unroll
    for (int i = 0; i < 4; i++)
#pragma unroll
        for (int j = 0; j < 8; j++) acc[i][j] = 0.f;

    for (int kk = 0; kk < CC; kk += 32) {
        __syncthreads();
        for (int idx = tid; idx < 64 * 32; idx += 256) {
            int o = idx >> 5, k = idx & 31;
            Ws[o][k] = W[(size_t)(o0 + o) * CC + kk + k];
        }
        for (int idx = tid; idx < 32 * 128; idx += 256) {
            int k = idx >> 7, n = idx & 127;
            Hs[k][n] = In[((size_t)b * CC + kk + k) * NPIX + n0 + n];
        }
        __syncthreads();
#pragma unroll
        for (int k = 0; k < 32; k++) {
            float wv[4];
#pragma unroll
            for (int i = 0; i < 4; i++) wv[i] = Ws[to * 4 + i][k];
            float4 h0 = *(const float4*)&Hs[k][tn * 4];
            float4 h1 = *(const float4*)&Hs[k][64 + tn * 4];
            float hv[8] = {h0.x, h0.y, h0.z, h0.w, h1.x, h1.y, h1.z, h1.w};
#pragma unroll
            for (int i = 0; i < 4; i++)
#pragma unroll
                for (int j = 0; j < 8; j++) acc[i][j] = fmaf(wv[i], hv[j], acc[i][j]);
        }
    }

#pragma unroll
    for (int i = 0; i < 4; i++) {
        int o = o0 + to * 4 + i;
        float bb = bias[o];
#pragma unroll
        for (int j = 0; j < 8; j++) {
            int n = n0 + ((j < 4) ? (tn * 4 + j) : (64 + tn * 4 + (j - 4)));
            size_t oidx = ((size_t)b * OCtot + o) * NPIX + n;
            float v = acc[i][j] + bb;
            if (resid) v += resid[((size_t)b * CC + o) * NPIX + n];
            Out[oidx] = v;
        }
    }
}

// ---------------------------------------------------------------------------
// mma.sync helpers
// ---------------------------------------------------------------------------
__device__ __forceinline__ void mma16816(float* d, const uint32_t* a,
                                         const uint32_t* b) {
    asm volatile(
        "mma.sync.aligned.m16n8k16.row.col.f32.bf16.bf16.f32 "
        "{%0,%1,%2,%3},{%4,%5,%6,%7},{%8,%9},{%0,%1,%2,%3};"
        : "+f"(d[0]), "+f"(d[1]), "+f"(d[2]), "+f"(d[3])
        : "r"(a[0]), "r"(a[1]), "r"(a[2]), "r"(a[3]), "r"(b[0]), "r"(b[1]));
}

__device__ __forceinline__ uint32_t pack_bf16x2(float lo_val, float hi_val) {
    uint32_t r;
    asm("cvt.rn.bf16x2.f32 %0, %1, %2;" : "=r"(r) : "f"(hi_val), "f"(lo_val));
    return r;
}

// ---------------------------------------------------------------------------
// K3: flash attention via mma.sync bf16 with split-bf16 emulated fp32.
// CTA = 128 threads (4 warps). Warp owns 32 q rows. Chunks of 64 keys.
// Channel dim doubled to 64 (hi | lo) for QK^T -> exact to ~2^-16.
// PV: O += P_hi*V_hi + P_lo*V_hi + P_hi*V_lo.
// ---------------------------------------------------------------------------
__global__ void __launch_bounds__(128) attn_mma_kernel() {
    __shared__ __align__(16) __nv_bfloat16 Qs[128][68];  // [q][ch hi0-31|lo32-63]
    __shared__ __align__(16) __nv_bfloat16 Ks[64][68];   // [key][ch hi|lo]
    __shared__ __align__(16) __nv_bfloat16 Vh[32][68];   // [ch][key]
    __shared__ __align__(16) __nv_bfloat16 Vl[32][68];

    const int tid = threadIdx.x;
    const int lane = tid & 31;
    const int wid = tid >> 5;
    const int g = lane >> 2;       // row group in fragment
    const int qu = (lane & 3) * 2; // col pair in fragment
    const int b = blockIdx.z, hh = blockIdx.y;
    const int q0 = blockIdx.x * 128;
    const float scale = 0.17677669529663687f;  // 1/sqrt(32)

    const float* qb = g_qkv + ((size_t)b * 3 * CC + hh * DH) * NPIX;
    const float* kb = qb + (size_t)CC * NPIX;
    const float* vb = qb + (size_t)2 * CC * NPIX;

    // ---- load Q (scaled, split hi/lo), row = tid ----
#pragma unroll
    for (int c = 0; c < DH; c++) {
        float v = qb[(size_t)c * NPIX + q0 + tid] * scale;
        __nv_bfloat16 hi = __float2bfloat16(v);
        Qs[tid][c] = hi;
        Qs[tid][c + 32] = __float2bfloat16(v - __bfloat162float(hi));
    }
    __syncthreads();

    // ---- persistent Q A-fragments: qa[mi][kk][4] ----
    const int qr = wid * 32;
    uint32_t qa[2][4][4];
#pragma unroll
    for (int mi = 0; mi < 2; mi++)
#pragma unroll
        for (int kk = 0; kk < 4; kk++) {
            int r0 = qr + mi * 16 + g;
            int c0 = kk * 16 + qu;
            qa[mi][kk][0] = *(const uint32_t*)&Qs[r0][c0];
            qa[mi][kk][1] = *(const uint32_t*)&Qs[r0 + 8][c0];
            qa[mi][kk][2] = *(const uint32_t*)&Qs[r0][c0 + 8];
            qa[mi][kk][3] = *(const uint32_t*)&Qs[r0 + 8][c0 + 8];
        }

    float o[2][4][4];
#pragma unroll
    for (int mi = 0; mi < 2; mi++)
#pragma unroll
        for (int ci = 0; ci < 4; ci++)
#pragma unroll
            for (int r = 0; r < 4; r++) o[mi][ci][r] = 0.f;
    float mrun[2][2] = {{-3.0e38f, -3.0e38f}, {-3.0e38f, -3.0e38f}};
    float lrun[2][2] = {{0.f, 0.f}, {0.f, 0.f}};

    const int key = tid & 63;
    const int chb = (tid >> 6) * 16;

    for (int m0 = 0; m0 < NPIX; m0 += 64) {
        __syncthreads();
        // ---- load K, V chunk (split hi/lo) ----
#pragma unroll
        for (int i = 0; i < 16; i++) {
            int c = chb + i;
            float kv = kb[(size_t)c * NPIX + m0 + key];
            __nv_bfloat16 khi = __float2bfloat16(kv);
            Ks[key][c] = khi;
            Ks[key][c + 32] = __float2bfloat16(kv - __bfloat162float(khi));
            float vv = vb[(size_t)c * NPIX + m0 + key];
            __nv_bfloat16 vhi = __float2bfloat16(vv);
            Vh[c][key] = vhi;
            Vl[c][key] = __float2bfloat16(vv - __bfloat162float(vhi));
        }
        __syncthreads();

        // ---- S = Q K^T : sacc[mi][nj][4], 64 keys x 32q per warp ----
        float sacc[2][8][4];
#pragma unroll
        for (int nj = 0; nj < 8; nj++) {
            uint32_t bbf[4][2];
            int kn = nj * 8 + g;
#pragma unroll
            for (int kk = 0; kk < 4; kk++) {
                bbf[kk][0] = *(const uint32_t*)&Ks[kn][kk * 16 + qu];
                bbf[kk][1] = *(const uint32_t*)&Ks[kn][kk * 16 + qu + 8];
            }
#pragma unroll
            for (int mi = 0; mi < 2; mi++) {
#pragma unroll
                for (int r = 0; r < 4; r++) sacc[mi][nj][r] = 0.f;
#pragma unroll
                for (int kk = 0; kk < 4; kk++)
                    mma16816(sacc[mi][nj], qa[mi][kk], bbf[kk]);
            }
        }

        // ---- online softmax ----
        float corr[2][2];
#pragma unroll
        for (int mi = 0; mi < 2; mi++)
#pragma unroll
            for (int h2 = 0; h2 < 2; h2++) {
                float mx = -3.0e38f;
#pragma unroll
                for (int nj = 0; nj < 8; nj++)
                    mx = fmaxf(mx, fmaxf(sacc[mi][nj][h2 * 2],
                                         sacc[mi][nj][h2 * 2 + 1]));
                mx = fmaxf(mx, __shfl_xor_sync(0xffffffffu, mx, 1));
                mx = fmaxf(mx, __shfl_xor_sync(0xffffffffu, mx, 2));
                float mnew = fmaxf(mrun[mi][h2], mx);
                float cr = __expf(mrun[mi][h2] - mnew);
                corr[mi][h2] = cr;
                mrun[mi][h2] = mnew;
                float ls = 0.f;
#pragma unroll
                for (int nj = 0; nj < 8; nj++) {
                    float p0 = __expf(sacc[mi][nj][h2 * 2] - mnew);
                    float p1 = __expf(sacc[mi][nj][h2 * 2 + 1] - mnew);
                    sacc[mi][nj][h2 * 2] = p0;
                    sacc[mi][nj][h2 * 2 + 1] = p1;
                    ls += p0 + p1;
                }
                ls += __shfl_xor_sync(0xffffffffu, ls, 1);
                ls += __shfl_xor_sync(0xffffffffu, ls, 2);
                lrun[mi][h2] = lrun[mi][h2] * cr + ls;
#pragma unroll
                for (int ci = 0; ci < 4; ci++) {
                    o[mi][ci][h2 * 2] *= cr;
                    o[mi][ci][h2 * 2 + 1] *= cr;
                }
            }

        // ---- O += P V (split products), per 16-key tile ----
        // S-accum fragment {c0,c1,c2,c3} maps directly to PV A-fragment
        // {a0,a1,a2,a3} = {(g,k0),(g+8,k0),(g,k8),(g+8,k8)} — no reorder.
#pragma unroll
        for (int kt = 0; kt < 4; kt++) {
            uint32_t ph[2][4], pl[2][4];
#pragma unroll
            for (int mi = 0; mi < 2; mi++) {
#pragma unroll
                for (int half = 0; half < 2; half++) {
                    float* sp = sacc[mi][2 * kt + half];
#pragma unroll
                    for (int rr = 0; rr < 2; rr++) {
                        float f0 = sp[rr * 2], f1 = sp[rr * 2 + 1];
                        uint32_t hp = pack_bf16x2(f0, f1);
                        __nv_bfloat16 h0 = __float2bfloat16(f0);
                        __nv_bfloat16 h1 = __float2bfloat16(f1);
                        uint32_t lp = pack_bf16x2(f0 - __bfloat162float(h0),
                                                  f1 - __bfloat162float(h1));
                        ph[mi][half * 2 + rr] = hp;
                        pl[mi][half * 2 + rr] = lp;
                    }
                }
            }
            uint32_t vbh[4][2], vbl[4][2];
#pragma unroll
            for (int ci = 0; ci < 4; ci++) {
                int ch = ci * 8 + g;
                int kk0 = kt * 16 + qu;
                vbh[ci][0] = *(const uint32_t*)&Vh[ch][kk0];
                vbh[ci][1] = *(const uint32_t*)&Vh[ch][kk0 + 8];
                vbl[ci][0] = *(const uint32_t*)&Vl[ch][kk0];
                vbl[ci][1] = *(const uint32_t*)&Vl[ch][kk0 + 8];
            }
#pragma unroll
            for (int mi = 0; mi < 2; mi++)
#pragma unroll
                for (int ci = 0; ci < 4; ci++) {
                    mma16816(o[mi][ci], ph[mi], vbh[ci]);
                    mma16816(o[mi][ci], pl[mi], vbh[ci]);
                    mma16816(o[mi][ci], ph[mi], vbl[ci]);
                }
        }
    }

    // ---- normalize + store ----
#pragma unroll
    for (int mi = 0; mi < 2; mi++)
#pragma unroll
        for (int h2 = 0; h2 < 2; h2++) {
            float invl = 1.0f / lrun[mi][h2];
            int qrow = q0 + qr + mi * 16 + g + h2 * 8;
#pragma unroll
            for (int ci = 0; ci < 4; ci++) {
                int ch = ci * 8 + qu;
                g_att[((size_t)b * CC + hh * DH + ch) * NPIX + qrow] =
                    o[mi][ci][h2 * 2] * invl;
                g_att[((size_t)b * CC + hh * DH + ch + 1) * NPIX + qrow] =
                    o[mi][ci][h2 * 2 + 1] * invl;
            }
        }
}

// ---------------------------------------------------------------------------
extern "C" void kernel_launch(void* const* d_in, const int* in_sizes, int n_in,
                              void* d_out, int out_size) {
    const float* x      = (const float*)d_in[0];
    const float* norm_w = (const float*)d_in[1];
    const float* norm_b = (const float*)d_in[2];
    const float* qkv_w  = (const float*)d_in[3];
    const float* qkv_b  = (const float*)d_in[4];
    const float* proj_w = (const float*)d_in[5];
    const float* proj_b = (const float*)d_in[6];
    float* out = (float*)d_out;

    float *g_h_p, *g_qkv_p, *g_att_p;
    cudaGetSymbolAddress((void**)&g_h_p, g_h);
    cudaGetSymbolAddress((void**)&g_qkv_p, g_qkv);
    cudaGetSymbolAddress((void**)&g_att_p, g_att);

    // K1: norm
    norm_kernel<<<(BB * NPIX) / 256, 256>>>(x, norm_w, norm_b);

    // K2: qkv = qkv_w @ h  -> [b, 384, n]
    gemm_kernel<<<dim3(NPIX / 128, 384 / 64, BB), 256>>>(
        qkv_w, qkv_b, g_h_p, g_qkv_p, nullptr, 3 * CC);

    // K3: tensor-core (mma.sync) attention -> g_att [b, 128, n]
    attn_mma_kernel<<<dim3(NPIX / 128, NH, BB), 128>>>();

    // K4: proj + bias + residual -> d_out
    gemm_kernel<<<dim3(NPIX / 128, CC / 64, BB), 256>>>(
        proj_w, proj_b, g_att_p, out, x, CC);
}

// round 5
// speedup vs baseline: 2.8898x; 1.0501x over previous
#include <cuda_runtime.h>
#include <cuda_bf16.h>
#include <math.h>
#include <stdint.h>

#define BB 4
#define CC 128
#define NPIX 4096
#define NH 4
#define DH 32
#define EPSF 1e-6f
// (1/sqrt(32)) * log2(e)
#define SCALE2 0.25503486f

// Scratch (device globals; no allocation in kernel_launch)
__device__ float g_h[BB * CC * NPIX];        // normalized input  [b, c, n]
__device__ float g_qkv[BB * 3 * CC * NPIX];  // qkv               [b, o, n]
__device__ float g_att[BB * CC * NPIX];      // attention output  [b, c, n]
// split-bf16 attention operands
__device__ __nv_bfloat16 g_q2[BB * NH * NPIX * 64];  // [b,h,n, ch: hi0-31|lo32-63]
__device__ __nv_bfloat16 g_k2[BB * NH * NPIX * 64];  // same layout
__device__ __nv_bfloat16 g_vh[BB * NH * DH * NPIX];  // [b,h,c,n]
__device__ __nv_bfloat16 g_vl[BB * NH * DH * NPIX];

// ---------------------------------------------------------------------------
// K1: per-pixel channel LayerNorm
// ---------------------------------------------------------------------------
__global__ void norm_kernel(const float* __restrict__ x,
                            const float* __restrict__ w,
                            const float* __restrict__ bias) {
    int pix = blockIdx.x * blockDim.x + threadIdx.x;
    int b = pix >> 12;
    int n = pix & (NPIX - 1);
    const float* xp = x + (size_t)b * CC * NPIX + n;
    float s = 0.f, s2 = 0.f;
#pragma unroll 8
    for (int c = 0; c < CC; c++) {
        float v = xp[(size_t)c * NPIX];
        s += v;
        s2 += v * v;
    }
    float mean = s * (1.0f / CC);
    float var  = s2 * (1.0f / CC) - mean * mean;
    float inv  = rsqrtf(var + EPSF);
    float* hp = g_h + (size_t)b * CC * NPIX + n;
#pragma unroll 8
    for (int c = 0; c < CC; c++) {
        float v = xp[(size_t)c * NPIX];
        hp[(size_t)c * NPIX] = (v - mean) * inv * w[c] + bias[c];
    }
}

// ---------------------------------------------------------------------------
// K2/K4: SIMT GEMM (unchanged)
// ---------------------------------------------------------------------------
__global__ void gemm_kernel(const float* __restrict__ W,
                            const float* __restrict__ bias,
                            const float* __restrict__ In,
                            float* __restrict__ Out,
                            const float* __restrict__ resid,
                            int OCtot) {
    __shared__ float Ws[64][33];
    __shared__ float Hs[32][128];

    const int b  = blockIdx.z;
    const int o0 = blockIdx.y * 64;
    const int n0 = blockIdx.x * 128;
    const int tid = threadIdx.x;
    const int to = tid >> 4;
    const int tn = tid & 15;

    float acc[4][8];
#pragma unroll
    for (int i = 0; i < 4; i++)
#pragma unroll
        for (int j = 0; j < 8; j++) acc[i][j] = 0.f;

    for (int kk = 0; kk < CC; kk += 32) {
        __syncthreads();
        for (int idx = tid; idx < 64 * 32; idx += 256) {
            int o = idx >> 5, k = idx & 31;
            Ws[o][k] = W[(size_t)(o0 + o) * CC + kk + k];
        }
        for (int idx = tid; idx < 32 * 128; idx += 256) {
            int k = idx >> 7, n = idx & 127;
            Hs[k][n] = In[((size_t)b * CC + kk + k) * NPIX + n0 + n];
        }
        __syncthreads();
#pragma unroll
        for (int k = 0; k < 32; k++) {
            float wv[4];
#pragma unroll
            for (int i = 0; i < 4; i++) wv[i] = Ws[to * 4 + i][k];
            float4 h0 = *(const float4*)&Hs[k][tn * 4];
            float4 h1 = *(const float4*)&Hs[k][64 + tn * 4];
            float hv[8] = {h0.x, h0.y, h0.z, h0.w, h1.x, h1.y, h1.z, h1.w};
#pragma unroll
            for (int i = 0; i < 4; i++)
#pragma unroll
                for (int j = 0; j < 8; j++) acc[i][j] = fmaf(wv[i], hv[j], acc[i][j]);
        }
    }

#pragma unroll
    for (int i = 0; i < 4; i++) {
        int o = o0 + to * 4 + i;
        float bb = bias[o];
#pragma unroll
        for (int j = 0; j < 8; j++) {
            int n = n0 + ((j < 4) ? (tn * 4 + j) : (64 + tn * 4 + (j - 4)));
            size_t oidx = ((size_t)b * OCtot + o) * NPIX + n;
            float v = acc[i][j] + bb;
            if (resid) v += resid[((size_t)b * CC + o) * NPIX + n];
            Out[oidx] = v;
        }
    }
}

// ---------------------------------------------------------------------------
// helpers
// ---------------------------------------------------------------------------
__device__ __forceinline__ void mma16816(float* d, const uint32_t* a,
                                         const uint32_t* b) {
    asm volatile(
        "mma.sync.aligned.m16n8k16.row.col.f32.bf16.bf16.f32 "
        "{%0,%1,%2,%3},{%4,%5,%6,%7},{%8,%9},{%0,%1,%2,%3};"
        : "+f"(d[0]), "+f"(d[1]), "+f"(d[2]), "+f"(d[3])
        : "r"(a[0]), "r"(a[1]), "r"(a[2]), "r"(a[3]), "r"(b[0]), "r"(b[1]));
}

// low 16 bits = a, high 16 bits = b
__device__ __forceinline__ uint32_t pack_bf16x2(float a, float b) {
    uint32_t r;
    asm("cvt.rn.bf16x2.f32 %0, %1, %2;" : "=r"(r) : "f"(b), "f"(a));
    return r;
}

// ---------------------------------------------------------------------------
// K2b: split Q/K into bf16 hi|lo rows [b,h,n,64]; Q scaled by SCALE2
// one thread per (b,h,n)
// ---------------------------------------------------------------------------
__global__ void split_qk_kernel() {
    int t = blockIdx.x * 256 + threadIdx.x;   // 0 .. 65535
    int b = t >> 14, h = (t >> 12) & 3, n = t & (NPIX - 1);
    const float* qs = g_qkv + ((size_t)(b * 3) * CC + h * DH) * NPIX + n;
    const float* ks = qs + (size_t)CC * NPIX;
    __nv_bfloat16* qdst = g_q2 + ((size_t)(b * NH + h) * NPIX + n) * 64;
    __nv_bfloat16* kdst = g_k2 + ((size_t)(b * NH + h) * NPIX + n) * 64;

#pragma unroll
    for (int blk = 0; blk < 4; blk++) {
        uint32_t qh[2], ql[2], kh[2], kl[2];
#pragma unroll
        for (int p = 0; p < 2; p++) {
            int c = blk * 8 + p * 4;
            float q0 = qs[(size_t)(c + 0) * NPIX] * SCALE2;
            float q1 = qs[(size_t)(c + 1) * NPIX] * SCALE2;
            float q2v = qs[(size_t)(c + 2) * NPIX] * SCALE2;
            float q3 = qs[(size_t)(c + 3) * NPIX] * SCALE2;
            // build hi pack then lo pack (2 channels per u32, need 2 u32 per 4 ch)
            __nv_bfloat16 h0 = __float2bfloat16(q0), h1 = __float2bfloat16(q1);
            __nv_bfloat16 h2 = __float2bfloat16(q2v), h3 = __float2bfloat16(q3);
            qh[p] = (p == 0) ? 0u : qh[p];  // placeholder keeps compiler calm
            uint32_t hA = ((uint32_t)*(unsigned short*)&h0) |
                          ((uint32_t)*(unsigned short*)&h1 << 16);
            uint32_t hB = ((uint32_t)*(unsigned short*)&h2) |
                          ((uint32_t)*(unsigned short*)&h3 << 16);
            uint32_t lA = pack_bf16x2(q0 - __bfloat162float(h0),
                                      q1 - __bfloat162float(h1));
            uint32_t lB = pack_bf16x2(q2v - __bfloat162float(h2),
                                      q3 - __bfloat162float(h3));
            // store 4-ch granules directly
            *(uint2*)(qdst + blk * 8 + p * 4)      = make_uint2(hA, hB);
            *(uint2*)(qdst + 32 + blk * 8 + p * 4) = make_uint2(lA, lB);

            float k0 = ks[(size_t)(c + 0) * NPIX];
            float k1 = ks[(size_t)(c + 1) * NPIX];
            float k2v = ks[(size_t)(c + 2) * NPIX];
            float k3 = ks[(size_t)(c + 3) * NPIX];
            __nv_bfloat16 g0 = __float2bfloat16(k0), g1 = __float2bfloat16(k1);
            __nv_bfloat16 g2 = __float2bfloat16(k2v), g3 = __float2bfloat16(k3);
            uint32_t khA = ((uint32_t)*(unsigned short*)&g0) |
                           ((uint32_t)*(unsigned short*)&g1 << 16);
            uint32_t khB = ((uint32_t)*(unsigned short*)&g2) |
                           ((uint32_t)*(unsigned short*)&g3 << 16);
            uint32_t klA = pack_bf16x2(k0 - __bfloat162float(g0),
                                       k1 - __bfloat162float(g1));
            uint32_t klB = pack_bf16x2(k2v - __bfloat162float(g2),
                                       k3 - __bfloat162float(g3));
            *(uint2*)(kdst + blk * 8 + p * 4)      = make_uint2(khA, khB);
            *(uint2*)(kdst + 32 + blk * 8 + p * 4) = make_uint2(klA, klB);
            (void)qh; (void)ql; (void)kh; (void)kl;
        }
    }
}

// ---------------------------------------------------------------------------
// K2c: split V into bf16 hi/lo planes [b,h,c,n]; one thread per element
// ---------------------------------------------------------------------------
__global__ void split_v_kernel() {
    size_t t = (size_t)blockIdx.x * 256 + threadIdx.x;  // 0 .. 2097151
    int n = (int)(t & (NPIX - 1));
    int c = (int)((t >> 12) & (DH - 1));
    int h = (int)((t >> 17) & (NH - 1));
    int b = (int)(t >> 19);
    float v = g_qkv[((size_t)(b * 3 + 2) * CC + h * DH + c) * NPIX + n];
    __nv_bfloat16 hi = __float2bfloat16(v);
    g_vh[t] = hi;
    g_vl[t] = __float2bfloat16(v - __bfloat162float(hi));
}

// ---------------------------------------------------------------------------
// K3: flash attention via mma.sync, pre-split bf16 operands.
// CTA = 256 threads (8 warps), each warp owns 16 q rows -> 128 q per CTA.
// Key chunks of 64. exp2-domain softmax (log2e folded into Q).
// ---------------------------------------------------------------------------
__global__ void __launch_bounds__(256) attn_mma_kernel() {
    __shared__ __align__(16) __nv_bfloat16 Ks[64][72];  // [key][ch hi|lo]
    __shared__ __align__(16) __nv_bfloat16 Vh[32][72];  // [ch][key]
    __shared__ __align__(16) __nv_bfloat16 Vl[32][72];

    const int tid = threadIdx.x;
    const int lane = tid & 31;
    const int wid = tid >> 5;      // 0..7
    const int g = lane >> 2;
    const int qu = (lane & 3) * 2;
    const int b = blockIdx.z, hh = blockIdx.y;
    const int q0 = blockIdx.x * 128;
    const int bh = b * NH + hh;

    const __nv_bfloat16* qgl = g_q2 + ((size_t)bh * NPIX + q0 + wid * 16) * 64;
    const __nv_bfloat16* kgl = g_k2 + (size_t)bh * NPIX * 64;
    const __nv_bfloat16* vhgl = g_vh + (size_t)bh * DH * NPIX;
    const __nv_bfloat16* vlgl = g_vl + (size_t)bh * DH * NPIX;

    // ---- persistent Q A-fragments (direct from global) ----
    uint32_t qa[4][4];
#pragma unroll
    for (int kk = 0; kk < 4; kk++) {
        int c0 = kk * 16 + qu;
        qa[kk][0] = *(const uint32_t*)(qgl + (size_t)g * 64 + c0);
        qa[kk][1] = *(const uint32_t*)(qgl + (size_t)(g + 8) * 64 + c0);
        qa[kk][2] = *(const uint32_t*)(qgl + (size_t)g * 64 + c0 + 8);
        qa[kk][3] = *(const uint32_t*)(qgl + (size_t)(g + 8) * 64 + c0 + 8);
    }

    float o[4][4];
#pragma unroll
    for (int ci = 0; ci < 4; ci++)
#pragma unroll
        for (int r = 0; r < 4; r++) o[ci][r] = 0.f;
    float mrun[2] = {-3.0e38f, -3.0e38f};
    float lrun[2] = {0.f, 0.f};

    const int krow0 = tid >> 3, kpart = tid & 7;   // K copy indices
    const int vrow = tid >> 3;                     // 0..31

    for (int m0 = 0; m0 < NPIX; m0 += 64) {
        __syncthreads();
        // ---- fill smem: pure uint4 copies ----
        *(uint4*)&Ks[krow0][kpart * 8] =
            *(const uint4*)(kgl + (size_t)(m0 + krow0) * 64 + kpart * 8);
        *(uint4*)&Ks[krow0 + 32][kpart * 8] =
            *(const uint4*)(kgl + (size_t)(m0 + krow0 + 32) * 64 + kpart * 8);
        *(uint4*)&Vh[vrow][kpart * 8] =
            *(const uint4*)(vhgl + (size_t)vrow * NPIX + m0 + kpart * 8);
        *(uint4*)&Vl[vrow][kpart * 8] =
            *(const uint4*)(vlgl + (size_t)vrow * NPIX + m0 + kpart * 8);
        __syncthreads();

        // ---- S = Q K^T (k=64 incl. hi|lo cross terms) ----
        float sacc[8][4];
#pragma unroll
        for (int nj = 0; nj < 8; nj++) {
            uint32_t bbf[4][2];
            int kn = nj * 8 + g;
#pragma unroll
            for (int kk = 0; kk < 4; kk++) {
                bbf[kk][0] = *(const uint32_t*)&Ks[kn][kk * 16 + qu];
                bbf[kk][1] = *(const uint32_t*)&Ks[kn][kk * 16 + qu + 8];
            }
#pragma unroll
            for (int r = 0; r < 4; r++) sacc[nj][r] = 0.f;
#pragma unroll
            for (int kk = 0; kk < 4; kk++) mma16816(sacc[nj], qa[kk], bbf[kk]);
        }

        // ---- online softmax (exp2 domain) ----
        float corr[2];
#pragma unroll
        for (int h2 = 0; h2 < 2; h2++) {
            float mx = -3.0e38f;
#pragma unroll
            for (int nj = 0; nj < 8; nj++)
                mx = fmaxf(mx, fmaxf(sacc[nj][h2 * 2], sacc[nj][h2 * 2 + 1]));
            mx = fmaxf(mx, __shfl_xor_sync(0xffffffffu, mx, 1));
            mx = fmaxf(mx, __shfl_xor_sync(0xffffffffu, mx, 2));
            float mnew = fmaxf(mrun[h2], mx);
            float cr = exp2f(mrun[h2] - mnew);
            corr[h2] = cr;
            mrun[h2] = mnew;
            float ls = 0.f;
#pragma unroll
            for (int nj = 0; nj < 8; nj++) {
                float p0 = exp2f(sacc[nj][h2 * 2] - mnew);
                float p1 = exp2f(sacc[nj][h2 * 2 + 1] - mnew);
                sacc[nj][h2 * 2] = p0;
                sacc[nj][h2 * 2 + 1] = p1;
                ls += p0 + p1;
            }
            ls += __shfl_xor_sync(0xffffffffu, ls, 1);
            ls += __shfl_xor_sync(0xffffffffu, ls, 2);
            lrun[h2] = lrun[h2] * cr + ls;
#pragma unroll
            for (int ci = 0; ci < 4; ci++) {
                o[ci][h2 * 2] *= cr;
                o[ci][h2 * 2 + 1] *= cr;
            }
        }

        // ---- O += P V (3 split products) per 16-key tile ----
#pragma unroll
        for (int kt = 0; kt < 4; kt++) {
            uint32_t ph[4], pl[4];
#pragma unroll
            for (int half = 0; half < 2; half++) {
                float* sp = sacc[2 * kt + half];
#pragma unroll
                for (int rr = 0; rr < 2; rr++) {
                    float f0 = sp[rr * 2], f1 = sp[rr * 2 + 1];
                    uint32_t hp = pack_bf16x2(f0, f1);
                    __nv_bfloat16 h0 = __float2bfloat16(f0);
                    __nv_bfloat16 h1 = __float2bfloat16(f1);
                    uint32_t lp = pack_bf16x2(f0 - __bfloat162float(h0),
                                              f1 - __bfloat162float(h1));
                    ph[half * 2 + rr] = hp;
                    pl[half * 2 + rr] = lp;
                }
            }
            uint32_t vbh[4][2], vbl[4][2];
#pragma unroll
            for (int ci = 0; ci < 4; ci++) {
                int ch = ci * 8 + g;
                int kk0 = kt * 16 + qu;
                vbh[ci][0] = *(const uint32_t*)&Vh[ch][kk0];
                vbh[ci][1] = *(const uint32_t*)&Vh[ch][kk0 + 8];
                vbl[ci][0] = *(const uint32_t*)&Vl[ch][kk0];
                vbl[ci][1] = *(const uint32_t*)&Vl[ch][kk0 + 8];
            }
#pragma unroll
            for (int ci = 0; ci < 4; ci++) {
                mma16816(o[ci], ph, vbh[ci]);
                mma16816(o[ci], pl, vbh[ci]);
                mma16816(o[ci], ph, vbl[ci]);
            }
        }
    }

    // ---- normalize + store ----
#pragma unroll
    for (int h2 = 0; h2 < 2; h2++) {
        float invl = 1.0f / lrun[h2];
        int qrow = q0 + wid * 16 + g + h2 * 8;
#pragma unroll
        for (int ci = 0; ci < 4; ci++) {
            int ch = ci * 8 + qu;
            g_att[((size_t)b * CC + hh * DH + ch) * NPIX + qrow] =
                o[ci][h2 * 2] * invl;
            g_att[((size_t)b * CC + hh * DH + ch + 1) * NPIX + qrow] =
                o[ci][h2 * 2 + 1] * invl;
        }
    }
}

// ---------------------------------------------------------------------------
extern "C" void kernel_launch(void* const* d_in, const int* in_sizes, int n_in,
                              void* d_out, int out_size) {
    const float* x      = (const float*)d_in[0];
    const float* norm_w = (const float*)d_in[1];
    const float* norm_b = (const float*)d_in[2];
    const float* qkv_w  = (const float*)d_in[3];
    const float* qkv_b  = (const float*)d_in[4];
    const float* proj_w = (const float*)d_in[5];
    const float* proj_b = (const float*)d_in[6];
    float* out = (float*)d_out;

    float *g_h_p, *g_qkv_p, *g_att_p;
    cudaGetSymbolAddress((void**)&g_h_p, g_h);
    cudaGetSymbolAddress((void**)&g_qkv_p, g_qkv);
    cudaGetSymbolAddress((void**)&g_att_p, g_att);

    // K1: norm
    norm_kernel<<<(BB * NPIX) / 256, 256>>>(x, norm_w, norm_b);

    // K2: qkv = qkv_w @ h  -> [b, 384, n]
    gemm_kernel<<<dim3(NPIX / 128, 384 / 64, BB), 256>>>(
        qkv_w, qkv_b, g_h_p, g_qkv_p, nullptr, 3 * CC);

    // K2b/K2c: split into bf16 hi/lo operand layouts
    split_qk_kernel<<<(BB * NH * NPIX) / 256, 256>>>();
    split_v_kernel<<<(BB * NH * DH * NPIX) / 256, 256>>>();

    // K3: tensor-core attention -> g_att [b, 128, n]
    attn_mma_kernel<<<dim3(NPIX / 128, NH, BB), 256>>>();

    // K4: proj + bias + residual -> d_out
    gemm_kernel<<<dim3(NPIX / 128, CC / 64, BB), 256>>>(
        proj_w, proj_b, g_att_p, out, x, CC);
}

// round 6
// speedup vs baseline: 3.7848x; 1.3097x over previous
#include <cuda_runtime.h>
#include <cuda_fp16.h>
#include <math.h>
#include <stdint.h>

#define BB 4
#define CC 128
#define NPIX 4096
#define NH 4
#define DH 32
#define EPSF 1e-6f
// (1/sqrt(32)) * log2(e)
#define SCALE2 0.25503486f

// Scratch (device globals; no allocation in kernel_launch)
__device__ float g_h[BB * CC * NPIX];        // normalized input  [b, c, n]
__device__ float g_qkv[BB * 3 * CC * NPIX];  // qkv               [b, o, n]
__device__ float g_att[BB * CC * NPIX];      // attention output  [b, c, n]
// split-fp16 attention operands
__device__ __half g_q2[BB * NH * NPIX * 64];  // [b,h,n, ch: hi0-31|lo32-63]
__device__ __half g_k2[BB * NH * NPIX * 64];  // same layout
__device__ __half g_v16[BB * NH * DH * NPIX]; // [b,h,c,n] plain fp16

// ---------------------------------------------------------------------------
// K1: per-pixel channel LayerNorm
// ---------------------------------------------------------------------------
__global__ void norm_kernel(const float* __restrict__ x,
                            const float* __restrict__ w,
                            const float* __restrict__ bias) {
    int pix = blockIdx.x * blockDim.x + threadIdx.x;
    int b = pix >> 12;
    int n = pix & (NPIX - 1);
    const float* xp = x + (size_t)b * CC * NPIX + n;
    float s = 0.f, s2 = 0.f;
#pragma unroll 8
    for (int c = 0; c < CC; c++) {
        float v = xp[(size_t)c * NPIX];
        s += v;
        s2 += v * v;
    }
    float mean = s * (1.0f / CC);
    float var  = s2 * (1.0f / CC) - mean * mean;
    float inv  = rsqrtf(var + EPSF);
    float* hp = g_h + (size_t)b * CC * NPIX + n;
#pragma unroll 8
    for (int c = 0; c < CC; c++) {
        float v = xp[(size_t)c * NPIX];
        hp[(size_t)c * NPIX] = (v - mean) * inv * w[c] + bias[c];
    }
}

// ---------------------------------------------------------------------------
// K2/K4: SIMT GEMM (unchanged)
// ---------------------------------------------------------------------------
__global__ void gemm_kernel(const float* __restrict__ W,
                            const float* __restrict__ bias,
                            const float* __restrict__ In,
                            float* __restrict__ Out,
                            const float* __restrict__ resid,
                            int OCtot) {
    __shared__ float Ws[64][33];
    __shared__ float Hs[32][128];

    const int b  = blockIdx.z;
    const int o0 = blockIdx.y * 64;
    const int n0 = blockIdx.x * 128;
    const int tid = threadIdx.x;
    const int to = tid >> 4;
    const int tn = tid & 15;

    float acc[4][8];
#pragma unroll
    for (int i = 0; i < 4; i++)
#pragma unroll
        for (int j = 0; j < 8; j++) acc[i][j] = 0.f;

    for (int kk = 0; kk < CC; kk += 32) {
        __syncthreads();
        for (int idx = tid; idx < 64 * 32; idx += 256) {
            int o = idx >> 5, k = idx & 31;
            Ws[o][k] = W[(size_t)(o0 + o) * CC + kk + k];
        }
        for (int idx = tid; idx < 32 * 128; idx += 256) {
            int k = idx >> 7, n = idx & 127;
            Hs[k][n] = In[((size_t)b * CC + kk + k) * NPIX + n0 + n];
        }
        __syncthreads();
#pragma unroll
        for (int k = 0; k < 32; k++) {
            float wv[4];
#pragma unroll
            for (int i = 0; i < 4; i++) wv[i] = Ws[to * 4 + i][k];
            float4 h0 = *(const float4*)&Hs[k][tn * 4];
            float4 h1 = *(const float4*)&Hs[k][64 + tn * 4];
            float hv[8] = {h0.x, h0.y, h0.z, h0.w, h1.x, h1.y, h1.z, h1.w};
#pragma unroll
            for (int i = 0; i < 4; i++)
#pragma unroll
                for (int j = 0; j < 8; j++) acc[i][j] = fmaf(wv[i], hv[j], acc[i][j]);
        }
    }

#pragma unroll
    for (int i = 0; i < 4; i++) {
        int o = o0 + to * 4 + i;
        float bb = bias[o];
#pragma unroll
        for (int j = 0; j < 8; j++) {
            int n = n0 + ((j < 4) ? (tn * 4 + j) : (64 + tn * 4 + (j - 4)));
            size_t oidx = ((size_t)b * OCtot + o) * NPIX + n;
            float v = acc[i][j] + bb;
            if (resid) v += resid[((size_t)b * CC + o) * NPIX + n];
            Out[oidx] = v;
        }
    }
}

// ---------------------------------------------------------------------------
// helpers
// ---------------------------------------------------------------------------
__device__ __forceinline__ void mma16816h(float* d, const uint32_t* a,
                                          const uint32_t* b) {
    asm volatile(
        "mma.sync.aligned.m16n8k16.row.col.f32.f16.f16.f32 "
        "{%0,%1,%2,%3},{%4,%5,%6,%7},{%8,%9},{%0,%1,%2,%3};"
        : "+f"(d[0]), "+f"(d[1]), "+f"(d[2]), "+f"(d[3])
        : "r"(a[0]), "r"(a[1]), "r"(a[2]), "r"(a[3]), "r"(b[0]), "r"(b[1]));
}

// low 16 bits = a, high 16 bits = b
__device__ __forceinline__ uint32_t pack_f16x2(float a, float b) {
    uint32_t r;
    asm("cvt.rn.f16x2.f32 %0, %1, %2;" : "=r"(r) : "f"(b), "f"(a));
    return r;
}

// ---------------------------------------------------------------------------
// K2b: split Q/K into fp16 hi|lo rows [b,h,n,64]; Q scaled by SCALE2
// one thread per (b,h,n)
// ---------------------------------------------------------------------------
__global__ void split_qk_kernel() {
    int t = blockIdx.x * 256 + threadIdx.x;   // 0 .. 65535
    int b = t >> 14, h = (t >> 12) & 3, n = t & (NPIX - 1);
    const float* qs = g_qkv + ((size_t)(b * 3) * CC + h * DH) * NPIX + n;
    const float* ks = qs + (size_t)CC * NPIX;
    __half* qdst = g_q2 + ((size_t)(b * NH + h) * NPIX + n) * 64;
    __half* kdst = g_k2 + ((size_t)(b * NH + h) * NPIX + n) * 64;

#pragma unroll
    for (int p = 0; p < 8; p++) {
        int c = p * 4;
        float q0 = qs[(size_t)(c + 0) * NPIX] * SCALE2;
        float q1 = qs[(size_t)(c + 1) * NPIX] * SCALE2;
        float q2 = qs[(size_t)(c + 2) * NPIX] * SCALE2;
        float q3 = qs[(size_t)(c + 3) * NPIX] * SCALE2;
        __half h0 = __float2half_rn(q0), h1 = __float2half_rn(q1);
        __half h2 = __float2half_rn(q2), h3 = __float2half_rn(q3);
        uint32_t hA = ((uint32_t)*(unsigned short*)&h0) |
                      ((uint32_t)*(unsigned short*)&h1 << 16);
        uint32_t hB = ((uint32_t)*(unsigned short*)&h2) |
                      ((uint32_t)*(unsigned short*)&h3 << 16);
        uint32_t lA = pack_f16x2(q0 - __half2float(h0), q1 - __half2float(h1));
        uint32_t lB = pack_f16x2(q2 - __half2float(h2), q3 - __half2float(h3));
        *(uint2*)(qdst + c)      = make_uint2(hA, hB);
        *(uint2*)(qdst + 32 + c) = make_uint2(lA, lB);

        float k0 = ks[(size_t)(c + 0) * NPIX];
        float k1 = ks[(size_t)(c + 1) * NPIX];
        float k2 = ks[(size_t)(c + 2) * NPIX];
        float k3 = ks[(size_t)(c + 3) * NPIX];
        __half g0 = __float2half_rn(k0), g1 = __float2half_rn(k1);
        __half g2 = __float2half_rn(k2), g3 = __float2half_rn(k3);
        uint32_t khA = ((uint32_t)*(unsigned short*)&g0) |
                       ((uint32_t)*(unsigned short*)&g1 << 16);
        uint32_t khB = ((uint32_t)*(unsigned short*)&g2) |
                       ((uint32_t)*(unsigned short*)&g3 << 16);
        uint32_t klA = pack_f16x2(k0 - __half2float(g0), k1 - __half2float(g1));
        uint32_t klB = pack_f16x2(k2 - __half2float(g2), k3 - __half2float(g3));
        *(uint2*)(kdst + c)      = make_uint2(khA, khB);
        *(uint2*)(kdst + 32 + c) = make_uint2(klA, klB);
    }
}

// ---------------------------------------------------------------------------
// K2c: V -> plain fp16 [b,h,c,n]; one thread per element
// ---------------------------------------------------------------------------
__global__ void split_v_kernel() {
    size_t t = (size_t)blockIdx.x * 256 + threadIdx.x;  // 0 .. 2097151
    g_v16[t] = __float2half_rn(
        g_qkv[((size_t)((t >> 19) * 3 + 2) * CC) * NPIX +
              (((t >> 17) & (NH - 1)) * DH + ((t >> 12) & (DH - 1))) * NPIX +
              (t & (NPIX - 1))]);
}

// ---------------------------------------------------------------------------
// K3: flash attention via fp16 mma.sync.
// CTA = 256 threads (8 warps), warp = 16 q rows -> 128 q per CTA.
// Key chunks of 64. QK split-fp16 (k=64). P, V plain fp16.
// ---------------------------------------------------------------------------
__global__ void __launch_bounds__(256) attn_mma_kernel() {
    __shared__ __align__(16) __half Ks[64][72];  // [key][ch hi|lo]
    __shared__ __align__(16) __half Vs[32][72];  // [ch][key]

    const int tid = threadIdx.x;
    const int lane = tid & 31;
    const int wid = tid >> 5;      // 0..7
    const int g = lane >> 2;
    const int qu = (lane & 3) * 2;
    const int b = blockIdx.z, hh = blockIdx.y;
    const int q0 = blockIdx.x * 128;
    const int bh = b * NH + hh;

    const __half* qgl = g_q2 + ((size_t)bh * NPIX + q0 + wid * 16) * 64;
    const __half* kgl = g_k2 + (size_t)bh * NPIX * 64;
    const __half* vgl = g_v16 + (size_t)bh * DH * NPIX;

    // ---- persistent Q A-fragments (direct from global) ----
    uint32_t qa[4][4];
#pragma unroll
    for (int kk = 0; kk < 4; kk++) {
        int c0 = kk * 16 + qu;
        qa[kk][0] = *(const uint32_t*)(qgl + (size_t)g * 64 + c0);
        qa[kk][1] = *(const uint32_t*)(qgl + (size_t)(g + 8) * 64 + c0);
        qa[kk][2] = *(const uint32_t*)(qgl + (size_t)g * 64 + c0 + 8);
        qa[kk][3] = *(const uint32_t*)(qgl + (size_t)(g + 8) * 64 + c0 + 8);
    }

    float o[4][4];
#pragma unroll
    for (int ci = 0; ci < 4; ci++)
#pragma unroll
        for (int r = 0; r < 4; r++) o[ci][r] = 0.f;
    float mrun[2] = {-3.0e38f, -3.0e38f};
    float lrun[2] = {0.f, 0.f};

    const int krow0 = tid >> 3, kpart = tid & 7;
    const int vrow = tid >> 3;

    for (int m0 = 0; m0 < NPIX; m0 += 64) {
        __syncthreads();
        // ---- fill smem: pure uint4 copies ----
        *(uint4*)&Ks[krow0][kpart * 8] =
            *(const uint4*)(kgl + (size_t)(m0 + krow0) * 64 + kpart * 8);
        *(uint4*)&Ks[krow0 + 32][kpart * 8] =
            *(const uint4*)(kgl + (size_t)(m0 + krow0 + 32) * 64 + kpart * 8);
        *(uint4*)&Vs[vrow][kpart * 8] =
            *(const uint4*)(vgl + (size_t)vrow * NPIX + m0 + kpart * 8);
        __syncthreads();

        // ---- S = Q K^T (k=64 incl. hi|lo cross terms) ----
        float sacc[8][4];
#pragma unroll
        for (int nj = 0; nj < 8; nj++) {
            uint32_t bbf[4][2];
            int kn = nj * 8 + g;
#pragma unroll
            for (int kk = 0; kk < 4; kk++) {
                bbf[kk][0] = *(const uint32_t*)&Ks[kn][kk * 16 + qu];
                bbf[kk][1] = *(const uint32_t*)&Ks[kn][kk * 16 + qu + 8];
            }
#pragma unroll
            for (int r = 0; r < 4; r++) sacc[nj][r] = 0.f;
#pragma unroll
            for (int kk = 0; kk < 4; kk++) mma16816h(sacc[nj], qa[kk], bbf[kk]);
        }

        // ---- online softmax (exp2 domain) ----
#pragma unroll
        for (int h2 = 0; h2 < 2; h2++) {
            float mx = -3.0e38f;
#pragma unroll
            for (int nj = 0; nj < 8; nj++)
                mx = fmaxf(mx, fmaxf(sacc[nj][h2 * 2], sacc[nj][h2 * 2 + 1]));
            mx = fmaxf(mx, __shfl_xor_sync(0xffffffffu, mx, 1));
            mx = fmaxf(mx, __shfl_xor_sync(0xffffffffu, mx, 2));
            float mnew = fmaxf(mrun[h2], mx);
            float cr = exp2f(mrun[h2] - mnew);
            mrun[h2] = mnew;
            float ls = 0.f;
#pragma unroll
            for (int nj = 0; nj < 8; nj++) {
                float p0 = exp2f(sacc[nj][h2 * 2] - mnew);
                float p1 = exp2f(sacc[nj][h2 * 2 + 1] - mnew);
                sacc[nj][h2 * 2] = p0;
                sacc[nj][h2 * 2 + 1] = p1;
                ls += p0 + p1;
            }
            ls += __shfl_xor_sync(0xffffffffu, ls, 1);
            ls += __shfl_xor_sync(0xffffffffu, ls, 2);
            lrun[h2] = lrun[h2] * cr + ls;
#pragma unroll
            for (int ci = 0; ci < 4; ci++) {
                o[ci][h2 * 2] *= cr;
                o[ci][h2 * 2 + 1] *= cr;
            }
        }

        // ---- O += P V (single fp16 product) per 16-key tile ----
#pragma unroll
        for (int kt = 0; kt < 4; kt++) {
            uint32_t ph[4];
#pragma unroll
            for (int half = 0; half < 2; half++) {
                float* sp = sacc[2 * kt + half];
                ph[half * 2 + 0] = pack_f16x2(sp[0], sp[1]);
                ph[half * 2 + 1] = pack_f16x2(sp[2], sp[3]);
            }
            uint32_t vb[4][2];
#pragma unroll
            for (int ci = 0; ci < 4; ci++) {
                int ch = ci * 8 + g;
                int kk0 = kt * 16 + qu;
                vb[ci][0] = *(const uint32_t*)&Vs[ch][kk0];
                vb[ci][1] = *(const uint32_t*)&Vs[ch][kk0 + 8];
            }
#pragma unroll
            for (int ci = 0; ci < 4; ci++) mma16816h(o[ci], ph, vb[ci]);
        }
    }

    // ---- normalize + store ----
#pragma unroll
    for (int h2 = 0; h2 < 2; h2++) {
        float invl = 1.0f / lrun[h2];
        int qrow = q0 + wid * 16 + g + h2 * 8;
#pragma unroll
        for (int ci = 0; ci < 4; ci++) {
            int ch = ci * 8 + qu;
            g_att[((size_t)b * CC + hh * DH + ch) * NPIX + qrow] =
                o[ci][h2 * 2] * invl;
            g_att[((size_t)b * CC + hh * DH + ch + 1) * NPIX + qrow] =
                o[ci][h2 * 2 + 1] * invl;
        }
    }
}

// ---------------------------------------------------------------------------
extern "C" void kernel_launch(void* const* d_in, const int* in_sizes, int n_in,
                              void* d_out, int out_size) {
    const float* x      = (const float*)d_in[0];
    const float* norm_w = (const float*)d_in[1];
    const float* norm_b = (const float*)d_in[2];
    const float* qkv_w  = (const float*)d_in[3];
    const float* qkv_b  = (const float*)d_in[4];
    const float* proj_w = (const float*)d_in[5];
    const float* proj_b = (const float*)d_in[6];
    float* out = (float*)d_out;

    float *g_h_p, *g_qkv_p, *g_att_p;
    cudaGetSymbolAddress((void**)&g_h_p, g_h);
    cudaGetSymbolAddress((void**)&g_qkv_p, g_qkv);
    cudaGetSymbolAddress((void**)&g_att_p, g_att);

    // K1: norm
    norm_kernel<<<(BB * NPIX) / 256, 256>>>(x, norm_w, norm_b);

    // K2: qkv = qkv_w @ h  -> [b, 384, n]
    gemm_kernel<<<dim3(NPIX / 128, 384 / 64, BB), 256>>>(
        qkv_w, qkv_b, g_h_p, g_qkv_p, nullptr, 3 * CC);

    // K2b/K2c: fp16 operand layouts
    split_qk_kernel<<<(BB * NH * NPIX) / 256, 256>>>();
    split_v_kernel<<<(BB * NH * DH * NPIX) / 256, 256>>>();

    // K3: tensor-core attention -> g_att [b, 128, n]
    attn_mma_kernel<<<dim3(NPIX / 128, NH, BB), 256>>>();

    // K4: proj + bias + residual -> d_out
    gemm_kernel<<<dim3(NPIX / 128, CC / 64, BB), 256>>>(
        proj_w, proj_b, g_att_p, out, x, CC);
}

// round 8
// speedup vs baseline: 3.8279x; 1.0114x over previous
#include <cuda_runtime.h>
#include <cuda_fp16.h>
#include <math.h>
#include <stdint.h>

#define BB 4
#define CC 128
#define NPIX 4096
#define NH 4
#define DH 32
#define EPSF 1e-6f
// (1/sqrt(32)) * log2(e)
#define SCALE2 0.25503486f

// Scratch (device globals)
__device__ float  g_qkv[BB * 3 * CC * NPIX];          // qkv fp32 [b][o][n]
__device__ __half g_ht[(size_t)BB * NPIX * CC];        // normed h fp16 [b][n][c]
__device__ __half g_wq[384 * 256];                     // qkv_w split hi|lo
__device__ __half g_wp[128 * 256];                     // proj_w split hi|lo
__device__ __half g_q16[(size_t)BB * NH * NPIX * DH];  // [bh][n][c], scaled
__device__ __half g_k16[(size_t)BB * NH * NPIX * DH];  // [bh][n][c]
__device__ __half g_v16[(size_t)BB * NH * DH * NPIX];  // [bh][c][n]
__device__ __half g_at[(size_t)BB * NPIX * CC];        // attn out fp16 [b][n][c]

// ---------------------------------------------------------------------------
// fast exp2 on the FMA pipe (no MUFU). |rel err| ~2e-6 for x in [-100, 0].
// ---------------------------------------------------------------------------
__device__ __forceinline__ float fexp2(float x) {
    x = fmaxf(x, -100.0f);
    float z = x + 12582912.0f;              // 1.5*2^23: RN encodes int(x)
    int i = __float_as_int(z) << 23;        // integer part -> exponent field
    float r = x - (z - 12582912.0f);        // r in [-0.5, 0.5]
    float p = 1.0f + r * (0.69314718f + r * (0.24022650f + r * (0.05550411f +
              r * (0.00961813f + r * 0.00133336f))));
    return __int_as_float(__float_as_int(p) + i);
}

// ---------------------------------------------------------------------------
// mma helpers
// ---------------------------------------------------------------------------
__device__ __forceinline__ void mma16816h(float* d, const uint32_t* a,
                                          const uint32_t* b) {
    asm volatile(
        "mma.sync.aligned.m16n8k16.row.col.f32.f16.f16.f32 "
        "{%0,%1,%2,%3},{%4,%5,%6,%7},{%8,%9},{%0,%1,%2,%3};"
        : "+f"(d[0]), "+f"(d[1]), "+f"(d[2]), "+f"(d[3])
        : "r"(a[0]), "r"(a[1]), "r"(a[2]), "r"(a[3]), "r"(b[0]), "r"(b[1]));
}

__device__ __forceinline__ uint32_t pack_f16x2(float a, float b) {
    uint32_t r;
    asm("cvt.rn.f16x2.f32 %0, %1, %2;" : "=r"(r) : "f"(b), "f"(a));
    return r;
}

// ---------------------------------------------------------------------------
// K0: weight split (qkv_w and proj_w -> fp16 hi|lo, [o][256])
// ---------------------------------------------------------------------------
__global__ void wconv_kernel(const float* __restrict__ qkv_w,
                             const float* __restrict__ proj_w) {
    int t = blockIdx.x * 256 + threadIdx.x;   // 0 .. 65535
    const float* src;
    __half* dst;
    int idx;
    if (t < 384 * 128) { src = qkv_w; dst = g_wq; idx = t; }
    else               { src = proj_w; dst = g_wp; idx = t - 384 * 128; }
    int row = idx >> 7, c = idx & 127;
    float v = src[idx];
    __half hi = __float2half_rn(v);
    dst[row * 256 + c] = hi;
    dst[row * 256 + 128 + c] = __float2half_rn(v - __half2float(hi));
}

// ---------------------------------------------------------------------------
// K1: per-pixel channel LayerNorm -> fp16 [b][n][c]
// ---------------------------------------------------------------------------
__global__ void norm_kernel(const float* __restrict__ x,
                            const float* __restrict__ w,
                            const float* __restrict__ bias) {
    int pix = blockIdx.x * blockDim.x + threadIdx.x;
    int b = pix >> 12;
    int n = pix & (NPIX - 1);
    const float* xp = x + (size_t)b * CC * NPIX + n;
    float s = 0.f, s2 = 0.f;
#pragma unroll 8
    for (int c = 0; c < CC; c++) {
        float v = xp[(size_t)c * NPIX];
        s += v;
        s2 += v * v;
    }
    float mean = s * (1.0f / CC);
    float var  = s2 * (1.0f / CC) - mean * mean;
    float inv  = rsqrtf(var + EPSF);
    __half* hp = g_ht + ((size_t)b * NPIX + n) * CC;
#pragma unroll 4
    for (int c = 0; c < CC; c += 2) {
        float v0 = (xp[(size_t)c * NPIX] - mean) * inv * w[c] + bias[c];
        float v1 = (xp[(size_t)(c + 1) * NPIX] - mean) * inv * w[c + 1] + bias[c + 1];
        *(__half2*)(hp + c) = __floats2half2_rn(v0, v1);
    }
}

// ---------------------------------------------------------------------------
// K2/K4: fp16 tensor-core GEMM. Out[b,o,n] = (Wh+Wl)[o,:]·H[b,n,:] + bias (+resid)
// CTA 256 thr (8 warps), tile 64 o x 128 n. W split -> 2 MMAs per kstep.
// ---------------------------------------------------------------------------
__global__ void __launch_bounds__(256) gemm16_kernel(
    const __half* __restrict__ W2, const float* __restrict__ bias,
    const __half* __restrict__ Hin, float* __restrict__ Out,
    const float* __restrict__ resid, int Otot) {
    __shared__ __align__(16) __half Hs[128][136];

    const int tid = threadIdx.x, lane = tid & 31, wid = tid >> 5;
    const int g = lane >> 2, qu = (lane & 3) * 2;
    const int b = blockIdx.z, o0 = blockIdx.y * 64, n0 = blockIdx.x * 128;
    const int os = wid & 3, ns = wid >> 2;

    // load H tile [128 n][128 c], pure uint4 copies
    {
        const __half* hsrc = Hin + ((size_t)b * NPIX + n0) * CC;
        int row = tid >> 1, part = tid & 1;
#pragma unroll
        for (int j = 0; j < 8; j++)
            *(uint4*)&Hs[row][part * 64 + j * 8] =
                *(const uint4*)(hsrc + (size_t)row * CC + part * 64 + j * 8);
    }
    __syncthreads();

    float acc[8][4];
#pragma unroll
    for (int nj = 0; nj < 8; nj++)
#pragma unroll
        for (int r = 0; r < 4; r++) acc[nj][r] = 0.f;

    const __half* w0 = W2 + (size_t)(o0 + os * 16 + g) * 256;
    const __half* w8 = w0 + 8 * 256;

#pragma unroll
    for (int kk = 0; kk < 8; kk++) {
        int c0 = kk * 16 + qu;
        uint32_t ah[4], al[4];
        ah[0] = *(const uint32_t*)(w0 + c0);
        ah[1] = *(const uint32_t*)(w8 + c0);
        ah[2] = *(const uint32_t*)(w0 + c0 + 8);
        ah[3] = *(const uint32_t*)(w8 + c0 + 8);
        al[0] = *(const uint32_t*)(w0 + 128 + c0);
        al[1] = *(const uint32_t*)(w8 + 128 + c0);
        al[2] = *(const uint32_t*)(w0 + 128 + c0 + 8);
        al[3] = *(const uint32_t*)(w8 + 128 + c0 + 8);
#pragma unroll
        for (int nj = 0; nj < 8; nj++) {
            uint32_t bf[2];
            const __half* hrow = &Hs[ns * 64 + nj * 8 + g][0];
            bf[0] = *(const uint32_t*)(hrow + c0);
            bf[1] = *(const uint32_t*)(hrow + c0 + 8);
            mma16816h(acc[nj], ah, bf);
            mma16816h(acc[nj], al, bf);
        }
    }

    const int orow = o0 + os * 16 + g;
    const float b0 = bias[orow], b8 = bias[orow + 8];
#pragma unroll
    for (int nj = 0; nj < 8; nj++) {
        int n = n0 + ns * 64 + nj * 8 + qu;
        float2 v0 = make_float2(acc[nj][0] + b0, acc[nj][1] + b0);
        float2 v1 = make_float2(acc[nj][2] + b8, acc[nj][3] + b8);
        if (resid) {
            float2 r0 = *(const float2*)(resid + ((size_t)b * Otot + orow) * NPIX + n);
            float2 r1 = *(const float2*)(resid + ((size_t)b * Otot + orow + 8) * NPIX + n);
            v0.x += r0.x; v0.y += r0.y;
            v1.x += r1.x; v1.y += r1.y;
        }
        *(float2*)(Out + ((size_t)b * Otot + orow) * NPIX + n) = v0;
        *(float2*)(Out + ((size_t)b * Otot + orow + 8) * NPIX + n) = v1;
    }
}

// ---------------------------------------------------------------------------
// K2b: qkv fp32 -> fp16 operand layouts (Q scaled; Q/K [bh][n][c], V [bh][c][n])
// ---------------------------------------------------------------------------
__global__ void convqkv_kernel() {
    int t = blockIdx.x * 256 + threadIdx.x;   // 0 .. 65535
    int b = t >> 14, h = (t >> 12) & 3, n = t & (NPIX - 1);
    int bh = b * NH + h;
    const float* qs = g_qkv + ((size_t)(b * 3) * CC + h * DH) * NPIX + n;
    const float* ks = qs + (size_t)CC * NPIX;
    const float* vs = ks + (size_t)CC * NPIX;
    __half* qd = g_q16 + ((size_t)bh * NPIX + n) * DH;
    __half* kd = g_k16 + ((size_t)bh * NPIX + n) * DH;
    __half* vd = g_v16 + (size_t)bh * DH * NPIX + n;
#pragma unroll
    for (int c = 0; c < DH; c += 2) {
        *(__half2*)(qd + c) = __floats2half2_rn(qs[(size_t)c * NPIX] * SCALE2,
                                                qs[(size_t)(c + 1) * NPIX] * SCALE2);
        *(__half2*)(kd + c) = __floats2half2_rn(ks[(size_t)c * NPIX],
                                                ks[(size_t)(c + 1) * NPIX]);
    }
#pragma unroll
    for (int c = 0; c < DH; c++)
        vd[(size_t)c * NPIX] = __float2half_rn(vs[(size_t)c * NPIX]);
}

// ---------------------------------------------------------------------------
// K3: flash attention, plain fp16 mma (QK k=32, PV k=64), fexp2 softmax.
// CTA 256 thr (8 warps), warp = 16 q rows -> 128 q per CTA. 64-key chunks.
// ---------------------------------------------------------------------------
__global__ void __launch_bounds__(256) attn_mma_kernel() {
    __shared__ __align__(16) __half Ks[64][40];  // [key][ch] (80B row, 16-aligned)
    __shared__ __align__(16) __half Vs[32][72];  // [ch][key] (144B row, 16-aligned)

    const int tid = threadIdx.x;
    const int lane = tid & 31;
    const int wid = tid >> 5;
    const int g = lane >> 2;
    const int qu = (lane & 3) * 2;
    const int b = blockIdx.z, hh = blockIdx.y;
    const int q0 = blockIdx.x * 128;
    const int bh = b * NH + hh;

    const __half* qgl = g_q16 + ((size_t)bh * NPIX + q0 + wid * 16) * DH;
    const __half* kgl = g_k16 + (size_t)bh * NPIX * DH;
    const __half* vgl = g_v16 + (size_t)bh * DH * NPIX;

    // persistent Q A-fragments (k=32 -> 2 ksteps)
    uint32_t qa[2][4];
#pragma unroll
    for (int kk = 0; kk < 2; kk++) {
        int c0 = kk * 16 + qu;
        qa[kk][0] = *(const uint32_t*)(qgl + (size_t)g * DH + c0);
        qa[kk][1] = *(const uint32_t*)(qgl + (size_t)(g + 8) * DH + c0);
        qa[kk][2] = *(const uint32_t*)(qgl + (size_t)g * DH + c0 + 8);
        qa[kk][3] = *(const uint32_t*)(qgl + (size_t)(g + 8) * DH + c0 + 8);
    }

    float o[4][4];
#pragma unroll
    for (int ci = 0; ci < 4; ci++)
#pragma unroll
        for (int r = 0; r < 4; r++) o[ci][r] = 0.f;
    float mrun[2] = {-3.0e38f, -3.0e38f};
    float lrun[2] = {0.f, 0.f};

    const int krow = tid >> 2, kpart = tid & 3;   // 64 rows x 4 uint4
    const int vrow = tid >> 3, vpart = tid & 7;   // 32 rows x 8 uint4

    for (int m0 = 0; m0 < NPIX; m0 += 64) {
        __syncthreads();
        *(uint4*)&Ks[krow][kpart * 8] =
            *(const uint4*)(kgl + (size_t)(m0 + krow) * DH + kpart * 8);
        *(uint4*)&Vs[vrow][vpart * 8] =
            *(const uint4*)(vgl + (size_t)vrow * NPIX + m0 + vpart * 8);
        __syncthreads();

        // ---- S = Q K^T (k=32) ----
        float sacc[8][4];
#pragma unroll
        for (int nj = 0; nj < 8; nj++) {
            const __half* krow_p = &Ks[nj * 8 + g][0];
#pragma unroll
            for (int r = 0; r < 4; r++) sacc[nj][r] = 0.f;
#pragma unroll
            for (int kk = 0; kk < 2; kk++) {
                uint32_t bf[2];
                bf[0] = *(const uint32_t*)(krow_p + kk * 16 + qu);
                bf[1] = *(const uint32_t*)(krow_p + kk * 16 + qu + 8);
                mma16816h(sacc[nj], qa[kk], bf);
            }
        }

        // ---- online softmax (fexp2, FMA pipe) ----
#pragma unroll
        for (int h2 = 0; h2 < 2; h2++) {
            float mx = -3.0e38f;
#pragma unroll
            for (int nj = 0; nj < 8; nj++)
                mx = fmaxf(mx, fmaxf(sacc[nj][h2 * 2], sacc[nj][h2 * 2 + 1]));
            mx = fmaxf(mx, __shfl_xor_sync(0xffffffffu, mx, 1));
            mx = fmaxf(mx, __shfl_xor_sync(0xffffffffu, mx, 2));
            float mnew = fmaxf(mrun[h2], mx);
            float cr = fexp2(mrun[h2] - mnew);
            mrun[h2] = mnew;
            float ls = 0.f;
#pragma unroll
            for (int nj = 0; nj < 8; nj++) {
                float p0 = fexp2(sacc[nj][h2 * 2] - mnew);
                float p1 = fexp2(sacc[nj][h2 * 2 + 1] - mnew);
                sacc[nj][h2 * 2] = p0;
                sacc[nj][h2 * 2 + 1] = p1;
                ls += p0 + p1;
            }
            ls += __shfl_xor_sync(0xffffffffu, ls, 1);
            ls += __shfl_xor_sync(0xffffffffu, ls, 2);
            lrun[h2] = lrun[h2] * cr + ls;
#pragma unroll
            for (int ci = 0; ci < 4; ci++) {
                o[ci][h2 * 2] *= cr;
                o[ci][h2 * 2 + 1] *= cr;
            }
        }

        // ---- O += P V per 16-key tile ----
#pragma unroll
        for (int kt = 0; kt < 4; kt++) {
            uint32_t ph[4];
#pragma unroll
            for (int half = 0; half < 2; half++) {
                float* sp = sacc[2 * kt + half];
                ph[half * 2 + 0] = pack_f16x2(sp[0], sp[1]);
                ph[half * 2 + 1] = pack_f16x2(sp[2], sp[3]);
            }
#pragma unroll
            for (int ci = 0; ci < 4; ci++) {
                uint32_t vb[2];
                const __half* vrow_p = &Vs[ci * 8 + g][kt * 16 + qu];
                vb[0] = *(const uint32_t*)(vrow_p);
                vb[1] = *(const uint32_t*)(vrow_p + 8);
                mma16816h(o[ci], ph, vb);
            }
        }
    }

    // ---- normalize + store fp16 [b][n][c] ----
#pragma unroll
    for (int h2 = 0; h2 < 2; h2++) {
        float invl = 1.0f / lrun[h2];
        int qrow = q0 + wid * 16 + g + h2 * 8;
        __half* od = g_at + ((size_t)b * NPIX + qrow) * CC + hh * DH;
#pragma unroll
        for (int ci = 0; ci < 4; ci++) {
            *(__half2*)(od + ci * 8 + qu) =
                __floats2half2_rn(o[ci][h2 * 2] * invl, o[ci][h2 * 2 + 1] * invl);
        }
    }
}

// ---------------------------------------------------------------------------
extern "C" void kernel_launch(void* const* d_in, const int* in_sizes, int n_in,
                              void* d_out, int out_size) {
    const float* x      = (const float*)d_in[0];
    const float* norm_w = (const float*)d_in[1];
    const float* norm_b = (const float*)d_in[2];
    const float* qkv_w  = (const float*)d_in[3];
    const float* qkv_b  = (const float*)d_in[4];
    const float* proj_w = (const float*)d_in[5];
    const float* proj_b = (const float*)d_in[6];
    float* out = (float*)d_out;

    float* g_qkv_p;
    __half *g_ht_p, *g_wq_p, *g_wp_p, *g_at_p;
    cudaGetSymbolAddress((void**)&g_qkv_p, g_qkv);
    cudaGetSymbolAddress((void**)&g_ht_p, g_ht);
    cudaGetSymbolAddress((void**)&g_wq_p, g_wq);
    cudaGetSymbolAddress((void**)&g_wp_p, g_wp);
    cudaGetSymbolAddress((void**)&g_at_p, g_at);

    // K0: weight split (independent of norm)
    wconv_kernel<<<256, 256>>>(qkv_w, proj_w);

    // K1: norm -> fp16 [b][n][c]
    norm_kernel<<<(BB * NPIX) / 256, 256>>>(x, norm_w, norm_b);

    // K2: qkv = qkv_w @ h -> fp32 [b][384][n]
    gemm16_kernel<<<dim3(NPIX / 128, 384 / 64, BB), 256>>>(
        g_wq_p, qkv_b, g_ht_p, g_qkv_p, nullptr, 3 * CC);

    // K2b: fp16 attention operand layouts
    convqkv_kernel<<<(BB * NH * NPIX) / 256, 256>>>();

    // K3: attention -> fp16 [b][n][c]
    attn_mma_kernel<<<dim3(NPIX / 128, NH, BB), 256>>>();

    // K4: proj + bias + residual -> d_out
    gemm16_kernel<<<dim3(NPIX / 128, CC / 64, BB), 256>>>(
        g_wp_p, proj_b, g_at_p, out, x, CC);
}

// round 9
// speedup vs baseline: 5.4830x; 1.4324x over previous
#include <cuda_runtime.h>
#include <cuda_fp16.h>
#include <math.h>
#include <stdint.h>

#define BB 4
#define CC 128
#define NPIX 4096
#define NH 4
#define DH 32
#define EPSF 1e-6f
// (1/sqrt(32)) * log2(e)
#define SCALE2 0.25503486f

// Scratch (device globals)
__device__ __half g_ht[(size_t)BB * NPIX * CC];        // normed h fp16 [b][n][c]
__device__ __half g_wq[384 * 256];                     // qkv_w split hi|lo
__device__ __half g_wp[128 * 256];                     // proj_w split hi|lo
__device__ __half g_q16[(size_t)BB * NH * NPIX * DH];  // [bh][n][c], scaled
__device__ __half g_k16[(size_t)BB * NH * NPIX * DH];  // [bh][n][c]
__device__ __half g_v16[(size_t)BB * NH * DH * NPIX];  // [bh][c][n]
__device__ __half g_at[(size_t)BB * NPIX * CC];        // attn out fp16 [b][n][c]

// ---------------------------------------------------------------------------
// helpers
// ---------------------------------------------------------------------------
__device__ __forceinline__ float ex2(float x) {
    float r;
    asm("ex2.approx.ftz.f32 %0, %1;" : "=f"(r) : "f"(x));
    return r;
}

__device__ __forceinline__ void mma16816h(float* d, const uint32_t* a,
                                          const uint32_t* b) {
    asm volatile(
        "mma.sync.aligned.m16n8k16.row.col.f32.f16.f16.f32 "
        "{%0,%1,%2,%3},{%4,%5,%6,%7},{%8,%9},{%0,%1,%2,%3};"
        : "+f"(d[0]), "+f"(d[1]), "+f"(d[2]), "+f"(d[3])
        : "r"(a[0]), "r"(a[1]), "r"(a[2]), "r"(a[3]), "r"(b[0]), "r"(b[1]));
}

__device__ __forceinline__ uint32_t pack_f16x2(float a, float b) {
    uint32_t r;
    asm("cvt.rn.f16x2.f32 %0, %1, %2;" : "=r"(r) : "f"(b), "f"(a));
    return r;
}

// ---------------------------------------------------------------------------
// K0: weight split (qkv_w and proj_w -> fp16 hi|lo, [o][256])
// ---------------------------------------------------------------------------
__global__ void wconv_kernel(const float* __restrict__ qkv_w,
                             const float* __restrict__ proj_w) {
    int t = blockIdx.x * 256 + threadIdx.x;   // 0 .. 65535
    const float* src;
    __half* dst;
    int idx;
    if (t < 384 * 128) { src = qkv_w; dst = g_wq; idx = t; }
    else               { src = proj_w; dst = g_wp; idx = t - 384 * 128; }
    int row = idx >> 7, c = idx & 127;
    float v = src[idx];
    __half hi = __float2half_rn(v);
    dst[row * 256 + c] = hi;
    dst[row * 256 + 128 + c] = __float2half_rn(v - __half2float(hi));
}

// ---------------------------------------------------------------------------
// K1: per-pixel channel LayerNorm -> fp16 [b][n][c]
// ---------------------------------------------------------------------------
__global__ void norm_kernel(const float* __restrict__ x,
                            const float* __restrict__ w,
                            const float* __restrict__ bias) {
    int pix = blockIdx.x * blockDim.x + threadIdx.x;
    int b = pix >> 12;
    int n = pix & (NPIX - 1);
    const float* xp = x + (size_t)b * CC * NPIX + n;
    float s = 0.f, s2 = 0.f;
#pragma unroll 8
    for (int c = 0; c < CC; c++) {
        float v = xp[(size_t)c * NPIX];
        s += v;
        s2 += v * v;
    }
    float mean = s * (1.0f / CC);
    float var  = s2 * (1.0f / CC) - mean * mean;
    float inv  = rsqrtf(var + EPSF);
    __half* hp = g_ht + ((size_t)b * NPIX + n) * CC;
#pragma unroll 4
    for (int c = 0; c < CC; c += 2) {
        float v0 = (xp[(size_t)c * NPIX] - mean) * inv * w[c] + bias[c];
        float v1 = (xp[(size_t)(c + 1) * NPIX] - mean) * inv * w[c + 1] + bias[c + 1];
        *(__half2*)(hp + c) = __floats2half2_rn(v0, v1);
    }
}

// ---------------------------------------------------------------------------
// K2: qkv GEMM with fused attention-layout epilogue.
// Tile 64 o x 128 n. o0<128 -> Q ([bh][n][c], scaled), <256 -> K, else V ([bh][c][n]).
// ---------------------------------------------------------------------------
__global__ void __launch_bounds__(256) gemmqkv_kernel(
    const float* __restrict__ bias) {
    __shared__ __align__(16) __half Hs[128][136];

    const int tid = threadIdx.x, lane = tid & 31, wid = tid >> 5;
    const int g = lane >> 2, qu = (lane & 3) * 2;
    const int b = blockIdx.z, o0 = blockIdx.y * 64, n0 = blockIdx.x * 128;
    const int os = wid & 3, ns = wid >> 2;

    {
        const __half* hsrc = g_ht + ((size_t)b * NPIX + n0) * CC;
        int row = tid >> 1, part = tid & 1;
#pragma unroll
        for (int j = 0; j < 8; j++)
            *(uint4*)&Hs[row][part * 64 + j * 8] =
                *(const uint4*)(hsrc + (size_t)row * CC + part * 64 + j * 8);
    }
    __syncthreads();

    float acc[8][4];
#pragma unroll
    for (int nj = 0; nj < 8; nj++)
#pragma unroll
        for (int r = 0; r < 4; r++) acc[nj][r] = 0.f;

    const __half* w0 = g_wq + (size_t)(o0 + os * 16 + g) * 256;
    const __half* w8 = w0 + 8 * 256;

#pragma unroll
    for (int kk = 0; kk < 8; kk++) {
        int c0 = kk * 16 + qu;
        uint32_t ah[4], al[4];
        ah[0] = *(const uint32_t*)(w0 + c0);
        ah[1] = *(const uint32_t*)(w8 + c0);
        ah[2] = *(const uint32_t*)(w0 + c0 + 8);
        ah[3] = *(const uint32_t*)(w8 + c0 + 8);
        al[0] = *(const uint32_t*)(w0 + 128 + c0);
        al[1] = *(const uint32_t*)(w8 + 128 + c0);
        al[2] = *(const uint32_t*)(w0 + 128 + c0 + 8);
        al[3] = *(const uint32_t*)(w8 + 128 + c0 + 8);
#pragma unroll
        for (int nj = 0; nj < 8; nj++) {
            uint32_t bf[2];
            const __half* hrow = &Hs[ns * 64 + nj * 8 + g][0];
            bf[0] = *(const uint32_t*)(hrow + c0);
            bf[1] = *(const uint32_t*)(hrow + c0 + 8);
            mma16816h(acc[nj], ah, bf);
            mma16816h(acc[nj], al, bf);
        }
    }

    const int orow = o0 + os * 16 + g;
    const float b0 = bias[orow], b8 = bias[orow + 8];

    if (o0 >= 256) {
        // ---- V: direct store [bh][c][n] ----
        int h = (orow - 256) >> 5, c = orow & 31;
        __half* v0p = g_v16 + ((size_t)(b * NH + h) * DH + c) * NPIX + n0;
        __half* v8p = v0p + 8 * NPIX;   // c+8 stays within the same 32-ch head
#pragma unroll
        for (int nj = 0; nj < 8; nj++) {
            int n = ns * 64 + nj * 8 + qu;
            *(__half2*)(v0p + n) = __floats2half2_rn(acc[nj][0] + b0, acc[nj][1] + b0);
            *(__half2*)(v8p + n) = __floats2half2_rn(acc[nj][2] + b8, acc[nj][3] + b8);
        }
    } else {
        // ---- Q/K: stage [o][n] in smem, then transposed coalesced write ----
        const bool isQ = (o0 < 128);
        const float sc = isQ ? SCALE2 : 1.0f;
        __syncthreads();  // done reading Hs as B operand
        int lo = os * 16 + g;
#pragma unroll
        for (int nj = 0; nj < 8; nj++) {
            int nn = ns * 64 + nj * 8 + qu;
            *(__half2*)&Hs[lo][nn] =
                __floats2half2_rn((acc[nj][0] + b0) * sc, (acc[nj][1] + b0) * sc);
            *(__half2*)&Hs[lo + 8][nn] =
                __floats2half2_rn((acc[nj][2] + b8) * sc, (acc[nj][3] + b8) * sc);
        }
        __syncthreads();
        // write-out: 256 threads = 128 n x 2 head-halves
        int n_loc = tid & 127;
        int hseg = tid >> 7;                 // 0/1 (two heads per 64-o tile)
        int oBase = (isQ ? o0 : o0 - 128) + hseg * 32;
        int head = oBase >> 5;
        __half* dst = (isQ ? g_q16 : g_k16) +
                      ((size_t)(b * NH + head) * NPIX + n0 + n_loc) * DH;
        __half tmp[32];
#pragma unroll
        for (int c = 0; c < 32; c++) tmp[c] = Hs[hseg * 32 + c][n_loc];
#pragma unroll
        for (int j = 0; j < 4; j++)
            *(uint4*)(dst + j * 8) = *(uint4*)(tmp + j * 8);
    }
}

// ---------------------------------------------------------------------------
// K4: generic fp16 GEMM (proj): fp32 out + bias + residual
// ---------------------------------------------------------------------------
__global__ void __launch_bounds__(256) gemm16_kernel(
    const __half* __restrict__ W2, const float* __restrict__ bias,
    const __half* __restrict__ Hin, float* __restrict__ Out,
    const float* __restrict__ resid, int Otot) {
    __shared__ __align__(16) __half Hs[128][136];

    const int tid = threadIdx.x, lane = tid & 31, wid = tid >> 5;
    const int g = lane >> 2, qu = (lane & 3) * 2;
    const int b = blockIdx.z, o0 = blockIdx.y * 64, n0 = blockIdx.x * 128;
    const int os = wid & 3, ns = wid >> 2;

    {
        const __half* hsrc = Hin + ((size_t)b * NPIX + n0) * CC;
        int row = tid >> 1, part = tid & 1;
#pragma unroll
        for (int j = 0; j < 8; j++)
            *(uint4*)&Hs[row][part * 64 + j * 8] =
                *(const uint4*)(hsrc + (size_t)row * CC + part * 64 + j * 8);
    }
    __syncthreads();

    float acc[8][4];
#pragma unroll
    for (int nj = 0; nj < 8; nj++)
#pragma unroll
        for (int r = 0; r < 4; r++) acc[nj][r] = 0.f;

    const __half* w0 = W2 + (size_t)(o0 + os * 16 + g) * 256;
    const __half* w8 = w0 + 8 * 256;

#pragma unroll
    for (int kk = 0; kk < 8; kk++) {
        int c0 = kk * 16 + qu;
        uint32_t ah[4], al[4];
        ah[0] = *(const uint32_t*)(w0 + c0);
        ah[1] = *(const uint32_t*)(w8 + c0);
        ah[2] = *(const uint32_t*)(w0 + c0 + 8);
        ah[3] = *(const uint32_t*)(w8 + c0 + 8);
        al[0] = *(const uint32_t*)(w0 + 128 + c0);
        al[1] = *(const uint32_t*)(w8 + 128 + c0);
        al[2] = *(const uint32_t*)(w0 + 128 + c0 + 8);
        al[3] = *(const uint32_t*)(w8 + 128 + c0 + 8);
#pragma unroll
        for (int nj = 0; nj < 8; nj++) {
            uint32_t bf[2];
            const __half* hrow = &Hs[ns * 64 + nj * 8 + g][0];
            bf[0] = *(const uint32_t*)(hrow + c0);
            bf[1] = *(const uint32_t*)(hrow + c0 + 8);
            mma16816h(acc[nj], ah, bf);
            mma16816h(acc[nj], al, bf);
        }
    }

    const int orow = o0 + os * 16 + g;
    const float b0 = bias[orow], b8 = bias[orow + 8];
#pragma unroll
    for (int nj = 0; nj < 8; nj++) {
        int n = n0 + ns * 64 + nj * 8 + qu;
        float2 v0 = make_float2(acc[nj][0] + b0, acc[nj][1] + b0);
        float2 v1 = make_float2(acc[nj][2] + b8, acc[nj][3] + b8);
        float2 r0 = *(const float2*)(resid + ((size_t)b * Otot + orow) * NPIX + n);
        float2 r1 = *(const float2*)(resid + ((size_t)b * Otot + orow + 8) * NPIX + n);
        v0.x += r0.x; v0.y += r0.y;
        v1.x += r1.x; v1.y += r1.y;
        *(float2*)(Out + ((size_t)b * Otot + orow) * NPIX + n) = v0;
        *(float2*)(Out + ((size_t)b * Otot + orow + 8) * NPIX + n) = v1;
    }
}

// ---------------------------------------------------------------------------
// K3: flash attention, fp16 mma, MUFU ex2 softmax, double-buffered smem.
// CTA 256 thr (8 warps), warp = 16 q rows -> 128 q per CTA. 64-key chunks.
// ---------------------------------------------------------------------------
__global__ void __launch_bounds__(256) attn_mma_kernel() {
    __shared__ __align__(16) __half Ks[2][64][40];
    __shared__ __align__(16) __half Vs[2][32][72];

    const int tid = threadIdx.x;
    const int lane = tid & 31;
    const int wid = tid >> 5;
    const int g = lane >> 2;
    const int qu = (lane & 3) * 2;
    const int b = blockIdx.z, hh = blockIdx.y;
    const int q0 = blockIdx.x * 128;
    const int bh = b * NH + hh;

    const __half* qgl = g_q16 + ((size_t)bh * NPIX + q0 + wid * 16) * DH;
    const __half* kgl = g_k16 + (size_t)bh * NPIX * DH;
    const __half* vgl = g_v16 + (size_t)bh * DH * NPIX;

    uint32_t qa[2][4];
#pragma unroll
    for (int kk = 0; kk < 2; kk++) {
        int c0 = kk * 16 + qu;
        qa[kk][0] = *(const uint32_t*)(qgl + (size_t)g * DH + c0);
        qa[kk][1] = *(const uint32_t*)(qgl + (size_t)(g + 8) * DH + c0);
        qa[kk][2] = *(const uint32_t*)(qgl + (size_t)g * DH + c0 + 8);
        qa[kk][3] = *(const uint32_t*)(qgl + (size_t)(g + 8) * DH + c0 + 8);
    }

    float o[4][4];
#pragma unroll
    for (int ci = 0; ci < 4; ci++)
#pragma unroll
        for (int r = 0; r < 4; r++) o[ci][r] = 0.f;
    float mrun[2] = {-3.0e38f, -3.0e38f};
    float lrun[2] = {0.f, 0.f};

    const int krow = tid >> 2, kpart = tid & 3;
    const int vrow = tid >> 3, vpart = tid & 7;

    // preload chunk 0
    *(uint4*)&Ks[0][krow][kpart * 8] =
        *(const uint4*)(kgl + (size_t)krow * DH + kpart * 8);
    *(uint4*)&Vs[0][vrow][vpart * 8] =
        *(const uint4*)(vgl + (size_t)vrow * NPIX + vpart * 8);
    __syncthreads();

    int cur = 0;
    for (int m0 = 0; m0 < NPIX; m0 += 64, cur ^= 1) {
        // issue next-chunk loads into the other buffer
        if (m0 + 64 < NPIX) {
            *(uint4*)&Ks[cur ^ 1][krow][kpart * 8] =
                *(const uint4*)(kgl + (size_t)(m0 + 64 + krow) * DH + kpart * 8);
            *(uint4*)&Vs[cur ^ 1][vrow][vpart * 8] =
                *(const uint4*)(vgl + (size_t)vrow * NPIX + m0 + 64 + vpart * 8);
        }

        // ---- S = Q K^T (k=32) ----
        float sacc[8][4];
#pragma unroll
        for (int nj = 0; nj < 8; nj++) {
            const __half* krow_p = &Ks[cur][nj * 8 + g][0];
#pragma unroll
            for (int r = 0; r < 4; r++) sacc[nj][r] = 0.f;
#pragma unroll
            for (int kk = 0; kk < 2; kk++) {
                uint32_t bf[2];
                bf[0] = *(const uint32_t*)(krow_p + kk * 16 + qu);
                bf[1] = *(const uint32_t*)(krow_p + kk * 16 + qu + 8);
                mma16816h(sacc[nj], qa[kk], bf);
            }
        }

        // ---- online softmax (MUFU ex2) ----
#pragma unroll
        for (int h2 = 0; h2 < 2; h2++) {
            float mx = -3.0e38f;
#pragma unroll
            for (int nj = 0; nj < 8; nj++)
                mx = fmaxf(mx, fmaxf(sacc[nj][h2 * 2], sacc[nj][h2 * 2 + 1]));
            mx = fmaxf(mx, __shfl_xor_sync(0xffffffffu, mx, 1));
            mx = fmaxf(mx, __shfl_xor_sync(0xffffffffu, mx, 2));
            float mnew = fmaxf(mrun[h2], mx);
            float cr = ex2(mrun[h2] - mnew);
            mrun[h2] = mnew;
            float ls = 0.f;
#pragma unroll
            for (int nj = 0; nj < 8; nj++) {
                float p0 = ex2(sacc[nj][h2 * 2] - mnew);
                float p1 = ex2(sacc[nj][h2 * 2 + 1] - mnew);
                sacc[nj][h2 * 2] = p0;
                sacc[nj][h2 * 2 + 1] = p1;
                ls += p0 + p1;
            }
            ls += __shfl_xor_sync(0xffffffffu, ls, 1);
            ls += __shfl_xor_sync(0xffffffffu, ls, 2);
            lrun[h2] = lrun[h2] * cr + ls;
#pragma unroll
            for (int ci = 0; ci < 4; ci++) {
                o[ci][h2 * 2] *= cr;
                o[ci][h2 * 2 + 1] *= cr;
            }
        }

        // ---- O += P V per 16-key tile ----
#pragma unroll
        for (int kt = 0; kt < 4; kt++) {
            uint32_t ph[4];
#pragma unroll
            for (int half = 0; half < 2; half++) {
                float* sp = sacc[2 * kt + half];
                ph[half * 2 + 0] = pack_f16x2(sp[0], sp[1]);
                ph[half * 2 + 1] = pack_f16x2(sp[2], sp[3]);
            }
#pragma unroll
            for (int ci = 0; ci < 4; ci++) {
                uint32_t vb[2];
                const __half* vrow_p = &Vs[cur][ci * 8 + g][kt * 16 + qu];
                vb[0] = *(const uint32_t*)(vrow_p);
                vb[1] = *(const uint32_t*)(vrow_p + 8);
                mma16816h(o[ci], ph, vb);
            }
        }

        __syncthreads();  // everyone done with buf cur; next-chunk STS drained
    }

    // ---- normalize + store fp16 [b][n][c] ----
#pragma unroll
    for (int h2 = 0; h2 < 2; h2++) {
        float invl = 1.0f / lrun[h2];
        int qrow = q0 + wid * 16 + g + h2 * 8;
        __half* od = g_at + ((size_t)b * NPIX + qrow) * CC + hh * DH;
#pragma unroll
        for (int ci = 0; ci < 4; ci++) {
            *(__half2*)(od + ci * 8 + qu) =
                __floats2half2_rn(o[ci][h2 * 2] * invl, o[ci][h2 * 2 + 1] * invl);
        }
    }
}

// ---------------------------------------------------------------------------
extern "C" void kernel_launch(void* const* d_in, const int* in_sizes, int n_in,
                              void* d_out, int out_size) {
    const float* x      = (const float*)d_in[0];
    const float* norm_w = (const float*)d_in[1];
    const float* norm_b = (const float*)d_in[2];
    const float* qkv_w  = (const float*)d_in[3];
    const float* qkv_b  = (const float*)d_in[4];
    const float* proj_w = (const float*)d_in[5];
    const float* proj_b = (const float*)d_in[6];
    float* out = (float*)d_out;

    __half *g_wp_p, *g_at_p;
    cudaGetSymbolAddress((void**)&g_wp_p, g_wp);
    cudaGetSymbolAddress((void**)&g_at_p, g_at);

    // K0: weight split
    wconv_kernel<<<256, 256>>>(qkv_w, proj_w);

    // K1: norm -> fp16 [b][n][c]
    norm_kernel<<<(BB * NPIX) / 256, 256>>>(x, norm_w, norm_b);

    // K2: qkv GEMM with fused attention-layout epilogue
    gemmqkv_kernel<<<dim3(NPIX / 128, 384 / 64, BB), 256>>>(qkv_b);

    // K3: attention -> fp16 [b][n][c]   (4th launch: ncu profiles this)
    attn_mma_kernel<<<dim3(NPIX / 128, NH, BB), 256>>>();

    // K4: proj + bias + residual -> d_out
    gemm16_kernel<<<dim3(NPIX / 128, CC / 64, BB), 256>>>(
        g_wp_p, proj_b, g_at_p, out, x, CC);
}

// round 10
// speedup vs baseline: 5.8696x; 1.0705x over previous
#include <cuda_runtime.h>
#include <cuda_fp16.h>
#include <math.h>
#include <stdint.h>

#define BB 4
#define CC 128
#define NPIX 4096
#define NH 4
#define DH 32
#define EPSF 1e-6f
// (1/sqrt(32)) * log2(e)
#define SCALE2 0.25503486f

// Scratch (device globals)
__device__ __half g_ht[(size_t)BB * NPIX * CC];        // normed h fp16 [b][n][c]
__device__ __half g_wq[384 * 256];                     // qkv_w split hi|lo
__device__ __half g_wp[128 * 256];                     // proj_w split hi|lo
__device__ __half g_q16[(size_t)BB * NH * NPIX * DH];  // [bh][n][c], scaled
__device__ __half g_k16[(size_t)BB * NH * NPIX * DH];  // [bh][n][c]
__device__ __half g_v16[(size_t)BB * NH * DH * NPIX];  // [bh][c][n]
__device__ __half g_at[(size_t)BB * NPIX * CC];        // attn out fp16 [b][n][c]

// ---------------------------------------------------------------------------
// helpers
// ---------------------------------------------------------------------------
__device__ __forceinline__ float ex2(float x) {
    float r;
    asm("ex2.approx.ftz.f32 %0, %1;" : "=f"(r) : "f"(x));
    return r;
}

__device__ __forceinline__ uint32_t hex2(uint32_t a) {
    uint32_t d;
    asm("ex2.approx.f16x2 %0, %1;" : "=r"(d) : "r"(a));
    return d;
}

__device__ __forceinline__ uint32_t hadd2(uint32_t a, uint32_t b) {
    uint32_t d;
    asm("add.f16x2 %0, %1, %2;" : "=r"(d) : "r"(a), "r"(b));
    return d;
}

__device__ __forceinline__ void mma16816h(float* d, const uint32_t* a,
                                          const uint32_t* b) {
    asm volatile(
        "mma.sync.aligned.m16n8k16.row.col.f32.f16.f16.f32 "
        "{%0,%1,%2,%3},{%4,%5,%6,%7},{%8,%9},{%0,%1,%2,%3};"
        : "+f"(d[0]), "+f"(d[1]), "+f"(d[2]), "+f"(d[3])
        : "r"(a[0]), "r"(a[1]), "r"(a[2]), "r"(a[3]), "r"(b[0]), "r"(b[1]));
}

__device__ __forceinline__ void ldmx4(uint32_t& r0, uint32_t& r1, uint32_t& r2,
                                      uint32_t& r3, uint32_t addr) {
    asm volatile(
        "ldmatrix.sync.aligned.m8n8.x4.shared.b16 {%0,%1,%2,%3}, [%4];"
        : "=r"(r0), "=r"(r1), "=r"(r2), "=r"(r3) : "r"(addr));
}

__device__ __forceinline__ uint32_t pack_f16x2(float a, float b) {
    uint32_t r;
    asm("cvt.rn.f16x2.f32 %0, %1, %2;" : "=r"(r) : "f"(b), "f"(a));
    return r;
}

// ---------------------------------------------------------------------------
// K0: weight split (qkv_w and proj_w -> fp16 hi|lo, [o][256])
// ---------------------------------------------------------------------------
__global__ void wconv_kernel(const float* __restrict__ qkv_w,
                             const float* __restrict__ proj_w) {
    int t = blockIdx.x * 256 + threadIdx.x;   // 0 .. 65535
    const float* src;
    __half* dst;
    int idx;
    if (t < 384 * 128) { src = qkv_w; dst = g_wq; idx = t; }
    else               { src = proj_w; dst = g_wp; idx = t - 384 * 128; }
    int row = idx >> 7, c = idx & 127;
    float v = src[idx];
    __half hi = __float2half_rn(v);
    dst[row * 256 + c] = hi;
    dst[row * 256 + 128 + c] = __float2half_rn(v - __half2float(hi));
}

// ---------------------------------------------------------------------------
// K1: per-pixel channel LayerNorm -> fp16 [b][n][c]
// ---------------------------------------------------------------------------
__global__ void norm_kernel(const float* __restrict__ x,
                            const float* __restrict__ w,
                            const float* __restrict__ bias) {
    int pix = blockIdx.x * blockDim.x + threadIdx.x;
    int b = pix >> 12;
    int n = pix & (NPIX - 1);
    const float* xp = x + (size_t)b * CC * NPIX + n;
    float s = 0.f, s2 = 0.f;
#pragma unroll 8
    for (int c = 0; c < CC; c++) {
        float v = xp[(size_t)c * NPIX];
        s += v;
        s2 += v * v;
    }
    float mean = s * (1.0f / CC);
    float var  = s2 * (1.0f / CC) - mean * mean;
    float inv  = rsqrtf(var + EPSF);
    __half* hp = g_ht + ((size_t)b * NPIX + n) * CC;
#pragma unroll 4
    for (int c = 0; c < CC; c += 2) {
        float v0 = (xp[(size_t)c * NPIX] - mean) * inv * w[c] + bias[c];
        float v1 = (xp[(size_t)(c + 1) * NPIX] - mean) * inv * w[c + 1] + bias[c + 1];
        *(__half2*)(hp + c) = __floats2half2_rn(v0, v1);
    }
}

// ---------------------------------------------------------------------------
// K2: qkv GEMM with fused attention-layout epilogue.
// ---------------------------------------------------------------------------
__global__ void __launch_bounds__(256) gemmqkv_kernel(
    const float* __restrict__ bias) {
    __shared__ __align__(16) __half Hs[128][136];

    const int tid = threadIdx.x, lane = tid & 31, wid = tid >> 5;
    const int g = lane >> 2, qu = (lane & 3) * 2;
    const int b = blockIdx.z, o0 = blockIdx.y * 64, n0 = blockIdx.x * 128;
    const int os = wid & 3, ns = wid >> 2;

    {
        const __half* hsrc = g_ht + ((size_t)b * NPIX + n0) * CC;
        int row = tid >> 1, part = tid & 1;
#pragma unroll
        for (int j = 0; j < 8; j++)
            *(uint4*)&Hs[row][part * 64 + j * 8] =
                *(const uint4*)(hsrc + (size_t)row * CC + part * 64 + j * 8);
    }
    __syncthreads();

    float acc[8][4];
#pragma unroll
    for (int nj = 0; nj < 8; nj++)
#pragma unroll
        for (int r = 0; r < 4; r++) acc[nj][r] = 0.f;

    const __half* w0 = g_wq + (size_t)(o0 + os * 16 + g) * 256;
    const __half* w8 = w0 + 8 * 256;

#pragma unroll
    for (int kk = 0; kk < 8; kk++) {
        int c0 = kk * 16 + qu;
        uint32_t ah[4], al[4];
        ah[0] = *(const uint32_t*)(w0 + c0);
        ah[1] = *(const uint32_t*)(w8 + c0);
        ah[2] = *(const uint32_t*)(w0 + c0 + 8);
        ah[3] = *(const uint32_t*)(w8 + c0 + 8);
        al[0] = *(const uint32_t*)(w0 + 128 + c0);
        al[1] = *(const uint32_t*)(w8 + 128 + c0);
        al[2] = *(const uint32_t*)(w0 + 128 + c0 + 8);
        al[3] = *(const uint32_t*)(w8 + 128 + c0 + 8);
#pragma unroll
        for (int nj = 0; nj < 8; nj++) {
            uint32_t bf[2];
            const __half* hrow = &Hs[ns * 64 + nj * 8 + g][0];
            bf[0] = *(const uint32_t*)(hrow + c0);
            bf[1] = *(const uint32_t*)(hrow + c0 + 8);
            mma16816h(acc[nj], ah, bf);
            mma16816h(acc[nj], al, bf);
        }
    }

    const int orow = o0 + os * 16 + g;
    const float b0 = bias[orow], b8 = bias[orow + 8];

    if (o0 >= 256) {
        int h = (orow - 256) >> 5, c = orow & 31;
        __half* v0p = g_v16 + ((size_t)(b * NH + h) * DH + c) * NPIX + n0;
        __half* v8p = v0p + 8 * NPIX;
#pragma unroll
        for (int nj = 0; nj < 8; nj++) {
            int n = ns * 64 + nj * 8 + qu;
            *(__half2*)(v0p + n) = __floats2half2_rn(acc[nj][0] + b0, acc[nj][1] + b0);
            *(__half2*)(v8p + n) = __floats2half2_rn(acc[nj][2] + b8, acc[nj][3] + b8);
        }
    } else {
        const bool isQ = (o0 < 128);
        const float sc = isQ ? SCALE2 : 1.0f;
        __syncthreads();
        int lo = os * 16 + g;
#pragma unroll
        for (int nj = 0; nj < 8; nj++) {
            int nn = ns * 64 + nj * 8 + qu;
            *(__half2*)&Hs[lo][nn] =
                __floats2half2_rn((acc[nj][0] + b0) * sc, (acc[nj][1] + b0) * sc);
            *(__half2*)&Hs[lo + 8][nn] =
                __floats2half2_rn((acc[nj][2] + b8) * sc, (acc[nj][3] + b8) * sc);
        }
        __syncthreads();
        int n_loc = tid & 127;
        int hseg = tid >> 7;
        int oBase = (isQ ? o0 : o0 - 128) + hseg * 32;
        int head = oBase >> 5;
        __half* dst = (isQ ? g_q16 : g_k16) +
                      ((size_t)(b * NH + head) * NPIX + n0 + n_loc) * DH;
        __half tmp[32];
#pragma unroll
        for (int c = 0; c < 32; c++) tmp[c] = Hs[hseg * 32 + c][n_loc];
#pragma unroll
        for (int j = 0; j < 4; j++)
            *(uint4*)(dst + j * 8) = *(uint4*)(tmp + j * 8);
    }
}

// ---------------------------------------------------------------------------
// K4: generic fp16 GEMM (proj): fp32 out + bias + residual
// ---------------------------------------------------------------------------
__global__ void __launch_bounds__(256) gemm16_kernel(
    const __half* __restrict__ W2, const float* __restrict__ bias,
    const __half* __restrict__ Hin, float* __restrict__ Out,
    const float* __restrict__ resid, int Otot) {
    __shared__ __align__(16) __half Hs[128][136];

    const int tid = threadIdx.x, lane = tid & 31, wid = tid >> 5;
    const int g = lane >> 2, qu = (lane & 3) * 2;
    const int b = blockIdx.z, o0 = blockIdx.y * 64, n0 = blockIdx.x * 128;
    const int os = wid & 3, ns = wid >> 2;

    {
        const __half* hsrc = Hin + ((size_t)b * NPIX + n0) * CC;
        int row = tid >> 1, part = tid & 1;
#pragma unroll
        for (int j = 0; j < 8; j++)
            *(uint4*)&Hs[row][part * 64 + j * 8] =
                *(const uint4*)(hsrc + (size_t)row * CC + part * 64 + j * 8);
    }
    __syncthreads();

    float acc[8][4];
#pragma unroll
    for (int nj = 0; nj < 8; nj++)
#pragma unroll
        for (int r = 0; r < 4; r++) acc[nj][r] = 0.f;

    const __half* w0 = W2 + (size_t)(o0 + os * 16 + g) * 256;
    const __half* w8 = w0 + 8 * 256;

#pragma unroll
    for (int kk = 0; kk < 8; kk++) {
        int c0 = kk * 16 + qu;
        uint32_t ah[4], al[4];
        ah[0] = *(const uint32_t*)(w0 + c0);
        ah[1] = *(const uint32_t*)(w8 + c0);
        ah[2] = *(const uint32_t*)(w0 + c0 + 8);
        ah[3] = *(const uint32_t*)(w8 + c0 + 8);
        al[0] = *(const uint32_t*)(w0 + 128 + c0);
        al[1] = *(const uint32_t*)(w8 + 128 + c0);
        al[2] = *(const uint32_t*)(w0 + 128 + c0 + 8);
        al[3] = *(const uint32_t*)(w8 + 128 + c0 + 8);
#pragma unroll
        for (int nj = 0; nj < 8; nj++) {
            uint32_t bf[2];
            const __half* hrow = &Hs[ns * 64 + nj * 8 + g][0];
            bf[0] = *(const uint32_t*)(hrow + c0);
            bf[1] = *(const uint32_t*)(hrow + c0 + 8);
            mma16816h(acc[nj], ah, bf);
            mma16816h(acc[nj], al, bf);
        }
    }

    const int orow = o0 + os * 16 + g;
    const float b0 = bias[orow], b8 = bias[orow + 8];
#pragma unroll
    for (int nj = 0; nj < 8; nj++) {
        int n = n0 + ns * 64 + nj * 8 + qu;
        float2 v0 = make_float2(acc[nj][0] + b0, acc[nj][1] + b0);
        float2 v1 = make_float2(acc[nj][2] + b8, acc[nj][3] + b8);
        float2 r0 = *(const float2*)(resid + ((size_t)b * Otot + orow) * NPIX + n);
        float2 r1 = *(const float2*)(resid + ((size_t)b * Otot + orow + 8) * NPIX + n);
        v0.x += r0.x; v0.y += r0.y;
        v1.x += r1.x; v1.y += r1.y;
        *(float2*)(Out + ((size_t)b * Otot + orow) * NPIX + n) = v0;
        *(float2*)(Out + ((size_t)b * Otot + orow + 8) * NPIX + n) = v1;
    }
}

// ---------------------------------------------------------------------------
// K3: flash attention: fp16 mma, ldmatrix fragments, f16x2 MUFU softmax,
// double-buffered smem. CTA 256 thr (8 warps), warp = 16 q rows.
// ---------------------------------------------------------------------------
__global__ void __launch_bounds__(256) attn_mma_kernel() {
    __shared__ __align__(16) __half Ks[2][64][40];  // 80B row stride
    __shared__ __align__(16) __half Vs[2][32][72];  // 144B row stride

    const int tid = threadIdx.x;
    const int lane = tid & 31;
    const int wid = tid >> 5;
    const int g = lane >> 2;
    const int qu = (lane & 3) * 2;
    const int b = blockIdx.z, hh = blockIdx.y;
    const int q0 = blockIdx.x * 128;
    const int bh = b * NH + hh;

    const __half* qgl = g_q16 + ((size_t)bh * NPIX + q0 + wid * 16) * DH;
    const __half* kgl = g_k16 + (size_t)bh * NPIX * DH;
    const __half* vgl = g_v16 + (size_t)bh * DH * NPIX;

    uint32_t qa[2][4];
#pragma unroll
    for (int kk = 0; kk < 2; kk++) {
        int c0 = kk * 16 + qu;
        qa[kk][0] = *(const uint32_t*)(qgl + (size_t)g * DH + c0);
        qa[kk][1] = *(const uint32_t*)(qgl + (size_t)(g + 8) * DH + c0);
        qa[kk][2] = *(const uint32_t*)(qgl + (size_t)g * DH + c0 + 8);
        qa[kk][3] = *(const uint32_t*)(qgl + (size_t)(g + 8) * DH + c0 + 8);
    }

    float o[4][4];
#pragma unroll
    for (int ci = 0; ci < 4; ci++)
#pragma unroll
        for (int r = 0; r < 4; r++) o[ci][r] = 0.f;
    float mrun[2] = {-3.0e38f, -3.0e38f};
    float lrun[2] = {0.f, 0.f};

    const int krow = tid >> 2, kpart = tid & 3;
    const int vrow = tid >> 3, vpart = tid & 7;

    // ldmatrix per-lane byte offsets (within a buffer)
    const uint32_t ks_base = (uint32_t)__cvta_generic_to_shared(&Ks[0][0][0]);
    const uint32_t vs_base = (uint32_t)__cvta_generic_to_shared(&Vs[0][0][0]);
    const uint32_t koff = ((lane & 7) * 40 + (lane >> 3) * 8) * 2;
    // V: matrix m = lane>>3: ci_sub = m>>1, colblk = (m&1)*8
    const uint32_t voff = ((((lane >> 4) & 1) * 8 + (lane & 7)) * 72 +
                           ((lane >> 3) & 1) * 8) * 2;

    // preload chunk 0
    *(uint4*)&Ks[0][krow][kpart * 8] =
        *(const uint4*)(kgl + (size_t)krow * DH + kpart * 8);
    *(uint4*)&Vs[0][vrow][vpart * 8] =
        *(const uint4*)(vgl + (size_t)vrow * NPIX + vpart * 8);
    __syncthreads();

    int cur = 0;
    for (int m0 = 0; m0 < NPIX; m0 += 64, cur ^= 1) {
        if (m0 + 64 < NPIX) {
            *(uint4*)&Ks[cur ^ 1][krow][kpart * 8] =
                *(const uint4*)(kgl + (size_t)(m0 + 64 + krow) * DH + kpart * 8);
            *(uint4*)&Vs[cur ^ 1][vrow][vpart * 8] =
                *(const uint4*)(vgl + (size_t)vrow * NPIX + m0 + 64 + vpart * 8);
        }

        const uint32_t kb = ks_base + (uint32_t)cur * (64 * 40 * 2) + koff;
        const uint32_t vb_base = vs_base + (uint32_t)cur * (32 * 72 * 2) + voff;

        // ---- S = Q K^T (k=32); one ldmatrix.x4 per nj ----
        float sacc[8][4];
#pragma unroll
        for (int nj = 0; nj < 8; nj++) {
            uint32_t b00, b01, b10, b11;   // {kk0 bf0, kk0 bf1, kk1 bf0, kk1 bf1}
            ldmx4(b00, b01, b10, b11, kb + nj * (8 * 40 * 2));
#pragma unroll
            for (int r = 0; r < 4; r++) sacc[nj][r] = 0.f;
            uint32_t bf0[2] = {b00, b01};
            uint32_t bf1[2] = {b10, b11};
            mma16816h(sacc[nj], qa[0], bf0);
            mma16816h(sacc[nj], qa[1], bf1);
        }

        // ---- online softmax: max in f32, exp+sum in f16x2 (MUFU halved) ----
        float cr[2], mnew[2];
#pragma unroll
        for (int h2 = 0; h2 < 2; h2++) {
            float mx = -3.0e38f;
#pragma unroll
            for (int nj = 0; nj < 8; nj++)
                mx = fmaxf(mx, fmaxf(sacc[nj][h2 * 2], sacc[nj][h2 * 2 + 1]));
            mx = fmaxf(mx, __shfl_xor_sync(0xffffffffu, mx, 1));
            mx = fmaxf(mx, __shfl_xor_sync(0xffffffffu, mx, 2));
            mnew[h2] = fmaxf(mrun[h2], mx);
            cr[h2] = ex2(mrun[h2] - mnew[h2]);
            mrun[h2] = mnew[h2];
        }

        uint32_t p16[8][2];
#pragma unroll
        for (int nj = 0; nj < 8; nj++) {
            p16[nj][0] = hex2(pack_f16x2(sacc[nj][0] - mnew[0],
                                         sacc[nj][1] - mnew[0]));
            p16[nj][1] = hex2(pack_f16x2(sacc[nj][2] - mnew[1],
                                         sacc[nj][3] - mnew[1]));
        }

#pragma unroll
        for (int h2 = 0; h2 < 2; h2++) {
            uint32_t t = hadd2(hadd2(hadd2(p16[0][h2], p16[1][h2]),
                                     hadd2(p16[2][h2], p16[3][h2])),
                               hadd2(hadd2(p16[4][h2], p16[5][h2]),
                                     hadd2(p16[6][h2], p16[7][h2])));
            float2 f = __half22float2(*(__half2*)&t);
            float ls = f.x + f.y;
            ls += __shfl_xor_sync(0xffffffffu, ls, 1);
            ls += __shfl_xor_sync(0xffffffffu, ls, 2);
            lrun[h2] = lrun[h2] * cr[h2] + ls;
#pragma unroll
            for (int ci = 0; ci < 4; ci++) {
                o[ci][h2 * 2] *= cr[h2];
                o[ci][h2 * 2 + 1] *= cr[h2];
            }
        }

        // ---- O += P V per 16-key tile; p16 IS the A-fragment ----
#pragma unroll
        for (int kt = 0; kt < 4; kt++) {
            uint32_t ph[4] = {p16[2 * kt][0], p16[2 * kt][1],
                              p16[2 * kt + 1][0], p16[2 * kt + 1][1]};
            // 2 ldmatrix.x4 -> vb[ci][0..1] for ci=0..3
            uint32_t v00, v01, v10, v11, v20, v21, v30, v31;
            ldmx4(v00, v01, v10, v11, vb_base + kt * 32);
            ldmx4(v20, v21, v30, v31, vb_base + kt * 32 + (16 * 72 * 2));
            {
                uint32_t vb0[2] = {v00, v01}; mma16816h(o[0], ph, vb0);
                uint32_t vb1[2] = {v10, v11}; mma16816h(o[1], ph, vb1);
                uint32_t vb2[2] = {v20, v21}; mma16816h(o[2], ph, vb2);
                uint32_t vb3[2] = {v30, v31}; mma16816h(o[3], ph, vb3);
            }
        }

        __syncthreads();
    }

    // ---- normalize + store fp16 [b][n][c] ----
#pragma unroll
    for (int h2 = 0; h2 < 2; h2++) {
        float invl = 1.0f / lrun[h2];
        int qrow = q0 + wid * 16 + g + h2 * 8;
        __half* od = g_at + ((size_t)b * NPIX + qrow) * CC + hh * DH;
#pragma unroll
        for (int ci = 0; ci < 4; ci++) {
            *(__half2*)(od + ci * 8 + qu) =
                __floats2half2_rn(o[ci][h2 * 2] * invl, o[ci][h2 * 2 + 1] * invl);
        }
    }
}

// ---------------------------------------------------------------------------
extern "C" void kernel_launch(void* const* d_in, const int* in_sizes, int n_in,
                              void* d_out, int out_size) {
    const float* x      = (const float*)d_in[0];
    const float* norm_w = (const float*)d_in[1];
    const float* norm_b = (const float*)d_in[2];
    const float* qkv_w  = (const float*)d_in[3];
    const float* qkv_b  = (const float*)d_in[4];
    const float* proj_w = (const float*)d_in[5];
    const float* proj_b = (const float*)d_in[6];
    float* out = (float*)d_out;

    __half *g_wp_p, *g_at_p;
    cudaGetSymbolAddress((void**)&g_wp_p, g_wp);
    cudaGetSymbolAddress((void**)&g_at_p, g_at);

    // K0: weight split
    wconv_kernel<<<256, 256>>>(qkv_w, proj_w);

    // K1: norm -> fp16 [b][n][c]
    norm_kernel<<<(BB * NPIX) / 256, 256>>>(x, norm_w, norm_b);

    // K2: qkv GEMM with fused attention-layout epilogue
    gemmqkv_kernel<<<dim3(NPIX / 128, 384 / 64, BB), 256>>>(qkv_b);

    // K3: attention -> fp16 [b][n][c]   (4th launch: ncu profiles this)
    attn_mma_kernel<<<dim3(NPIX / 128, NH, BB), 256>>>();

    // K4: proj + bias + residual -> d_out
    gemm16_kernel<<<dim3(NPIX / 128, CC / 64, BB), 256>>>(
        g_wp_p, proj_b, g_at_p, out, x, CC);
}

// round 11
// speedup vs baseline: 6.2213x; 1.0599x over previous
#include <cuda_runtime.h>
#include <cuda_fp16.h>
#include <math.h>
#include <stdint.h>

#define BB 4
#define CC 128
#define NPIX 4096
#define NH 4
#define DH 32
#define EPSF 1e-6f
// (1/sqrt(32)) * log2(e)
#define SCALE2 0.25503486f

// Scratch (device globals)
__device__ __half g_ht[(size_t)BB * NPIX * CC];        // normed h fp16 [b][n][c]
__device__ __half g_wq[384 * 256];                     // qkv_w split hi|lo
__device__ __half g_wp[128 * 256];                     // proj_w split hi|lo
__device__ __half g_q16[(size_t)BB * NH * NPIX * DH];  // [bh][n][c], scaled
__device__ __half g_k16[(size_t)BB * NH * NPIX * DH];  // [bh][n][c]
__device__ __half g_v16[(size_t)BB * NH * DH * NPIX];  // [bh][c][n]
__device__ __half g_at[(size_t)BB * NPIX * CC];        // attn out fp16 [b][n][c]
__device__ float  g_qb[BB * NH * NPIX];                // |q_n| per row (log2 dom)
__device__ unsigned g_kmax[BB * NH];                   // bits of max |k|^2

// ---------------------------------------------------------------------------
// helpers
// ---------------------------------------------------------------------------
__device__ __forceinline__ uint32_t hex2(uint32_t a) {
    uint32_t d;
    asm("ex2.approx.f16x2 %0, %1;" : "=r"(d) : "r"(a));
    return d;
}

__device__ __forceinline__ uint32_t hadd2(uint32_t a, uint32_t b) {
    uint32_t d;
    asm("add.f16x2 %0, %1, %2;" : "=r"(d) : "r"(a), "r"(b));
    return d;
}

__device__ __forceinline__ void mma16816h(float* d, const uint32_t* a,
                                          const uint32_t* b) {
    asm volatile(
        "mma.sync.aligned.m16n8k16.row.col.f32.f16.f16.f32 "
        "{%0,%1,%2,%3},{%4,%5,%6,%7},{%8,%9},{%0,%1,%2,%3};"
        : "+f"(d[0]), "+f"(d[1]), "+f"(d[2]), "+f"(d[3])
        : "r"(a[0]), "r"(a[1]), "r"(a[2]), "r"(a[3]), "r"(b[0]), "r"(b[1]));
}

__device__ __forceinline__ void ldmx4(uint32_t& r0, uint32_t& r1, uint32_t& r2,
                                      uint32_t& r3, uint32_t addr) {
    asm volatile(
        "ldmatrix.sync.aligned.m8n8.x4.shared.b16 {%0,%1,%2,%3}, [%4];"
        : "=r"(r0), "=r"(r1), "=r"(r2), "=r"(r3) : "r"(addr));
}

__device__ __forceinline__ uint32_t pack_f16x2(float a, float b) {
    uint32_t r;
    asm("cvt.rn.f16x2.f32 %0, %1, %2;" : "=r"(r) : "f"(b), "f"(a));
    return r;
}

// ---------------------------------------------------------------------------
// K0: weight split + g_kmax reset
// ---------------------------------------------------------------------------
__global__ void wconv_kernel(const float* __restrict__ qkv_w,
                             const float* __restrict__ proj_w) {
    int t = blockIdx.x * 256 + threadIdx.x;   // 0 .. 65535
    if (t < BB * NH) g_kmax[t] = 0u;
    const float* src;
    __half* dst;
    int idx;
    if (t < 384 * 128) { src = qkv_w; dst = g_wq; idx = t; }
    else               { src = proj_w; dst = g_wp; idx = t - 384 * 128; }
    int row = idx >> 7, c = idx & 127;
    float v = src[idx];
    __half hi = __float2half_rn(v);
    dst[row * 256 + c] = hi;
    dst[row * 256 + 128 + c] = __float2half_rn(v - __half2float(hi));
}

// ---------------------------------------------------------------------------
// K1: per-pixel channel LayerNorm -> fp16 [b][n][c]
// ---------------------------------------------------------------------------
__global__ void norm_kernel(const float* __restrict__ x,
                            const float* __restrict__ w,
                            const float* __restrict__ bias) {
    int pix = blockIdx.x * blockDim.x + threadIdx.x;
    int b = pix >> 12;
    int n = pix & (NPIX - 1);
    const float* xp = x + (size_t)b * CC * NPIX + n;
    float s = 0.f, s2 = 0.f;
#pragma unroll 8
    for (int c = 0; c < CC; c++) {
        float v = xp[(size_t)c * NPIX];
        s += v;
        s2 += v * v;
    }
    float mean = s * (1.0f / CC);
    float var  = s2 * (1.0f / CC) - mean * mean;
    float inv  = rsqrtf(var + EPSF);
    __half* hp = g_ht + ((size_t)b * NPIX + n) * CC;
#pragma unroll 4
    for (int c = 0; c < CC; c += 2) {
        float v0 = (xp[(size_t)c * NPIX] - mean) * inv * w[c] + bias[c];
        float v1 = (xp[(size_t)(c + 1) * NPIX] - mean) * inv * w[c + 1] + bias[c + 1];
        *(__half2*)(hp + c) = __floats2half2_rn(v0, v1);
    }
}

// ---------------------------------------------------------------------------
// K2: qkv GEMM with fused attention-layout epilogue + softmax-bound stats.
// ---------------------------------------------------------------------------
__global__ void __launch_bounds__(256) gemmqkv_kernel(
    const float* __restrict__ bias) {
    __shared__ __align__(16) __half Hs[128][136];
    __shared__ float red[8];

    const int tid = threadIdx.x, lane = tid & 31, wid = tid >> 5;
    const int g = lane >> 2, qu = (lane & 3) * 2;
    const int b = blockIdx.z, o0 = blockIdx.y * 64, n0 = blockIdx.x * 128;
    const int os = wid & 3, ns = wid >> 2;

    {
        const __half* hsrc = g_ht + ((size_t)b * NPIX + n0) * CC;
        int row = tid >> 1, part = tid & 1;
#pragma unroll
        for (int j = 0; j < 8; j++)
            *(uint4*)&Hs[row][part * 64 + j * 8] =
                *(const uint4*)(hsrc + (size_t)row * CC + part * 64 + j * 8);
    }
    __syncthreads();

    float acc[8][4];
#pragma unroll
    for (int nj = 0; nj < 8; nj++)
#pragma unroll
        for (int r = 0; r < 4; r++) acc[nj][r] = 0.f;

    const __half* w0 = g_wq + (size_t)(o0 + os * 16 + g) * 256;
    const __half* w8 = w0 + 8 * 256;

#pragma unroll
    for (int kk = 0; kk < 8; kk++) {
        int c0 = kk * 16 + qu;
        uint32_t ah[4], al[4];
        ah[0] = *(const uint32_t*)(w0 + c0);
        ah[1] = *(const uint32_t*)(w8 + c0);
        ah[2] = *(const uint32_t*)(w0 + c0 + 8);
        ah[3] = *(const uint32_t*)(w8 + c0 + 8);
        al[0] = *(const uint32_t*)(w0 + 128 + c0);
        al[1] = *(const uint32_t*)(w8 + 128 + c0);
        al[2] = *(const uint32_t*)(w0 + 128 + c0 + 8);
        al[3] = *(const uint32_t*)(w8 + 128 + c0 + 8);
#pragma unroll
        for (int nj = 0; nj < 8; nj++) {
            uint32_t bf[2];
            const __half* hrow = &Hs[ns * 64 + nj * 8 + g][0];
            bf[0] = *(const uint32_t*)(hrow + c0);
            bf[1] = *(const uint32_t*)(hrow + c0 + 8);
            mma16816h(acc[nj], ah, bf);
            mma16816h(acc[nj], al, bf);
        }
    }

    const int orow = o0 + os * 16 + g;
    const float b0 = bias[orow], b8 = bias[orow + 8];

    if (o0 >= 256) {
        int h = (orow - 256) >> 5, c = orow & 31;
        __half* v0p = g_v16 + ((size_t)(b * NH + h) * DH + c) * NPIX + n0;
        __half* v8p = v0p + 8 * NPIX;
#pragma unroll
        for (int nj = 0; nj < 8; nj++) {
            int n = ns * 64 + nj * 8 + qu;
            *(__half2*)(v0p + n) = __floats2half2_rn(acc[nj][0] + b0, acc[nj][1] + b0);
            *(__half2*)(v8p + n) = __floats2half2_rn(acc[nj][2] + b8, acc[nj][3] + b8);
        }
    } else {
        const bool isQ = (o0 < 128);
        const float sc = isQ ? SCALE2 : 1.0f;
        __syncthreads();
        int lo = os * 16 + g;
#pragma unroll
        for (int nj = 0; nj < 8; nj++) {
            int nn = ns * 64 + nj * 8 + qu;
            *(__half2*)&Hs[lo][nn] =
                __floats2half2_rn((acc[nj][0] + b0) * sc, (acc[nj][1] + b0) * sc);
            *(__half2*)&Hs[lo + 8][nn] =
                __floats2half2_rn((acc[nj][2] + b8) * sc, (acc[nj][3] + b8) * sc);
        }
        __syncthreads();
        int n_loc = tid & 127;
        int hseg = tid >> 7;
        int oBase = (isQ ? o0 : o0 - 128) + hseg * 32;
        int head = oBase >> 5;
        int bh = b * NH + head;
        __half* dst = (isQ ? g_q16 : g_k16) +
                      ((size_t)bh * NPIX + n0 + n_loc) * DH;
        __half tmp[32];
        float nrm2 = 0.f;
#pragma unroll
        for (int c = 0; c < 32; c++) {
            tmp[c] = Hs[hseg * 32 + c][n_loc];
            float f = __half2float(tmp[c]);
            nrm2 = fmaf(f, f, nrm2);
        }
#pragma unroll
        for (int j = 0; j < 4; j++)
            *(uint4*)(dst + j * 8) = *(uint4*)(tmp + j * 8);

        if (isQ) {
            g_qb[(size_t)bh * NPIX + n0 + n_loc] = sqrtf(nrm2);
        } else {
            // max |k|^2 over CTA (per hseg) then one atomic
#pragma unroll
            for (int off = 16; off > 0; off >>= 1)
                nrm2 = fmaxf(nrm2, __shfl_xor_sync(0xffffffffu, nrm2, off));
            if (lane == 0) red[wid] = nrm2;
            __syncthreads();
            if ((tid & 127) == 0) {
                float m = fmaxf(fmaxf(red[hseg * 4], red[hseg * 4 + 1]),
                                fmaxf(red[hseg * 4 + 2], red[hseg * 4 + 3]));
                atomicMax(&g_kmax[bh], __float_as_uint(m));
            }
        }
    }
}

// ---------------------------------------------------------------------------
// K4: generic fp16 GEMM (proj): fp32 out + bias + residual
// ---------------------------------------------------------------------------
__global__ void __launch_bounds__(256) gemm16_kernel(
    const __half* __restrict__ W2, const float* __restrict__ bias,
    const __half* __restrict__ Hin, float* __restrict__ Out,
    const float* __restrict__ resid, int Otot) {
    __shared__ __align__(16) __half Hs[128][136];

    const int tid = threadIdx.x, lane = tid & 31, wid = tid >> 5;
    const int g = lane >> 2, qu = (lane & 3) * 2;
    const int b = blockIdx.z, o0 = blockIdx.y * 64, n0 = blockIdx.x * 128;
    const int os = wid & 3, ns = wid >> 2;

    {
        const __half* hsrc = Hin + ((size_t)b * NPIX + n0) * CC;
        int row = tid >> 1, part = tid & 1;
#pragma unroll
        for (int j = 0; j < 8; j++)
            *(uint4*)&Hs[row][part * 64 + j * 8] =
                *(const uint4*)(hsrc + (size_t)row * CC + part * 64 + j * 8);
    }
    __syncthreads();

    float acc[8][4];
#pragma unroll
    for (int nj = 0; nj < 8; nj++)
#pragma unroll
        for (int r = 0; r < 4; r++) acc[nj][r] = 0.f;

    const __half* w0 = W2 + (size_t)(o0 + os * 16 + g) * 256;
    const __half* w8 = w0 + 8 * 256;

#pragma unroll
    for (int kk = 0; kk < 8; kk++) {
        int c0 = kk * 16 + qu;
        uint32_t ah[4], al[4];
        ah[0] = *(const uint32_t*)(w0 + c0);
        ah[1] = *(const uint32_t*)(w8 + c0);
        ah[2] = *(const uint32_t*)(w0 + c0 + 8);
        ah[3] = *(const uint32_t*)(w8 + c0 + 8);
        al[0] = *(const uint32_t*)(w0 + 128 + c0);
        al[1] = *(const uint32_t*)(w8 + 128 + c0);
        al[2] = *(const uint32_t*)(w0 + 128 + c0 + 8);
        al[3] = *(const uint32_t*)(w8 + 128 + c0 + 8);
#pragma unroll
        for (int nj = 0; nj < 8; nj++) {
            uint32_t bf[2];
            const __half* hrow = &Hs[ns * 64 + nj * 8 + g][0];
            bf[0] = *(const uint32_t*)(hrow + c0);
            bf[1] = *(const uint32_t*)(hrow + c0 + 8);
            mma16816h(acc[nj], ah, bf);
            mma16816h(acc[nj], al, bf);
        }
    }

    const int orow = o0 + os * 16 + g;
    const float b0 = bias[orow], b8 = bias[orow + 8];
#pragma unroll
    for (int nj = 0; nj < 8; nj++) {
        int n = n0 + ns * 64 + nj * 8 + qu;
        float2 v0 = make_float2(acc[nj][0] + b0, acc[nj][1] + b0);
        float2 v1 = make_float2(acc[nj][2] + b8, acc[nj][3] + b8);
        float2 r0 = *(const float2*)(resid + ((size_t)b * Otot + orow) * NPIX + n);
        float2 r1 = *(const float2*)(resid + ((size_t)b * Otot + orow + 8) * NPIX + n);
        v0.x += r0.x; v0.y += r0.y;
        v1.x += r1.x; v1.y += r1.y;
        *(float2*)(Out + ((size_t)b * Otot + orow) * NPIX + n) = v0;
        *(float2*)(Out + ((size_t)b * Otot + orow + 8) * NPIX + n) = v1;
    }
}

// ---------------------------------------------------------------------------
// K3: flash attention with softmax-bound (no online max, no O rescale).
// p = exp2(s - B(row)), B = |q| * max|k| >= true max (Cauchy-Schwarz).
// ---------------------------------------------------------------------------
__global__ void __launch_bounds__(256) attn_mma_kernel() {
    __shared__ __align__(16) __half Ks[2][64][40];  // 80B row stride
    __shared__ __align__(16) __half Vs[2][32][72];  // 144B row stride

    const int tid = threadIdx.x;
    const int lane = tid & 31;
    const int wid = tid >> 5;
    const int g = lane >> 2;
    const int qu = (lane & 3) * 2;
    const int b = blockIdx.z, hh = blockIdx.y;
    const int q0 = blockIdx.x * 128;
    const int bh = b * NH + hh;

    const __half* qgl = g_q16 + ((size_t)bh * NPIX + q0 + wid * 16) * DH;
    const __half* kgl = g_k16 + (size_t)bh * NPIX * DH;
    const __half* vgl = g_v16 + (size_t)bh * DH * NPIX;

    // per-row softmax bound
    const float kmax = sqrtf(__uint_as_float(g_kmax[bh]));
    const float B0 = g_qb[(size_t)bh * NPIX + q0 + wid * 16 + g] * kmax;
    const float B8 = g_qb[(size_t)bh * NPIX + q0 + wid * 16 + g + 8] * kmax;

    uint32_t qa[2][4];
#pragma unroll
    for (int kk = 0; kk < 2; kk++) {
        int c0 = kk * 16 + qu;
        qa[kk][0] = *(const uint32_t*)(qgl + (size_t)g * DH + c0);
        qa[kk][1] = *(const uint32_t*)(qgl + (size_t)(g + 8) * DH + c0);
        qa[kk][2] = *(const uint32_t*)(qgl + (size_t)g * DH + c0 + 8);
        qa[kk][3] = *(const uint32_t*)(qgl + (size_t)(g + 8) * DH + c0 + 8);
    }

    float o[4][4];
#pragma unroll
    for (int ci = 0; ci < 4; ci++)
#pragma unroll
        for (int r = 0; r < 4; r++) o[ci][r] = 0.f;
    float lrun0 = 0.f, lrun8 = 0.f;   // per-lane partial sums

    const int krow = tid >> 2, kpart = tid & 3;
    const int vrow = tid >> 3, vpart = tid & 7;

    const uint32_t ks_base = (uint32_t)__cvta_generic_to_shared(&Ks[0][0][0]);
    const uint32_t vs_base = (uint32_t)__cvta_generic_to_shared(&Vs[0][0][0]);
    const uint32_t koff = ((lane & 7) * 40 + (lane >> 3) * 8) * 2;
    const uint32_t voff = ((((lane >> 4) & 1) * 8 + (lane & 7)) * 72 +
                           ((lane >> 3) & 1) * 8) * 2;

    *(uint4*)&Ks[0][krow][kpart * 8] =
        *(const uint4*)(kgl + (size_t)krow * DH + kpart * 8);
    *(uint4*)&Vs[0][vrow][vpart * 8] =
        *(const uint4*)(vgl + (size_t)vrow * NPIX + vpart * 8);
    __syncthreads();

    int cur = 0;
    for (int m0 = 0; m0 < NPIX; m0 += 64, cur ^= 1) {
        if (m0 + 64 < NPIX) {
            *(uint4*)&Ks[cur ^ 1][krow][kpart * 8] =
                *(const uint4*)(kgl + (size_t)(m0 + 64 + krow) * DH + kpart * 8);
            *(uint4*)&Vs[cur ^ 1][vrow][vpart * 8] =
                *(const uint4*)(vgl + (size_t)vrow * NPIX + m0 + 64 + vpart * 8);
        }

        const uint32_t kb = ks_base + (uint32_t)cur * (64 * 40 * 2) + koff;
        const uint32_t vb_base = vs_base + (uint32_t)cur * (32 * 72 * 2) + voff;

        // ---- S = Q K^T (k=32), then p = exp2(s - B) straight to fp16 ----
        uint32_t p16[8][2];
#pragma unroll
        for (int nj = 0; nj < 8; nj++) {
            uint32_t b00, b01, b10, b11;
            ldmx4(b00, b01, b10, b11, kb + nj * (8 * 40 * 2));
            float sacc[4] = {0.f, 0.f, 0.f, 0.f};
            uint32_t bf0[2] = {b00, b01};
            uint32_t bf1[2] = {b10, b11};
            mma16816h(sacc, qa[0], bf0);
            mma16816h(sacc, qa[1], bf1);
            p16[nj][0] = hex2(pack_f16x2(sacc[0] - B0, sacc[1] - B0));
            p16[nj][1] = hex2(pack_f16x2(sacc[2] - B8, sacc[3] - B8));
        }

        // ---- per-lane partial row sums (reduced once at the end) ----
        {
            uint32_t t0 = hadd2(hadd2(hadd2(p16[0][0], p16[1][0]),
                                      hadd2(p16[2][0], p16[3][0])),
                                hadd2(hadd2(p16[4][0], p16[5][0]),
                                      hadd2(p16[6][0], p16[7][0])));
            uint32_t t8 = hadd2(hadd2(hadd2(p16[0][1], p16[1][1]),
                                      hadd2(p16[2][1], p16[3][1])),
                                hadd2(hadd2(p16[4][1], p16[5][1]),
                                      hadd2(p16[6][1], p16[7][1])));
            float2 f0 = __half22float2(*(__half2*)&t0);
            float2 f8 = __half22float2(*(__half2*)&t8);
            lrun0 += f0.x + f0.y;
            lrun8 += f8.x + f8.y;
        }

        // ---- O += P V per 16-key tile (plain accumulation) ----
#pragma unroll
        for (int kt = 0; kt < 4; kt++) {
            uint32_t ph[4] = {p16[2 * kt][0], p16[2 * kt][1],
                              p16[2 * kt + 1][0], p16[2 * kt + 1][1]};
            uint32_t v00, v01, v10, v11, v20, v21, v30, v31;
            ldmx4(v00, v01, v10, v11, vb_base + kt * 32);
            ldmx4(v20, v21, v30, v31, vb_base + kt * 32 + (16 * 72 * 2));
            {
                uint32_t vb0[2] = {v00, v01}; mma16816h(o[0], ph, vb0);
                uint32_t vb1[2] = {v10, v11}; mma16816h(o[1], ph, vb1);
                uint32_t vb2[2] = {v20, v21}; mma16816h(o[2], ph, vb2);
                uint32_t vb3[2] = {v30, v31}; mma16816h(o[3], ph, vb3);
            }
        }

        __syncthreads();
    }

    // ---- final row-sum reduce (once), normalize + store ----
    lrun0 += __shfl_xor_sync(0xffffffffu, lrun0, 1);
    lrun0 += __shfl_xor_sync(0xffffffffu, lrun0, 2);
    lrun8 += __shfl_xor_sync(0xffffffffu, lrun8, 1);
    lrun8 += __shfl_xor_sync(0xffffffffu, lrun8, 2);
    float invl[2] = {1.0f / lrun0, 1.0f / lrun8};

#pragma unroll
    for (int h2 = 0; h2 < 2; h2++) {
        int qrow = q0 + wid * 16 + g + h2 * 8;
        __half* od = g_at + ((size_t)b * NPIX + qrow) * CC + hh * DH;
#pragma unroll
        for (int ci = 0; ci < 4; ci++) {
            *(__half2*)(od + ci * 8 + qu) =
                __floats2half2_rn(o[ci][h2 * 2] * invl[h2],
                                  o[ci][h2 * 2 + 1] * invl[h2]);
        }
    }
}

// ---------------------------------------------------------------------------
extern "C" void kernel_launch(void* const* d_in, const int* in_sizes, int n_in,
                              void* d_out, int out_size) {
    const float* x      = (const float*)d_in[0];
    const float* norm_w = (const float*)d_in[1];
    const float* norm_b = (const float*)d_in[2];
    const float* qkv_w  = (const float*)d_in[3];
    const float* qkv_b  = (const float*)d_in[4];
    const float* proj_w = (const float*)d_in[5];
    const float* proj_b = (const float*)d_in[6];
    float* out = (float*)d_out;

    __half *g_wp_p, *g_at_p;
    cudaGetSymbolAddress((void**)&g_wp_p, g_wp);
    cudaGetSymbolAddress((void**)&g_at_p, g_at);

    // K0: weight split + kmax reset
    wconv_kernel<<<256, 256>>>(qkv_w, proj_w);

    // K1: norm -> fp16 [b][n][c]
    norm_kernel<<<(BB * NPIX) / 256, 256>>>(x, norm_w, norm_b);

    // K2: qkv GEMM with fused attention-layout epilogue + bound stats
    gemmqkv_kernel<<<dim3(NPIX / 128, 384 / 64, BB), 256>>>(qkv_b);

    // K3: attention -> fp16 [b][n][c]   (4th launch: ncu profiles this)
    attn_mma_kernel<<<dim3(NPIX / 128, NH, BB), 256>>>();

    // K4: proj + bias + residual -> d_out
    gemm16_kernel<<<dim3(NPIX / 128, CC / 64, BB), 256>>>(
        g_wp_p, proj_b, g_at_p, out, x, CC);
}

// round 12
// speedup vs baseline: 7.4758x; 1.2017x over previous
#include <cuda_runtime.h>
#include <cuda_fp16.h>
#include <math.h>
#include <stdint.h>

#define BB 4
#define CC 128
#define NPIX 4096
#define NH 4
#define DH 32
#define EPSF 1e-6f
// (1/sqrt(32)) * log2(e)
#define SCALE2 0.25503486f

// Scratch (device globals)
__device__ __half g_ht[(size_t)BB * NPIX * CC];        // normed h fp16 [b][n][c]
__device__ __half g_wq[384 * 256];                     // qkv_w split hi|lo
__device__ __half g_wp[128 * 256];                     // proj_w split hi|lo
__device__ __half g_q16[(size_t)BB * NH * NPIX * DH];  // [bh][n][c], scaled
__device__ __half g_k16[(size_t)BB * NH * NPIX * DH];  // [bh][n][c]
__device__ __half g_v16[(size_t)BB * NH * DH * NPIX];  // [bh][c][n]
__device__ __half g_at[(size_t)BB * NPIX * CC];        // attn out fp16 [b][n][c]
__device__ float  g_qb[BB * NH * NPIX];                // |q_n| per row
__device__ unsigned g_kmax[BB * NH];                   // bits of max |k|^2

// ---------------------------------------------------------------------------
// helpers
// ---------------------------------------------------------------------------
__device__ __forceinline__ uint32_t hex2(uint32_t a) {
    uint32_t d;
    asm("ex2.approx.f16x2 %0, %1;" : "=r"(d) : "r"(a));
    return d;
}

__device__ __forceinline__ uint32_t hadd2(uint32_t a, uint32_t b) {
    uint32_t d;
    asm("add.f16x2 %0, %1, %2;" : "=r"(d) : "r"(a), "r"(b));
    return d;
}

__device__ __forceinline__ void mma16816h(float* d, const uint32_t* a,
                                          const uint32_t* b) {
    asm volatile(
        "mma.sync.aligned.m16n8k16.row.col.f32.f16.f16.f32 "
        "{%0,%1,%2,%3},{%4,%5,%6,%7},{%8,%9},{%0,%1,%2,%3};"
        : "+f"(d[0]), "+f"(d[1]), "+f"(d[2]), "+f"(d[3])
        : "r"(a[0]), "r"(a[1]), "r"(a[2]), "r"(a[3]), "r"(b[0]), "r"(b[1]));
}

__device__ __forceinline__ void ldmx4(uint32_t& r0, uint32_t& r1, uint32_t& r2,
                                      uint32_t& r3, uint32_t addr) {
    asm volatile(
        "ldmatrix.sync.aligned.m8n8.x4.shared.b16 {%0,%1,%2,%3}, [%4];"
        : "=r"(r0), "=r"(r1), "=r"(r2), "=r"(r3) : "r"(addr));
}

__device__ __forceinline__ uint32_t pack_f16x2(float a, float b) {
    uint32_t r;
    asm("cvt.rn.f16x2.f32 %0, %1, %2;" : "=r"(r) : "f"(b), "f"(a));
    return r;
}

__device__ __forceinline__ void cpasync16(uint32_t s, const void* g) {
    asm volatile("cp.async.cg.shared.global [%0], [%1], 16;"
                 :: "r"(s), "l"(g) : "memory");
}
#define CP_COMMIT() asm volatile("cp.async.commit_group;" ::: "memory")
#define CP_WAIT0()  asm volatile("cp.async.wait_group 0;" ::: "memory")

// ---------------------------------------------------------------------------
// K0: weight split + g_kmax reset
// ---------------------------------------------------------------------------
__global__ void wconv_kernel(const float* __restrict__ qkv_w,
                             const float* __restrict__ proj_w) {
    int t = blockIdx.x * 256 + threadIdx.x;   // 0 .. 65535
    if (t < BB * NH) g_kmax[t] = 0u;
    const float* src;
    __half* dst;
    int idx;
    if (t < 384 * 128) { src = qkv_w; dst = g_wq; idx = t; }
    else               { src = proj_w; dst = g_wp; idx = t - 384 * 128; }
    int row = idx >> 7, c = idx & 127;
    float v = src[idx];
    __half hi = __float2half_rn(v);
    dst[row * 256 + c] = hi;
    dst[row * 256 + 128 + c] = __float2half_rn(v - __half2float(hi));
}

// ---------------------------------------------------------------------------
// K1: per-pixel channel LayerNorm -> fp16 [b][n][c]
// ---------------------------------------------------------------------------
__global__ void norm_kernel(const float* __restrict__ x,
                            const float* __restrict__ w,
                            const float* __restrict__ bias) {
    int pix = blockIdx.x * blockDim.x + threadIdx.x;
    int b = pix >> 12;
    int n = pix & (NPIX - 1);
    const float* xp = x + (size_t)b * CC * NPIX + n;
    float s = 0.f, s2 = 0.f;
#pragma unroll 8
    for (int c = 0; c < CC; c++) {
        float v = xp[(size_t)c * NPIX];
        s += v;
        s2 += v * v;
    }
    float mean = s * (1.0f / CC);
    float var  = s2 * (1.0f / CC) - mean * mean;
    float inv  = rsqrtf(var + EPSF);
    __half* hp = g_ht + ((size_t)b * NPIX + n) * CC;
#pragma unroll 4
    for (int c = 0; c < CC; c += 2) {
        float v0 = (xp[(size_t)c * NPIX] - mean) * inv * w[c] + bias[c];
        float v1 = (xp[(size_t)(c + 1) * NPIX] - mean) * inv * w[c + 1] + bias[c + 1];
        *(__half2*)(hp + c) = __floats2half2_rn(v0, v1);
    }
}

// ---------------------------------------------------------------------------
// K2: qkv GEMM with fused attention-layout epilogue + softmax-bound stats.
// ---------------------------------------------------------------------------
__global__ void __launch_bounds__(256) gemmqkv_kernel(
    const float* __restrict__ bias) {
    __shared__ __align__(16) __half Hs[128][136];
    __shared__ float red[8];

    const int tid = threadIdx.x, lane = tid & 31, wid = tid >> 5;
    const int g = lane >> 2, qu = (lane & 3) * 2;
    const int b = blockIdx.z, o0 = blockIdx.y * 64, n0 = blockIdx.x * 128;
    const int os = wid & 3, ns = wid >> 2;

    {
        const __half* hsrc = g_ht + ((size_t)b * NPIX + n0) * CC;
        int row = tid >> 1, part = tid & 1;
#pragma unroll
        for (int j = 0; j < 8; j++)
            *(uint4*)&Hs[row][part * 64 + j * 8] =
                *(const uint4*)(hsrc + (size_t)row * CC + part * 64 + j * 8);
    }
    __syncthreads();

    float acc[8][4];
#pragma unroll
    for (int nj = 0; nj < 8; nj++)
#pragma unroll
        for (int r = 0; r < 4; r++) acc[nj][r] = 0.f;

    const __half* w0 = g_wq + (size_t)(o0 + os * 16 + g) * 256;
    const __half* w8 = w0 + 8 * 256;

#pragma unroll
    for (int kk = 0; kk < 8; kk++) {
        int c0 = kk * 16 + qu;
        uint32_t ah[4], al[4];
        ah[0] = *(const uint32_t*)(w0 + c0);
        ah[1] = *(const uint32_t*)(w8 + c0);
        ah[2] = *(const uint32_t*)(w0 + c0 + 8);
        ah[3] = *(const uint32_t*)(w8 + c0 + 8);
        al[0] = *(const uint32_t*)(w0 + 128 + c0);
        al[1] = *(const uint32_t*)(w8 + 128 + c0);
        al[2] = *(const uint32_t*)(w0 + 128 + c0 + 8);
        al[3] = *(const uint32_t*)(w8 + 128 + c0 + 8);
#pragma unroll
        for (int nj = 0; nj < 8; nj++) {
            uint32_t bf[2];
            const __half* hrow = &Hs[ns * 64 + nj * 8 + g][0];
            bf[0] = *(const uint32_t*)(hrow + c0);
            bf[1] = *(const uint32_t*)(hrow + c0 + 8);
            mma16816h(acc[nj], ah, bf);
            mma16816h(acc[nj], al, bf);
        }
    }

    const int orow = o0 + os * 16 + g;
    const float b0 = bias[orow], b8 = bias[orow + 8];

    if (o0 >= 256) {
        int h = (orow - 256) >> 5, c = orow & 31;
        __half* v0p = g_v16 + ((size_t)(b * NH + h) * DH + c) * NPIX + n0;
        __half* v8p = v0p + 8 * NPIX;
#pragma unroll
        for (int nj = 0; nj < 8; nj++) {
            int n = ns * 64 + nj * 8 + qu;
            *(__half2*)(v0p + n) = __floats2half2_rn(acc[nj][0] + b0, acc[nj][1] + b0);
            *(__half2*)(v8p + n) = __floats2half2_rn(acc[nj][2] + b8, acc[nj][3] + b8);
        }
    } else {
        const bool isQ = (o0 < 128);
        const float sc = isQ ? SCALE2 : 1.0f;
        __syncthreads();
        int lo = os * 16 + g;
#pragma unroll
        for (int nj = 0; nj < 8; nj++) {
            int nn = ns * 64 + nj * 8 + qu;
            *(__half2*)&Hs[lo][nn] =
                __floats2half2_rn((acc[nj][0] + b0) * sc, (acc[nj][1] + b0) * sc);
            *(__half2*)&Hs[lo + 8][nn] =
                __floats2half2_rn((acc[nj][2] + b8) * sc, (acc[nj][3] + b8) * sc);
        }
        __syncthreads();
        int n_loc = tid & 127;
        int hseg = tid >> 7;
        int oBase = (isQ ? o0 : o0 - 128) + hseg * 32;
        int head = oBase >> 5;
        int bh = b * NH + head;
        __half* dst = (isQ ? g_q16 : g_k16) +
                      ((size_t)bh * NPIX + n0 + n_loc) * DH;
        __half tmp[32];
        float nrm2 = 0.f;
#pragma unroll
        for (int c = 0; c < 32; c++) {
            tmp[c] = Hs[hseg * 32 + c][n_loc];
            float f = __half2float(tmp[c]);
            nrm2 = fmaf(f, f, nrm2);
        }
#pragma unroll
        for (int j = 0; j < 4; j++)
            *(uint4*)(dst + j * 8) = *(uint4*)(tmp + j * 8);

        if (isQ) {
            g_qb[(size_t)bh * NPIX + n0 + n_loc] = sqrtf(nrm2);
        } else {
#pragma unroll
            for (int off = 16; off > 0; off >>= 1)
                nrm2 = fmaxf(nrm2, __shfl_xor_sync(0xffffffffu, nrm2, off));
            if (lane == 0) red[wid] = nrm2;
            __syncthreads();
            if ((tid & 127) == 0) {
                float m = fmaxf(fmaxf(red[hseg * 4], red[hseg * 4 + 1]),
                                fmaxf(red[hseg * 4 + 2], red[hseg * 4 + 3]));
                atomicMax(&g_kmax[bh], __float_as_uint(m));
            }
        }
    }
}

// ---------------------------------------------------------------------------
// K4: generic fp16 GEMM (proj): fp32 out + bias + residual
// ---------------------------------------------------------------------------
__global__ void __launch_bounds__(256) gemm16_kernel(
    const __half* __restrict__ W2, const float* __restrict__ bias,
    const __half* __restrict__ Hin, float* __restrict__ Out,
    const float* __restrict__ resid, int Otot) {
    __shared__ __align__(16) __half Hs[128][136];

    const int tid = threadIdx.x, lane = tid & 31, wid = tid >> 5;
    const int g = lane >> 2, qu = (lane & 3) * 2;
    const int b = blockIdx.z, o0 = blockIdx.y * 64, n0 = blockIdx.x * 128;
    const int os = wid & 3, ns = wid >> 2;

    {
        const __half* hsrc = Hin + ((size_t)b * NPIX + n0) * CC;
        int row = tid >> 1, part = tid & 1;
#pragma unroll
        for (int j = 0; j < 8; j++)
            *(uint4*)&Hs[row][part * 64 + j * 8] =
                *(const uint4*)(hsrc + (size_t)row * CC + part * 64 + j * 8);
    }
    __syncthreads();

    float acc[8][4];
#pragma unroll
    for (int nj = 0; nj < 8; nj++)
#pragma unroll
        for (int r = 0; r < 4; r++) acc[nj][r] = 0.f;

    const __half* w0 = W2 + (size_t)(o0 + os * 16 + g) * 256;
    const __half* w8 = w0 + 8 * 256;

#pragma unroll
    for (int kk = 0; kk < 8; kk++) {
        int c0 = kk * 16 + qu;
        uint32_t ah[4], al[4];
        ah[0] = *(const uint32_t*)(w0 + c0);
        ah[1] = *(const uint32_t*)(w8 + c0);
        ah[2] = *(const uint32_t*)(w0 + c0 + 8);
        ah[3] = *(const uint32_t*)(w8 + c0 + 8);
        al[0] = *(const uint32_t*)(w0 + 128 + c0);
        al[1] = *(const uint32_t*)(w8 + 128 + c0);
        al[2] = *(const uint32_t*)(w0 + 128 + c0 + 8);
        al[3] = *(const uint32_t*)(w8 + 128 + c0 + 8);
#pragma unroll
        for (int nj = 0; nj < 8; nj++) {
            uint32_t bf[2];
            const __half* hrow = &Hs[ns * 64 + nj * 8 + g][0];
            bf[0] = *(const uint32_t*)(hrow + c0);
            bf[1] = *(const uint32_t*)(hrow + c0 + 8);
            mma16816h(acc[nj], ah, bf);
            mma16816h(acc[nj], al, bf);
        }
    }

    const int orow = o0 + os * 16 + g;
    const float b0 = bias[orow], b8 = bias[orow + 8];
#pragma unroll
    for (int nj = 0; nj < 8; nj++) {
        int n = n0 + ns * 64 + nj * 8 + qu;
        float2 v0 = make_float2(acc[nj][0] + b0, acc[nj][1] + b0);
        float2 v1 = make_float2(acc[nj][2] + b8, acc[nj][3] + b8);
        float2 r0 = *(const float2*)(resid + ((size_t)b * Otot + orow) * NPIX + n);
        float2 r1 = *(const float2*)(resid + ((size_t)b * Otot + orow + 8) * NPIX + n);
        v0.x += r0.x; v0.y += r0.y;
        v1.x += r1.x; v1.y += r1.y;
        *(float2*)(Out + ((size_t)b * Otot + orow) * NPIX + n) = v0;
        *(float2*)(Out + ((size_t)b * Otot + orow + 8) * NPIX + n) = v1;
    }
}

// ---------------------------------------------------------------------------
// K3: flash attention, softmax-bound, cp.async double buffer, 4 CTAs/SM.
// ---------------------------------------------------------------------------
__global__ void __launch_bounds__(256, 4) attn_mma_kernel() {
    __shared__ __align__(16) __half Ks[2][64][40];  // 80B row stride
    __shared__ __align__(16) __half Vs[2][32][72];  // 144B row stride

    const int tid = threadIdx.x;
    const int lane = tid & 31;
    const int wid = tid >> 5;
    const int g = lane >> 2;
    const int qu = (lane & 3) * 2;
    const int b = blockIdx.z, hh = blockIdx.y;
    const int q0 = blockIdx.x * 128;
    const int bh = b * NH + hh;

    const __half* qgl = g_q16 + ((size_t)bh * NPIX + q0 + wid * 16) * DH;
    const __half* kgl = g_k16 + (size_t)bh * NPIX * DH;
    const __half* vgl = g_v16 + (size_t)bh * DH * NPIX;

    const float kmax = sqrtf(__uint_as_float(g_kmax[bh]));
    const float B0 = g_qb[(size_t)bh * NPIX + q0 + wid * 16 + g] * kmax;
    const float B8 = g_qb[(size_t)bh * NPIX + q0 + wid * 16 + g + 8] * kmax;

    uint32_t qa[2][4];
#pragma unroll
    for (int kk = 0; kk < 2; kk++) {
        int c0 = kk * 16 + qu;
        qa[kk][0] = *(const uint32_t*)(qgl + (size_t)g * DH + c0);
        qa[kk][1] = *(const uint32_t*)(qgl + (size_t)(g + 8) * DH + c0);
        qa[kk][2] = *(const uint32_t*)(qgl + (size_t)g * DH + c0 + 8);
        qa[kk][3] = *(const uint32_t*)(qgl + (size_t)(g + 8) * DH + c0 + 8);
    }

    float o[4][4];
#pragma unroll
    for (int ci = 0; ci < 4; ci++)
#pragma unroll
        for (int r = 0; r < 4; r++) o[ci][r] = 0.f;
    float lrun0 = 0.f, lrun8 = 0.f;

    const int krow = tid >> 2, kpart = tid & 3;
    const int vrow = tid >> 3, vpart = tid & 7;

    const uint32_t ks_base = (uint32_t)__cvta_generic_to_shared(&Ks[0][0][0]);
    const uint32_t vs_base = (uint32_t)__cvta_generic_to_shared(&Vs[0][0][0]);
    const uint32_t koff = ((lane & 7) * 40 + (lane >> 3) * 8) * 2;
    const uint32_t voff = ((((lane >> 4) & 1) * 8 + (lane & 7)) * 72 +
                           ((lane >> 3) & 1) * 8) * 2;
    // per-thread cp.async store offsets (within a buffer)
    const uint32_t kst = (uint32_t)(krow * 40 + kpart * 8) * 2;
    const uint32_t vst = (uint32_t)(vrow * 72 + vpart * 8) * 2;
    const __half* kld = kgl + (size_t)krow * DH + kpart * 8;
    const __half* vld = vgl + (size_t)vrow * NPIX + vpart * 8;

    // preload chunk 0
    cpasync16(ks_base + kst, kld);
    cpasync16(vs_base + vst, vld);
    CP_COMMIT();
    CP_WAIT0();
    __syncthreads();

    int cur = 0;
    for (int m0 = 0; m0 < NPIX; m0 += 64, cur ^= 1) {
        if (m0 + 64 < NPIX) {
            uint32_t nb = (uint32_t)(cur ^ 1);
            cpasync16(ks_base + nb * (64 * 40 * 2) + kst,
                      kld + (size_t)(m0 + 64) * DH);
            cpasync16(vs_base + nb * (32 * 72 * 2) + vst, vld + m0 + 64);
            CP_COMMIT();
        }

        const uint32_t kb = ks_base + (uint32_t)cur * (64 * 40 * 2) + koff;
        const uint32_t vb_base = vs_base + (uint32_t)cur * (32 * 72 * 2) + voff;

        // ---- S = Q K^T (k=32), p = exp2(s - B) straight to fp16 ----
        uint32_t p16[8][2];
#pragma unroll
        for (int nj = 0; nj < 8; nj++) {
            uint32_t b00, b01, b10, b11;
            ldmx4(b00, b01, b10, b11, kb + nj * (8 * 40 * 2));
            float sacc[4] = {0.f, 0.f, 0.f, 0.f};
            uint32_t bf0[2] = {b00, b01};
            uint32_t bf1[2] = {b10, b11};
            mma16816h(sacc, qa[0], bf0);
            mma16816h(sacc, qa[1], bf1);
            p16[nj][0] = hex2(pack_f16x2(sacc[0] - B0, sacc[1] - B0));
            p16[nj][1] = hex2(pack_f16x2(sacc[2] - B8, sacc[3] - B8));
        }

        // ---- per-lane partial row sums ----
        {
            uint32_t t0 = hadd2(hadd2(hadd2(p16[0][0], p16[1][0]),
                                      hadd2(p16[2][0], p16[3][0])),
                                hadd2(hadd2(p16[4][0], p16[5][0]),
                                      hadd2(p16[6][0], p16[7][0])));
            uint32_t t8 = hadd2(hadd2(hadd2(p16[0][1], p16[1][1]),
                                      hadd2(p16[2][1], p16[3][1])),
                                hadd2(hadd2(p16[4][1], p16[5][1]),
                                      hadd2(p16[6][1], p16[7][1])));
            float2 f0 = __half22float2(*(__half2*)&t0);
            float2 f8 = __half22float2(*(__half2*)&t8);
            lrun0 += f0.x + f0.y;
            lrun8 += f8.x + f8.y;
        }

        // ---- O += P V per 16-key tile ----
#pragma unroll
        for (int kt = 0; kt < 4; kt++) {
            uint32_t ph[4] = {p16[2 * kt][0], p16[2 * kt][1],
                              p16[2 * kt + 1][0], p16[2 * kt + 1][1]};
            uint32_t v00, v01, v10, v11, v20, v21, v30, v31;
            ldmx4(v00, v01, v10, v11, vb_base + kt * 32);
            ldmx4(v20, v21, v30, v31, vb_base + kt * 32 + (16 * 72 * 2));
            {
                uint32_t vb0[2] = {v00, v01}; mma16816h(o[0], ph, vb0);
                uint32_t vb1[2] = {v10, v11}; mma16816h(o[1], ph, vb1);
                uint32_t vb2[2] = {v20, v21}; mma16816h(o[2], ph, vb2);
                uint32_t vb3[2] = {v30, v31}; mma16816h(o[3], ph, vb3);
            }
        }

        CP_WAIT0();
        __syncthreads();
    }

    // ---- final row-sum reduce, normalize + store ----
    lrun0 += __shfl_xor_sync(0xffffffffu, lrun0, 1);
    lrun0 += __shfl_xor_sync(0xffffffffu, lrun0, 2);
    lrun8 += __shfl_xor_sync(0xffffffffu, lrun8, 1);
    lrun8 += __shfl_xor_sync(0xffffffffu, lrun8, 2);
    float invl[2] = {1.0f / lrun0, 1.0f / lrun8};

#pragma unroll
    for (int h2 = 0; h2 < 2; h2++) {
        int qrow = q0 + wid * 16 + g + h2 * 8;
        __half* od = g_at + ((size_t)b * NPIX + qrow) * CC + hh * DH;
#pragma unroll
        for (int ci = 0; ci < 4; ci++) {
            *(__half2*)(od + ci * 8 + qu) =
                __floats2half2_rn(o[ci][h2 * 2] * invl[h2],
                                  o[ci][h2 * 2 + 1] * invl[h2]);
        }
    }
}

// ---------------------------------------------------------------------------
extern "C" void kernel_launch(void* const* d_in, const int* in_sizes, int n_in,
                              void* d_out, int out_size) {
    const float* x      = (const float*)d_in[0];
    const float* norm_w = (const float*)d_in[1];
    const float* norm_b = (const float*)d_in[2];
    const float* qkv_w  = (const float*)d_in[3];
    const float* qkv_b  = (const float*)d_in[4];
    const float* proj_w = (const float*)d_in[5];
    const float* proj_b = (const float*)d_in[6];
    float* out = (float*)d_out;

    __half *g_wp_p, *g_at_p;
    cudaGetSymbolAddress((void**)&g_wp_p, g_wp);
    cudaGetSymbolAddress((void**)&g_at_p, g_at);

    // K0: weight split + kmax reset
    wconv_kernel<<<256, 256>>>(qkv_w, proj_w);

    // K1: norm -> fp16 [b][n][c]
    norm_kernel<<<(BB * NPIX) / 256, 256>>>(x, norm_w, norm_b);

    // K2: qkv GEMM with fused attention-layout epilogue + bound stats
    gemmqkv_kernel<<<dim3(NPIX / 128, 384 / 64, BB), 256>>>(qkv_b);

    // K3: attention -> fp16 [b][n][c]   (4th launch: ncu profiles this)
    attn_mma_kernel<<<dim3(NPIX / 128, NH, BB), 256>>>();

    // K4: proj + bias + residual -> d_out
    gemm16_kernel<<<dim3(NPIX / 128, CC / 64, BB), 256>>>(
        g_wp_p, proj_b, g_at_p, out, x, CC);
}

// round 13
// speedup vs baseline: 8.2384x; 1.1020x over previous
#include <cuda_runtime.h>
#include <cuda_fp16.h>
#include <math.h>
#include <stdint.h>

#define BB 4
#define CC 128
#define NPIX 4096
#define NH 4
#define DH 32
#define EPSF 1e-6f
// (1/sqrt(32)) * log2(e)
#define SCALE2 0.25503486f

// Scratch (device globals)
__device__ __half g_ht[(size_t)BB * NPIX * CC];        // normed h fp16 [b][n][c]
__device__ __half g_wq[384 * 128];                     // qkv_w plain fp16
__device__ __half g_wp[128 * 256];                     // proj_w split hi|lo
__device__ __half g_q16[(size_t)BB * NH * NPIX * DH];  // [bh][n][c], scaled
__device__ __half g_k16[(size_t)BB * NH * NPIX * DH];  // [bh][n][c]
__device__ __half g_v16[(size_t)BB * NH * DH * NPIX];  // [bh][c][n]
__device__ __half g_at[(size_t)BB * NPIX * CC];        // attn out fp16 [b][n][c]
__device__ float  g_qb[BB * NH * NPIX];                // |q_n| per row
__device__ unsigned g_kmax[BB * NH];                   // bits of max |k|^2

// ---------------------------------------------------------------------------
// helpers
// ---------------------------------------------------------------------------
__device__ __forceinline__ uint32_t hex2(uint32_t a) {
    uint32_t d;
    asm("ex2.approx.f16x2 %0, %1;" : "=r"(d) : "r"(a));
    return d;
}

__device__ __forceinline__ uint32_t hadd2(uint32_t a, uint32_t b) {
    uint32_t d;
    asm("add.f16x2 %0, %1, %2;" : "=r"(d) : "r"(a), "r"(b));
    return d;
}

__device__ __forceinline__ void mma16816h(float* d, const uint32_t* a,
                                          const uint32_t* b) {
    asm volatile(
        "mma.sync.aligned.m16n8k16.row.col.f32.f16.f16.f32 "
        "{%0,%1,%2,%3},{%4,%5,%6,%7},{%8,%9},{%0,%1,%2,%3};"
        : "+f"(d[0]), "+f"(d[1]), "+f"(d[2]), "+f"(d[3])
        : "r"(a[0]), "r"(a[1]), "r"(a[2]), "r"(a[3]), "r"(b[0]), "r"(b[1]));
}

__device__ __forceinline__ void ldmx4(uint32_t& r0, uint32_t& r1, uint32_t& r2,
                                      uint32_t& r3, uint32_t addr) {
    asm volatile(
        "ldmatrix.sync.aligned.m8n8.x4.shared.b16 {%0,%1,%2,%3}, [%4];"
        : "=r"(r0), "=r"(r1), "=r"(r2), "=r"(r3) : "r"(addr));
}

__device__ __forceinline__ uint32_t pack_f16x2(float a, float b) {
    uint32_t r;
    asm("cvt.rn.f16x2.f32 %0, %1, %2;" : "=r"(r) : "f"(b), "f"(a));
    return r;
}

__device__ __forceinline__ void cpasync16(uint32_t s, const void* g) {
    asm volatile("cp.async.cg.shared.global [%0], [%1], 16;"
                 :: "r"(s), "l"(g) : "memory");
}
#define CP_COMMIT() asm volatile("cp.async.commit_group;" ::: "memory")

// ---------------------------------------------------------------------------
// K0: weight conversion (qkv plain fp16; proj split hi|lo) + g_kmax reset
// ---------------------------------------------------------------------------
__global__ void wconv_kernel(const float* __restrict__ qkv_w,
                             const float* __restrict__ proj_w) {
    int t = blockIdx.x * 256 + threadIdx.x;   // 0 .. 65535
    if (t < BB * NH) g_kmax[t] = 0u;
    if (t < 384 * 128) {
        g_wq[t] = __float2half_rn(qkv_w[t]);
    } else {
        int idx = t - 384 * 128;
        int row = idx >> 7, c = idx & 127;
        float v = proj_w[idx];
        __half hi = __float2half_rn(v);
        g_wp[row * 256 + c] = hi;
        g_wp[row * 256 + 128 + c] = __float2half_rn(v - __half2float(hi));
    }
}

// ---------------------------------------------------------------------------
// K1: LayerNorm, 4 threads/pixel -> fp16 [b][n][c]. 256 CTAs.
// ---------------------------------------------------------------------------
__global__ void __launch_bounds__(256) norm_kernel(
    const float* __restrict__ x, const float* __restrict__ w,
    const float* __restrict__ bias) {
    __shared__ float sred[2][4][64];
    const int tid = threadIdx.x;
    const int n_loc = tid & 63;
    const int cg = tid >> 6;                 // channel group 0..3
    const int pix = blockIdx.x * 64 + n_loc;
    const int b = pix >> 12, n = pix & (NPIX - 1);
    const float* xp = x + (size_t)b * CC * NPIX + n;

    float vals[32];
    float s = 0.f, s2 = 0.f;
#pragma unroll
    for (int i = 0; i < 32; i++) {
        float v = xp[(size_t)(cg * 32 + i) * NPIX];
        vals[i] = v;
        s += v;
        s2 = fmaf(v, v, s2);
    }
    sred[0][cg][n_loc] = s;
    sred[1][cg][n_loc] = s2;
    __syncthreads();
    s  = sred[0][0][n_loc] + sred[0][1][n_loc] + sred[0][2][n_loc] + sred[0][3][n_loc];
    s2 = sred[1][0][n_loc] + sred[1][1][n_loc] + sred[1][2][n_loc] + sred[1][3][n_loc];
    float mean = s * (1.0f / CC);
    float var  = s2 * (1.0f / CC) - mean * mean;
    float inv  = rsqrtf(var + EPSF);

    __half* hp = g_ht + ((size_t)b * NPIX + n) * CC + cg * 32;
#pragma unroll
    for (int i = 0; i < 32; i += 2) {
        int c = cg * 32 + i;
        float v0 = (vals[i] - mean) * inv * w[c] + bias[c];
        float v1 = (vals[i + 1] - mean) * inv * w[c + 1] + bias[c + 1];
        *(__half2*)(hp + i) = __floats2half2_rn(v0, v1);
    }
}

// ---------------------------------------------------------------------------
// K2: qkv GEMM (plain fp16 weights, 1 MMA/kstep) + fused layouts + stats.
// ---------------------------------------------------------------------------
__global__ void __launch_bounds__(256) gemmqkv_kernel(
    const float* __restrict__ bias) {
    __shared__ __align__(16) __half Hs[128][136];
    __shared__ float red[8];

    const int tid = threadIdx.x, lane = tid & 31, wid = tid >> 5;
    const int g = lane >> 2, qu = (lane & 3) * 2;
    const int b = blockIdx.z, o0 = blockIdx.y * 64, n0 = blockIdx.x * 128;
    const int os = wid & 3, ns = wid >> 2;

    {
        const __half* hsrc = g_ht + ((size_t)b * NPIX + n0) * CC;
        int row = tid >> 1, part = tid & 1;
#pragma unroll
        for (int j = 0; j < 8; j++)
            *(uint4*)&Hs[row][part * 64 + j * 8] =
                *(const uint4*)(hsrc + (size_t)row * CC + part * 64 + j * 8);
    }
    __syncthreads();

    float acc[8][4];
#pragma unroll
    for (int nj = 0; nj < 8; nj++)
#pragma unroll
        for (int r = 0; r < 4; r++) acc[nj][r] = 0.f;

    const __half* w0 = g_wq + (size_t)(o0 + os * 16 + g) * 128;
    const __half* w8 = w0 + 8 * 128;

#pragma unroll
    for (int kk = 0; kk < 8; kk++) {
        int c0 = kk * 16 + qu;
        uint32_t ah[4];
        ah[0] = *(const uint32_t*)(w0 + c0);
        ah[1] = *(const uint32_t*)(w8 + c0);
        ah[2] = *(const uint32_t*)(w0 + c0 + 8);
        ah[3] = *(const uint32_t*)(w8 + c0 + 8);
#pragma unroll
        for (int nj = 0; nj < 8; nj++) {
            uint32_t bf[2];
            const __half* hrow = &Hs[ns * 64 + nj * 8 + g][0];
            bf[0] = *(const uint32_t*)(hrow + c0);
            bf[1] = *(const uint32_t*)(hrow + c0 + 8);
            mma16816h(acc[nj], ah, bf);
        }
    }

    const int orow = o0 + os * 16 + g;
    const float b0 = bias[orow], b8 = bias[orow + 8];

    if (o0 >= 256) {
        int h = (orow - 256) >> 5, c = orow & 31;
        __half* v0p = g_v16 + ((size_t)(b * NH + h) * DH + c) * NPIX + n0;
        __half* v8p = v0p + 8 * NPIX;
#pragma unroll
        for (int nj = 0; nj < 8; nj++) {
            int n = ns * 64 + nj * 8 + qu;
            *(__half2*)(v0p + n) = __floats2half2_rn(acc[nj][0] + b0, acc[nj][1] + b0);
            *(__half2*)(v8p + n) = __floats2half2_rn(acc[nj][2] + b8, acc[nj][3] + b8);
        }
    } else {
        const bool isQ = (o0 < 128);
        const float sc = isQ ? SCALE2 : 1.0f;
        __syncthreads();
        int lo = os * 16 + g;
#pragma unroll
        for (int nj = 0; nj < 8; nj++) {
            int nn = ns * 64 + nj * 8 + qu;
            *(__half2*)&Hs[lo][nn] =
                __floats2half2_rn((acc[nj][0] + b0) * sc, (acc[nj][1] + b0) * sc);
            *(__half2*)&Hs[lo + 8][nn] =
                __floats2half2_rn((acc[nj][2] + b8) * sc, (acc[nj][3] + b8) * sc);
        }
        __syncthreads();
        int n_loc = tid & 127;
        int hseg = tid >> 7;
        int oBase = (isQ ? o0 : o0 - 128) + hseg * 32;
        int head = oBase >> 5;
        int bh = b * NH + head;
        __half* dst = (isQ ? g_q16 : g_k16) +
                      ((size_t)bh * NPIX + n0 + n_loc) * DH;
        __half tmp[32];
        float nrm2 = 0.f;
#pragma unroll
        for (int c = 0; c < 32; c++) {
            tmp[c] = Hs[hseg * 32 + c][n_loc];
            float f = __half2float(tmp[c]);
            nrm2 = fmaf(f, f, nrm2);
        }
#pragma unroll
        for (int j = 0; j < 4; j++)
            *(uint4*)(dst + j * 8) = *(uint4*)(tmp + j * 8);

        if (isQ) {
            g_qb[(size_t)bh * NPIX + n0 + n_loc] = sqrtf(nrm2);
        } else {
#pragma unroll
            for (int off = 16; off > 0; off >>= 1)
                nrm2 = fmaxf(nrm2, __shfl_xor_sync(0xffffffffu, nrm2, off));
            if (lane == 0) red[wid] = nrm2;
            __syncthreads();
            if ((tid & 127) == 0) {
                float m = fmaxf(fmaxf(red[hseg * 4], red[hseg * 4 + 1]),
                                fmaxf(red[hseg * 4 + 2], red[hseg * 4 + 3]));
                atomicMax(&g_kmax[bh], __float_as_uint(m));
            }
        }
    }
}

// ---------------------------------------------------------------------------
// K4: proj GEMM (split weights): fp32 out + bias + residual
// ---------------------------------------------------------------------------
__global__ void __launch_bounds__(256) gemm16_kernel(
    const __half* __restrict__ W2, const float* __restrict__ bias,
    const __half* __restrict__ Hin, float* __restrict__ Out,
    const float* __restrict__ resid, int Otot) {
    __shared__ __align__(16) __half Hs[128][136];

    const int tid = threadIdx.x, lane = tid & 31, wid = tid >> 5;
    const int g = lane >> 2, qu = (lane & 3) * 2;
    const int b = blockIdx.z, o0 = blockIdx.y * 64, n0 = blockIdx.x * 128;
    const int os = wid & 3, ns = wid >> 2;

    {
        const __half* hsrc = Hin + ((size_t)b * NPIX + n0) * CC;
        int row = tid >> 1, part = tid & 1;
#pragma unroll
        for (int j = 0; j < 8; j++)
            *(uint4*)&Hs[row][part * 64 + j * 8] =
                *(const uint4*)(hsrc + (size_t)row * CC + part * 64 + j * 8);
    }
    __syncthreads();

    float acc[8][4];
#pragma unroll
    for (int nj = 0; nj < 8; nj++)
#pragma unroll
        for (int r = 0; r < 4; r++) acc[nj][r] = 0.f;

    const __half* w0 = W2 + (size_t)(o0 + os * 16 + g) * 256;
    const __half* w8 = w0 + 8 * 256;

#pragma unroll
    for (int kk = 0; kk < 8; kk++) {
        int c0 = kk * 16 + qu;
        uint32_t ah[4], al[4];
        ah[0] = *(const uint32_t*)(w0 + c0);
        ah[1] = *(const uint32_t*)(w8 + c0);
        ah[2] = *(const uint32_t*)(w0 + c0 + 8);
        ah[3] = *(const uint32_t*)(w8 + c0 + 8);
        al[0] = *(const uint32_t*)(w0 + 128 + c0);
        al[1] = *(const uint32_t*)(w8 + 128 + c0);
        al[2] = *(const uint32_t*)(w0 + 128 + c0 + 8);
        al[3] = *(const uint32_t*)(w8 + 128 + c0 + 8);
#pragma unroll
        for (int nj = 0; nj < 8; nj++) {
            uint32_t bf[2];
            const __half* hrow = &Hs[ns * 64 + nj * 8 + g][0];
            bf[0] = *(const uint32_t*)(hrow + c0);
            bf[1] = *(const uint32_t*)(hrow + c0 + 8);
            mma16816h(acc[nj], ah, bf);
            mma16816h(acc[nj], al, bf);
        }
    }

    const int orow = o0 + os * 16 + g;
    const float b0 = bias[orow], b8 = bias[orow + 8];
#pragma unroll
    for (int nj = 0; nj < 8; nj++) {
        int n = n0 + ns * 64 + nj * 8 + qu;
        float2 v0 = make_float2(acc[nj][0] + b0, acc[nj][1] + b0);
        float2 v1 = make_float2(acc[nj][2] + b8, acc[nj][3] + b8);
        float2 r0 = *(const float2*)(resid + ((size_t)b * Otot + orow) * NPIX + n);
        float2 r1 = *(const float2*)(resid + ((size_t)b * Otot + orow + 8) * NPIX + n);
        v0.x += r0.x; v0.y += r0.y;
        v1.x += r1.x; v1.y += r1.y;
        *(float2*)(Out + ((size_t)b * Otot + orow) * NPIX + n) = v0;
        *(float2*)(Out + ((size_t)b * Otot + orow + 8) * NPIX + n) = v1;
    }
}

// ---------------------------------------------------------------------------
// K3: flash attention, softmax-bound, 4-stage cp.async pipeline, 4 CTAs/SM.
// ---------------------------------------------------------------------------
#define KBUF (64 * 40 * 2)
#define VBUF (32 * 72 * 2)
__global__ void __launch_bounds__(256, 4) attn_mma_kernel() {
    __shared__ __align__(16) __half Ks[4][64][40];  // 80B row stride
    __shared__ __align__(16) __half Vs[4][32][72];  // 144B row stride

    const int tid = threadIdx.x;
    const int lane = tid & 31;
    const int wid = tid >> 5;
    const int g = lane >> 2;
    const int qu = (lane & 3) * 2;
    const int b = blockIdx.z, hh = blockIdx.y;
    const int q0 = blockIdx.x * 128;
    const int bh = b * NH + hh;

    const __half* qgl = g_q16 + ((size_t)bh * NPIX + q0 + wid * 16) * DH;
    const __half* kgl = g_k16 + (size_t)bh * NPIX * DH;
    const __half* vgl = g_v16 + (size_t)bh * DH * NPIX;

    const float kmax = sqrtf(__uint_as_float(g_kmax[bh]));
    const float B0 = g_qb[(size_t)bh * NPIX + q0 + wid * 16 + g] * kmax;
    const float B8 = g_qb[(size_t)bh * NPIX + q0 + wid * 16 + g + 8] * kmax;

    uint32_t qa[2][4];
#pragma unroll
    for (int kk = 0; kk < 2; kk++) {
        int c0 = kk * 16 + qu;
        qa[kk][0] = *(const uint32_t*)(qgl + (size_t)g * DH + c0);
        qa[kk][1] = *(const uint32_t*)(qgl + (size_t)(g + 8) * DH + c0);
        qa[kk][2] = *(const uint32_t*)(qgl + (size_t)g * DH + c0 + 8);
        qa[kk][3] = *(const uint32_t*)(qgl + (size_t)(g + 8) * DH + c0 + 8);
    }

    float o[4][4];
#pragma unroll
    for (int ci = 0; ci < 4; ci++)
#pragma unroll
        for (int r = 0; r < 4; r++) o[ci][r] = 0.f;
    float lrun0 = 0.f, lrun8 = 0.f;

    const int krow = tid >> 2, kpart = tid & 3;
    const int vrow = tid >> 3, vpart = tid & 7;

    const uint32_t ks_base = (uint32_t)__cvta_generic_to_shared(&Ks[0][0][0]);
    const uint32_t vs_base = (uint32_t)__cvta_generic_to_shared(&Vs[0][0][0]);
    const uint32_t koff = ((lane & 7) * 40 + (lane >> 3) * 8) * 2;
    const uint32_t voff = ((((lane >> 4) & 1) * 8 + (lane & 7)) * 72 +
                           ((lane >> 3) & 1) * 8) * 2;
    const uint32_t kst = (uint32_t)(krow * 40 + kpart * 8) * 2;
    const uint32_t vst = (uint32_t)(vrow * 72 + vpart * 8) * 2;
    const __half* kld = kgl + (size_t)krow * DH + kpart * 8;
    const __half* vld = vgl + (size_t)vrow * NPIX + vpart * 8;

    // preload chunks 0..2 (one commit group each)
#pragma unroll
    for (int s = 0; s < 3; s++) {
        cpasync16(ks_base + s * KBUF + kst, kld + (size_t)(s * 64) * DH);
        cpasync16(vs_base + s * VBUF + vst, vld + s * 64);
        CP_COMMIT();
    }

    for (int i = 0; i < NPIX / 64; i++) {
        // chunk i ready when ≤2 groups pending (in-order completion)
        asm volatile("cp.async.wait_group 2;" ::: "memory");
        __syncthreads();

        const int st = i & 3;
        const uint32_t kb = ks_base + st * KBUF + koff;
        const uint32_t vb_base = vs_base + st * VBUF + voff;

        // ---- S = Q K^T (k=32), p = exp2(s - B) straight to fp16 ----
        uint32_t p16[8][2];
#pragma unroll
        for (int nj = 0; nj < 8; nj++) {
            uint32_t b00, b01, b10, b11;
            ldmx4(b00, b01, b10, b11, kb + nj * (8 * 40 * 2));
            float sacc[4] = {0.f, 0.f, 0.f, 0.f};
            uint32_t bf0[2] = {b00, b01};
            uint32_t bf1[2] = {b10, b11};
            mma16816h(sacc, qa[0], bf0);
            mma16816h(sacc, qa[1], bf1);
            p16[nj][0] = hex2(pack_f16x2(sacc[0] - B0, sacc[1] - B0));
            p16[nj][1] = hex2(pack_f16x2(sacc[2] - B8, sacc[3] - B8));
        }

        // ---- per-lane partial row sums ----
        {
            uint32_t t0 = hadd2(hadd2(hadd2(p16[0][0], p16[1][0]),
                                      hadd2(p16[2][0], p16[3][0])),
                                hadd2(hadd2(p16[4][0], p16[5][0]),
                                      hadd2(p16[6][0], p16[7][0])));
            uint32_t t8 = hadd2(hadd2(hadd2(p16[0][1], p16[1][1]),
                                      hadd2(p16[2][1], p16[3][1])),
                                hadd2(hadd2(p16[4][1], p16[5][1]),
                                      hadd2(p16[6][1], p16[7][1])));
            float2 f0 = __half22float2(*(__half2*)&t0);
            float2 f8 = __half22float2(*(__half2*)&t8);
            lrun0 += f0.x + f0.y;
            lrun8 += f8.x + f8.y;
        }

        // ---- O += P V per 16-key tile ----
#pragma unroll
        for (int kt = 0; kt < 4; kt++) {
            uint32_t ph[4] = {p16[2 * kt][0], p16[2 * kt][1],
                              p16[2 * kt + 1][0], p16[2 * kt + 1][1]};
            uint32_t v00, v01, v10, v11, v20, v21, v30, v31;
            ldmx4(v00, v01, v10, v11, vb_base + kt * 32);
            ldmx4(v20, v21, v30, v31, vb_base + kt * 32 + (16 * 72 * 2));
            {
                uint32_t vb0[2] = {v00, v01}; mma16816h(o[0], ph, vb0);
                uint32_t vb1[2] = {v10, v11}; mma16816h(o[1], ph, vb1);
                uint32_t vb2[2] = {v20, v21}; mma16816h(o[2], ph, vb2);
                uint32_t vb3[2] = {v30, v31}; mma16816h(o[3], ph, vb3);
            }
        }

        // issue chunk i+3 into stage (i+3)&3 (safe: chunk i-1 done CTA-wide),
        // always commit (empty groups keep the wait_group count aligned)
        if (i + 3 < NPIX / 64) {
            const int nst = (i + 3) & 3;
            cpasync16(ks_base + nst * KBUF + kst,
                      kld + (size_t)((i + 3) * 64) * DH);
            cpasync16(vs_base + nst * VBUF + vst, vld + (i + 3) * 64);
        }
        CP_COMMIT();
    }

    // ---- final row-sum reduce, normalize + store ----
    lrun0 += __shfl_xor_sync(0xffffffffu, lrun0, 1);
    lrun0 += __shfl_xor_sync(0xffffffffu, lrun0, 2);
    lrun8 += __shfl_xor_sync(0xffffffffu, lrun8, 1);
    lrun8 += __shfl_xor_sync(0xffffffffu, lrun8, 2);
    float invl[2] = {1.0f / lrun0, 1.0f / lrun8};

#pragma unroll
    for (int h2 = 0; h2 < 2; h2++) {
        int qrow = q0 + wid * 16 + g + h2 * 8;
        __half* od = g_at + ((size_t)b * NPIX + qrow) * CC + hh * DH;
#pragma unroll
        for (int ci = 0; ci < 4; ci++) {
            *(__half2*)(od + ci * 8 + qu) =
                __floats2half2_rn(o[ci][h2 * 2] * invl[h2],
                                  o[ci][h2 * 2 + 1] * invl[h2]);
        }
    }
}

// ---------------------------------------------------------------------------
extern "C" void kernel_launch(void* const* d_in, const int* in_sizes, int n_in,
                              void* d_out, int out_size) {
    const float* x      = (const float*)d_in[0];
    const float* norm_w = (const float*)d_in[1];
    const float* norm_b = (const float*)d_in[2];
    const float* qkv_w  = (const float*)d_in[3];
    const float* qkv_b  = (const float*)d_in[4];
    const float* proj_w = (const float*)d_in[5];
    const float* proj_b = (const float*)d_in[6];
    float* out = (float*)d_out;

    __half *g_wp_p, *g_at_p;
    cudaGetSymbolAddress((void**)&g_wp_p, g_wp);
    cudaGetSymbolAddress((void**)&g_at_p, g_at);

    // K0: weight conversion + kmax reset
    wconv_kernel<<<256, 256>>>(qkv_w, proj_w);

    // K1: norm -> fp16 [b][n][c]
    norm_kernel<<<(BB * NPIX) / 64, 256>>>(x, norm_w, norm_b);

    // K2: qkv GEMM + fused attention layouts + bound stats
    gemmqkv_kernel<<<dim3(NPIX / 128, 384 / 64, BB), 256>>>(qkv_b);

    // K3: attention -> fp16 [b][n][c]   (4th launch: ncu profiles this)
    attn_mma_kernel<<<dim3(NPIX / 128, NH, BB), 256>>>();

    // K4: proj + bias + residual -> d_out
    gemm16_kernel<<<dim3(NPIX / 128, CC / 64, BB), 256>>>(
        g_wp_p, proj_b, g_at_p, out, x, CC);
}

// round 14
// speedup vs baseline: 9.0217x; 1.0951x over previous
#include <cuda_runtime.h>
#include <cuda_fp16.h>
#include <math.h>
#include <stdint.h>

#define BB 4
#define CC 128
#define NPIX 4096
#define NH 4
#define DH 32
#define EPSF 1e-6f
// (1/sqrt(32)) * log2(e)
#define SCALE2 0.25503486f

// Scratch (device globals)
__device__ __half g_ht[(size_t)BB * NPIX * CC];        // normed h fp16 [b][n][c]
__device__ __half g_wq[384 * 128];                     // qkv_w plain fp16
__device__ __half g_wp[128 * 256];                     // proj_w split hi|lo
__device__ __half g_q16[(size_t)BB * NH * NPIX * DH];  // [bh][n][c], scaled
__device__ __half g_k16[(size_t)BB * NH * NPIX * DH];  // [bh][n][c]
__device__ __half g_v16[(size_t)BB * NH * DH * NPIX];  // [bh][c][n]
__device__ __half g_at[(size_t)BB * NPIX * CC];        // attn out fp16 [b][n][c]
__device__ float  g_qb[BB * NH * NPIX];                // |q_n| per row
__device__ unsigned g_kmax[BB * NH];                   // bits of max |k|^2

// ---------------------------------------------------------------------------
// helpers
// ---------------------------------------------------------------------------
__device__ __forceinline__ uint32_t hex2(uint32_t a) {
    uint32_t d;
    asm("ex2.approx.f16x2 %0, %1;" : "=r"(d) : "r"(a));
    return d;
}

__device__ __forceinline__ uint32_t hadd2(uint32_t a, uint32_t b) {
    uint32_t d;
    asm("add.f16x2 %0, %1, %2;" : "=r"(d) : "r"(a), "r"(b));
    return d;
}

__device__ __forceinline__ void mma16816h(float* d, const uint32_t* a,
                                          const uint32_t* b) {
    asm volatile(
        "mma.sync.aligned.m16n8k16.row.col.f32.f16.f16.f32 "
        "{%0,%1,%2,%3},{%4,%5,%6,%7},{%8,%9},{%0,%1,%2,%3};"
        : "+f"(d[0]), "+f"(d[1]), "+f"(d[2]), "+f"(d[3])
        : "r"(a[0]), "r"(a[1]), "r"(a[2]), "r"(a[3]), "r"(b[0]), "r"(b[1]));
}

__device__ __forceinline__ void ldmx4(uint32_t& r0, uint32_t& r1, uint32_t& r2,
                                      uint32_t& r3, uint32_t addr) {
    asm volatile(
        "ldmatrix.sync.aligned.m8n8.x4.shared.b16 {%0,%1,%2,%3}, [%4];"
        : "=r"(r0), "=r"(r1), "=r"(r2), "=r"(r3) : "r"(addr));
}

__device__ __forceinline__ uint32_t pack_f16x2(float a, float b) {
    uint32_t r;
    asm("cvt.rn.f16x2.f32 %0, %1, %2;" : "=r"(r) : "f"(b), "f"(a));
    return r;
}

__device__ __forceinline__ void cpasync16(uint32_t s, const void* g) {
    asm volatile("cp.async.cg.shared.global [%0], [%1], 16;"
                 :: "r"(s), "l"(g) : "memory");
}
#define CP_COMMIT() asm volatile("cp.async.commit_group;" ::: "memory")

// ---------------------------------------------------------------------------
// K0: weight conversion (qkv plain fp16; proj split hi|lo) + g_kmax reset
// ---------------------------------------------------------------------------
__global__ void wconv_kernel(const float* __restrict__ qkv_w,
                             const float* __restrict__ proj_w) {
    int t = blockIdx.x * 256 + threadIdx.x;   // 0 .. 65535
    if (t < BB * NH) g_kmax[t] = 0u;
    if (t < 384 * 128) {
        g_wq[t] = __float2half_rn(qkv_w[t]);
    } else {
        int idx = t - 384 * 128;
        int row = idx >> 7, c = idx & 127;
        float v = proj_w[idx];
        __half hi = __float2half_rn(v);
        g_wp[row * 256 + c] = hi;
        g_wp[row * 256 + 128 + c] = __float2half_rn(v - __half2float(hi));
    }
}

// ---------------------------------------------------------------------------
// K1: LayerNorm, 4 threads/pixel -> fp16 [b][n][c]. 256 CTAs.
// ---------------------------------------------------------------------------
__global__ void __launch_bounds__(256) norm_kernel(
    const float* __restrict__ x, const float* __restrict__ w,
    const float* __restrict__ bias) {
    __shared__ float sred[2][4][64];
    const int tid = threadIdx.x;
    const int n_loc = tid & 63;
    const int cg = tid >> 6;                 // channel group 0..3
    const int pix = blockIdx.x * 64 + n_loc;
    const int b = pix >> 12, n = pix & (NPIX - 1);
    const float* xp = x + (size_t)b * CC * NPIX + n;

    float vals[32];
    float s = 0.f, s2 = 0.f;
#pragma unroll
    for (int i = 0; i < 32; i++) {
        float v = xp[(size_t)(cg * 32 + i) * NPIX];
        vals[i] = v;
        s += v;
        s2 = fmaf(v, v, s2);
    }
    sred[0][cg][n_loc] = s;
    sred[1][cg][n_loc] = s2;
    __syncthreads();
    s  = sred[0][0][n_loc] + sred[0][1][n_loc] + sred[0][2][n_loc] + sred[0][3][n_loc];
    s2 = sred[1][0][n_loc] + sred[1][1][n_loc] + sred[1][2][n_loc] + sred[1][3][n_loc];
    float mean = s * (1.0f / CC);
    float var  = s2 * (1.0f / CC) - mean * mean;
    float inv  = rsqrtf(var + EPSF);

    __half* hp = g_ht + ((size_t)b * NPIX + n) * CC + cg * 32;
#pragma unroll
    for (int i = 0; i < 32; i += 2) {
        int c = cg * 32 + i;
        float v0 = (vals[i] - mean) * inv * w[c] + bias[c];
        float v1 = (vals[i + 1] - mean) * inv * w[c + 1] + bias[c + 1];
        *(__half2*)(hp + i) = __floats2half2_rn(v0, v1);
    }
}

// ---------------------------------------------------------------------------
// K2: qkv GEMM (plain fp16 weights, 1 MMA/kstep) + fused layouts + stats.
// ---------------------------------------------------------------------------
__global__ void __launch_bounds__(256) gemmqkv_kernel(
    const float* __restrict__ bias) {
    __shared__ __align__(16) __half Hs[128][136];
    __shared__ float red[8];

    const int tid = threadIdx.x, lane = tid & 31, wid = tid >> 5;
    const int g = lane >> 2, qu = (lane & 3) * 2;
    const int b = blockIdx.z, o0 = blockIdx.y * 64, n0 = blockIdx.x * 128;
    const int os = wid & 3, ns = wid >> 2;

    {
        const __half* hsrc = g_ht + ((size_t)b * NPIX + n0) * CC;
        int row = tid >> 1, part = tid & 1;
#pragma unroll
        for (int j = 0; j < 8; j++)
            *(uint4*)&Hs[row][part * 64 + j * 8] =
                *(const uint4*)(hsrc + (size_t)row * CC + part * 64 + j * 8);
    }
    __syncthreads();

    float acc[8][4];
#pragma unroll
    for (int nj = 0; nj < 8; nj++)
#pragma unroll
        for (int r = 0; r < 4; r++) acc[nj][r] = 0.f;

    const __half* w0 = g_wq + (size_t)(o0 + os * 16 + g) * 128;
    const __half* w8 = w0 + 8 * 128;

#pragma unroll
    for (int kk = 0; kk < 8; kk++) {
        int c0 = kk * 16 + qu;
        uint32_t ah[4];
        ah[0] = *(const uint32_t*)(w0 + c0);
        ah[1] = *(const uint32_t*)(w8 + c0);
        ah[2] = *(const uint32_t*)(w0 + c0 + 8);
        ah[3] = *(const uint32_t*)(w8 + c0 + 8);
#pragma unroll
        for (int nj = 0; nj < 8; nj++) {
            uint32_t bf[2];
            const __half* hrow = &Hs[ns * 64 + nj * 8 + g][0];
            bf[0] = *(const uint32_t*)(hrow + c0);
            bf[1] = *(const uint32_t*)(hrow + c0 + 8);
            mma16816h(acc[nj], ah, bf);
        }
    }

    const int orow = o0 + os * 16 + g;
    const float b0 = bias[orow], b8 = bias[orow + 8];

    if (o0 >= 256) {
        int h = (orow - 256) >> 5, c = orow & 31;
        __half* v0p = g_v16 + ((size_t)(b * NH + h) * DH + c) * NPIX + n0;
        __half* v8p = v0p + 8 * NPIX;
#pragma unroll
        for (int nj = 0; nj < 8; nj++) {
            int n = ns * 64 + nj * 8 + qu;
            *(__half2*)(v0p + n) = __floats2half2_rn(acc[nj][0] + b0, acc[nj][1] + b0);
            *(__half2*)(v8p + n) = __floats2half2_rn(acc[nj][2] + b8, acc[nj][3] + b8);
        }
    } else {
        const bool isQ = (o0 < 128);
        const float sc = isQ ? SCALE2 : 1.0f;
        __syncthreads();
        int lo = os * 16 + g;
#pragma unroll
        for (int nj = 0; nj < 8; nj++) {
            int nn = ns * 64 + nj * 8 + qu;
            *(__half2*)&Hs[lo][nn] =
                __floats2half2_rn((acc[nj][0] + b0) * sc, (acc[nj][1] + b0) * sc);
            *(__half2*)&Hs[lo + 8][nn] =
                __floats2half2_rn((acc[nj][2] + b8) * sc, (acc[nj][3] + b8) * sc);
        }
        __syncthreads();
        int n_loc = tid & 127;
        int hseg = tid >> 7;
        int oBase = (isQ ? o0 : o0 - 128) + hseg * 32;
        int head = oBase >> 5;
        int bh = b * NH + head;
        __half* dst = (isQ ? g_q16 : g_k16) +
                      ((size_t)bh * NPIX + n0 + n_loc) * DH;
        __half tmp[32];
        float nrm2 = 0.f;
#pragma unroll
        for (int c = 0; c < 32; c++) {
            tmp[c] = Hs[hseg * 32 + c][n_loc];
            float f = __half2float(tmp[c]);
            nrm2 = fmaf(f, f, nrm2);
        }
#pragma unroll
        for (int j = 0; j < 4; j++)
            *(uint4*)(dst + j * 8) = *(uint4*)(tmp + j * 8);

        if (isQ) {
            g_qb[(size_t)bh * NPIX + n0 + n_loc] = sqrtf(nrm2);
        } else {
#pragma unroll
            for (int off = 16; off > 0; off >>= 1)
                nrm2 = fmaxf(nrm2, __shfl_xor_sync(0xffffffffu, nrm2, off));
            if (lane == 0) red[wid] = nrm2;
            __syncthreads();
            if ((tid & 127) == 0) {
                float m = fmaxf(fmaxf(red[hseg * 4], red[hseg * 4 + 1]),
                                fmaxf(red[hseg * 4 + 2], red[hseg * 4 + 3]));
                atomicMax(&g_kmax[bh], __float_as_uint(m));
            }
        }
    }
}

// ---------------------------------------------------------------------------
// K4: proj GEMM (split weights): fp32 out + bias + residual
// ---------------------------------------------------------------------------
__global__ void __launch_bounds__(256) gemm16_kernel(
    const __half* __restrict__ W2, const float* __restrict__ bias,
    const __half* __restrict__ Hin, float* __restrict__ Out,
    const float* __restrict__ resid, int Otot) {
    __shared__ __align__(16) __half Hs[128][136];

    const int tid = threadIdx.x, lane = tid & 31, wid = tid >> 5;
    const int g = lane >> 2, qu = (lane & 3) * 2;
    const int b = blockIdx.z, o0 = blockIdx.y * 64, n0 = blockIdx.x * 128;
    const int os = wid & 3, ns = wid >> 2;

    {
        const __half* hsrc = Hin + ((size_t)b * NPIX + n0) * CC;
        int row = tid >> 1, part = tid & 1;
#pragma unroll
        for (int j = 0; j < 8; j++)
            *(uint4*)&Hs[row][part * 64 + j * 8] =
                *(const uint4*)(hsrc + (size_t)row * CC + part * 64 + j * 8);
    }
    __syncthreads();

    float acc[8][4];
#pragma unroll
    for (int nj = 0; nj < 8; nj++)
#pragma unroll
        for (int r = 0; r < 4; r++) acc[nj][r] = 0.f;

    const __half* w0 = W2 + (size_t)(o0 + os * 16 + g) * 256;
    const __half* w8 = w0 + 8 * 256;

#pragma unroll
    for (int kk = 0; kk < 8; kk++) {
        int c0 = kk * 16 + qu;
        uint32_t ah[4], al[4];
        ah[0] = *(const uint32_t*)(w0 + c0);
        ah[1] = *(const uint32_t*)(w8 + c0);
        ah[2] = *(const uint32_t*)(w0 + c0 + 8);
        ah[3] = *(const uint32_t*)(w8 + c0 + 8);
        al[0] = *(const uint32_t*)(w0 + 128 + c0);
        al[1] = *(const uint32_t*)(w8 + 128 + c0);
        al[2] = *(const uint32_t*)(w0 + 128 + c0 + 8);
        al[3] = *(const uint32_t*)(w8 + 128 + c0 + 8);
#pragma unroll
        for (int nj = 0; nj < 8; nj++) {
            uint32_t bf[2];
            const __half* hrow = &Hs[ns * 64 + nj * 8 + g][0];
            bf[0] = *(const uint32_t*)(hrow + c0);
            bf[1] = *(const uint32_t*)(hrow + c0 + 8);
            mma16816h(acc[nj], ah, bf);
            mma16816h(acc[nj], al, bf);
        }
    }

    const int orow = o0 + os * 16 + g;
    const float b0 = bias[orow], b8 = bias[orow + 8];
#pragma unroll
    for (int nj = 0; nj < 8; nj++) {
        int n = n0 + ns * 64 + nj * 8 + qu;
        float2 v0 = make_float2(acc[nj][0] + b0, acc[nj][1] + b0);
        float2 v1 = make_float2(acc[nj][2] + b8, acc[nj][3] + b8);
        float2 r0 = *(const float2*)(resid + ((size_t)b * Otot + orow) * NPIX + n);
        float2 r1 = *(const float2*)(resid + ((size_t)b * Otot + orow + 8) * NPIX + n);
        v0.x += r0.x; v0.y += r0.y;
        v1.x += r1.x; v1.y += r1.y;
        *(float2*)(Out + ((size_t)b * Otot + orow) * NPIX + n) = v0;
        *(float2*)(Out + ((size_t)b * Otot + orow + 8) * NPIX + n) = v1;
    }
}

// ---------------------------------------------------------------------------
// K3: flash attention, softmax-bound, 4-stage cp.async pipeline.
// CTA = 256 thr (8 warps), warp = 32 q rows (2 mi tiles) -> 256 q per CTA.
// K/V fragments loaded once per warp, reused across both mi tiles.
// ---------------------------------------------------------------------------
#define KBUF (64 * 40 * 2)
#define VBUF (32 * 72 * 2)
__global__ void __launch_bounds__(256, 2) attn_mma_kernel() {
    __shared__ __align__(16) __half Ks[4][64][40];  // 80B row stride
    __shared__ __align__(16) __half Vs[4][32][72];  // 144B row stride

    const int tid = threadIdx.x;
    const int lane = tid & 31;
    const int wid = tid >> 5;
    const int g = lane >> 2;
    const int qu = (lane & 3) * 2;
    const int b = blockIdx.z, hh = blockIdx.y;
    const int q0 = blockIdx.x * 256;
    const int bh = b * NH + hh;

    const __half* qgl = g_q16 + ((size_t)bh * NPIX + q0 + wid * 32) * DH;
    const __half* kgl = g_k16 + (size_t)bh * NPIX * DH;
    const __half* vgl = g_v16 + (size_t)bh * DH * NPIX;

    const float kmax = sqrtf(__uint_as_float(g_kmax[bh]));
    float B[2][2];
#pragma unroll
    for (int mi = 0; mi < 2; mi++)
#pragma unroll
        for (int h2 = 0; h2 < 2; h2++)
            B[mi][h2] = g_qb[(size_t)bh * NPIX + q0 + wid * 32 +
                             mi * 16 + g + h2 * 8] * kmax;

    uint32_t qa[2][2][4];
#pragma unroll
    for (int mi = 0; mi < 2; mi++)
#pragma unroll
        for (int kk = 0; kk < 2; kk++) {
            int r0 = mi * 16 + g;
            int c0 = kk * 16 + qu;
            qa[mi][kk][0] = *(const uint32_t*)(qgl + (size_t)r0 * DH + c0);
            qa[mi][kk][1] = *(const uint32_t*)(qgl + (size_t)(r0 + 8) * DH + c0);
            qa[mi][kk][2] = *(const uint32_t*)(qgl + (size_t)r0 * DH + c0 + 8);
            qa[mi][kk][3] = *(const uint32_t*)(qgl + (size_t)(r0 + 8) * DH + c0 + 8);
        }

    float o[2][4][4];
#pragma unroll
    for (int mi = 0; mi < 2; mi++)
#pragma unroll
        for (int ci = 0; ci < 4; ci++)
#pragma unroll
            for (int r = 0; r < 4; r++) o[mi][ci][r] = 0.f;
    float lrun[2][2] = {{0.f, 0.f}, {0.f, 0.f}};

    const int krow = tid >> 2, kpart = tid & 3;
    const int vrow = tid >> 3, vpart = tid & 7;

    const uint32_t ks_base = (uint32_t)__cvta_generic_to_shared(&Ks[0][0][0]);
    const uint32_t vs_base = (uint32_t)__cvta_generic_to_shared(&Vs[0][0][0]);
    const uint32_t koff = ((lane & 7) * 40 + (lane >> 3) * 8) * 2;
    const uint32_t voff = ((((lane >> 4) & 1) * 8 + (lane & 7)) * 72 +
                           ((lane >> 3) & 1) * 8) * 2;
    const uint32_t kst = (uint32_t)(krow * 40 + kpart * 8) * 2;
    const uint32_t vst = (uint32_t)(vrow * 72 + vpart * 8) * 2;
    const __half* kld = kgl + (size_t)krow * DH + kpart * 8;
    const __half* vld = vgl + (size_t)vrow * NPIX + vpart * 8;

    // preload chunks 0..2
#pragma unroll
    for (int s = 0; s < 3; s++) {
        cpasync16(ks_base + s * KBUF + kst, kld + (size_t)(s * 64) * DH);
        cpasync16(vs_base + s * VBUF + vst, vld + s * 64);
        CP_COMMIT();
    }

    for (int i = 0; i < NPIX / 64; i++) {
        asm volatile("cp.async.wait_group 2;" ::: "memory");
        __syncthreads();

        const int st = i & 3;
        const uint32_t kb = ks_base + st * KBUF + koff;
        const uint32_t vb_base = vs_base + st * VBUF + voff;

        // ---- S = Q K^T (k=32); K fragments shared across both mi tiles ----
        uint32_t p16[2][8][2];
#pragma unroll
        for (int nj = 0; nj < 8; nj++) {
            uint32_t b00, b01, b10, b11;
            ldmx4(b00, b01, b10, b11, kb + nj * (8 * 40 * 2));
            uint32_t bf0[2] = {b00, b01};
            uint32_t bf1[2] = {b10, b11};
#pragma unroll
            for (int mi = 0; mi < 2; mi++) {
                float sacc[4] = {0.f, 0.f, 0.f, 0.f};
                mma16816h(sacc, qa[mi][0], bf0);
                mma16816h(sacc, qa[mi][1], bf1);
                p16[mi][nj][0] = hex2(pack_f16x2(sacc[0] - B[mi][0],
                                                 sacc[1] - B[mi][0]));
                p16[mi][nj][1] = hex2(pack_f16x2(sacc[2] - B[mi][1],
                                                 sacc[3] - B[mi][1]));
            }
        }

        // ---- per-lane partial row sums ----
#pragma unroll
        for (int mi = 0; mi < 2; mi++)
#pragma unroll
            for (int h2 = 0; h2 < 2; h2++) {
                uint32_t t = hadd2(
                    hadd2(hadd2(p16[mi][0][h2], p16[mi][1][h2]),
                          hadd2(p16[mi][2][h2], p16[mi][3][h2])),
                    hadd2(hadd2(p16[mi][4][h2], p16[mi][5][h2]),
                          hadd2(p16[mi][6][h2], p16[mi][7][h2])));
                float2 f = __half22float2(*(__half2*)&t);
                lrun[mi][h2] += f.x + f.y;
            }

        // ---- O += P V; V fragments shared across both mi tiles ----
#pragma unroll
        for (int kt = 0; kt < 4; kt++) {
            uint32_t v00, v01, v10, v11, v20, v21, v30, v31;
            ldmx4(v00, v01, v10, v11, vb_base + kt * 32);
            ldmx4(v20, v21, v30, v31, vb_base + kt * 32 + (16 * 72 * 2));
            uint32_t vb0[2] = {v00, v01};
            uint32_t vb1[2] = {v10, v11};
            uint32_t vb2[2] = {v20, v21};
            uint32_t vb3[2] = {v30, v31};
#pragma unroll
            for (int mi = 0; mi < 2; mi++) {
                uint32_t ph[4] = {p16[mi][2 * kt][0], p16[mi][2 * kt][1],
                                  p16[mi][2 * kt + 1][0], p16[mi][2 * kt + 1][1]};
                mma16816h(o[mi][0], ph, vb0);
                mma16816h(o[mi][1], ph, vb1);
                mma16816h(o[mi][2], ph, vb2);
                mma16816h(o[mi][3], ph, vb3);
            }
        }

        if (i + 3 < NPIX / 64) {
            const int nst = (i + 3) & 3;
            cpasync16(ks_base + nst * KBUF + kst,
                      kld + (size_t)((i + 3) * 64) * DH);
            cpasync16(vs_base + nst * VBUF + vst, vld + (i + 3) * 64);
        }
        CP_COMMIT();
    }

    // ---- final row-sum reduce, normalize + store ----
#pragma unroll
    for (int mi = 0; mi < 2; mi++)
#pragma unroll
        for (int h2 = 0; h2 < 2; h2++) {
            float l = lrun[mi][h2];
            l += __shfl_xor_sync(0xffffffffu, l, 1);
            l += __shfl_xor_sync(0xffffffffu, l, 2);
            float invl = 1.0f / l;
            int qrow = q0 + wid * 32 + mi * 16 + g + h2 * 8;
            __half* od = g_at + ((size_t)b * NPIX + qrow) * CC + hh * DH;
#pragma unroll
            for (int ci = 0; ci < 4; ci++) {
                *(__half2*)(od + ci * 8 + qu) =
                    __floats2half2_rn(o[mi][ci][h2 * 2] * invl,
                                      o[mi][ci][h2 * 2 + 1] * invl);
            }
        }
}

// ---------------------------------------------------------------------------
extern "C" void kernel_launch(void* const* d_in, const int* in_sizes, int n_in,
                              void* d_out, int out_size) {
    const float* x      = (const float*)d_in[0];
    const float* norm_w = (const float*)d_in[1];
    const float* norm_b = (const float*)d_in[2];
    const float* qkv_w  = (const float*)d_in[3];
    const float* qkv_b  = (const float*)d_in[4];
    const float* proj_w = (const float*)d_in[5];
    const float* proj_b = (const float*)d_in[6];
    float* out = (float*)d_out;

    __half *g_wp_p, *g_at_p;
    cudaGetSymbolAddress((void**)&g_wp_p, g_wp);
    cudaGetSymbolAddress((void**)&g_at_p, g_at);

    // K0: weight conversion + kmax reset
    wconv_kernel<<<256, 256>>>(qkv_w, proj_w);

    // K1: norm -> fp16 [b][n][c]
    norm_kernel<<<(BB * NPIX) / 64, 256>>>(x, norm_w, norm_b);

    // K2: qkv GEMM + fused attention layouts + bound stats
    gemmqkv_kernel<<<dim3(NPIX / 128, 384 / 64, BB), 256>>>(qkv_b);

    // K3: attention -> fp16 [b][n][c]   (4th launch: ncu profiles this)
    attn_mma_kernel<<<dim3(NPIX / 256, NH, BB), 256>>>();

    // K4: proj + bias + residual -> d_out
    gemm16_kernel<<<dim3(NPIX / 128, CC / 64, BB), 256>>>(
        g_wp_p, proj_b, g_at_p, out, x, CC);
}